// round 2
// baseline (speedup 1.0000x reference)
#include <cuda_runtime.h>
#include <cstdint>
#include <cstddef>

#define B_    2
#define N_    2048
#define DIM_  1024
#define H_    16
#define DH_   64
#define MEM_  1024
#define CTX_  3072
#define SCALE_ 0.125f

// ---------------- scratch (static device globals; no allocation) ----------------
__device__ float g_Q  [B_ * N_ * DIM_];          // 16 MB   q projection [b,n,dim]
__device__ float g_KV [B_ * CTX_ * 2 * DIM_];    // 48 MB   kv projection [b,ctx,2dim]
__device__ float g_pos[N_ * DH_];                // 512 KB  pos' = pos_emb@Wp+bp
__device__ float g_PDT[134217728];               // 512 MB  PDT[b,h][j2][i] shifted pos dots (pre-scaled)
__device__ float g_O  [B_ * N_ * DIM_];          // 16 MB   attention output (merged heads)

// ---------------- generic tiled fp32 GEMM with bias: C = A @ B + bias ----------------
// A rows come from Alo (rows [0,MLo)) then Ahi (rows [MLo,M)) -> handles concat(mem, x).
// Tile 64x64, BK=16, 256 threads, 4x4 microtile.
__global__ __launch_bounds__(256) void gemm_bias(
    const float* __restrict__ Alo, int MLo, size_t sAlo,
    const float* __restrict__ Ahi, size_t sAhi,
    const float* __restrict__ Bm, const float* __restrict__ bias,
    float* __restrict__ C, size_t sC,
    int M, int N, int K)
{
    __shared__ float As[16][65];   // transposed A tile: As[k][m]
    __shared__ float Bs[16][64];   // Bs[k][n]

    const int batch   = blockIdx.z;
    const int rowBase = blockIdx.y * 64;
    const int colBase = blockIdx.x * 64;
    const int tid = threadIdx.x;
    const int tx = tid & 15, ty = tid >> 4;

    const float* AbLo = Alo + (size_t)batch * sAlo;
    const float* AbHi = Ahi + (size_t)batch * sAhi;

    const int arow = tid >> 2;            // 0..63
    const int ac   = (tid & 3) * 4;       // 0,4,8,12
    const int brow = tid >> 4;            // 0..15
    const int bc   = (tid & 15) * 4;      // 0..60

    const int grow = rowBase + arow;
    const float* Aptr = (grow < MLo) ? (AbLo + (size_t)grow * K)
                                     : (AbHi + (size_t)(grow - MLo) * K);

    float acc[4][4] = {};

    for (int k0 = 0; k0 < K; k0 += 16) {
        float4 av = *(const float4*)(Aptr + k0 + ac);
        float4 bv = *(const float4*)(Bm + (size_t)(k0 + brow) * N + colBase + bc);
        __syncthreads();
        As[ac + 0][arow] = av.x;
        As[ac + 1][arow] = av.y;
        As[ac + 2][arow] = av.z;
        As[ac + 3][arow] = av.w;
        *(float4*)&Bs[brow][bc] = bv;
        __syncthreads();
#pragma unroll
        for (int kk = 0; kk < 16; ++kk) {
            float a0 = As[kk][ty * 4 + 0];
            float a1 = As[kk][ty * 4 + 1];
            float a2 = As[kk][ty * 4 + 2];
            float a3 = As[kk][ty * 4 + 3];
            float4 b4 = *(const float4*)&Bs[kk][tx * 4];
            acc[0][0] += a0 * b4.x; acc[0][1] += a0 * b4.y; acc[0][2] += a0 * b4.z; acc[0][3] += a0 * b4.w;
            acc[1][0] += a1 * b4.x; acc[1][1] += a1 * b4.y; acc[1][2] += a1 * b4.z; acc[1][3] += a1 * b4.w;
            acc[2][0] += a2 * b4.x; acc[2][1] += a2 * b4.y; acc[2][2] += a2 * b4.z; acc[2][3] += a2 * b4.w;
            acc[3][0] += a3 * b4.x; acc[3][1] += a3 * b4.y; acc[3][2] += a3 * b4.z; acc[3][3] += a3 * b4.w;
        }
    }

    float4 bvv = *(const float4*)(bias + colBase + tx * 4);
    float* Cb = C + (size_t)batch * sC;
#pragma unroll
    for (int a = 0; a < 4; ++a) {
        int row = rowBase + ty * 4 + a;
        float4 o;
        o.x = acc[a][0] + bvv.x;
        o.y = acc[a][1] + bvv.y;
        o.z = acc[a][2] + bvv.z;
        o.w = acc[a][3] + bvv.w;
        *(float4*)(Cb + (size_t)row * N + colBase + tx * 4) = o;
    }
}

// ---------------- skewed pos-dots GEMM ----------------
// PDT[b,h][j2][i] = SCALE * sum_d Q[b,i,h*64+d] * pos'[j2 - i + (N_-1)][d]   (valid for j2 <= i)
// Transposed [j2][i] layout => attention reads are warp-coalesced.
// Two passes over d (32 each) to stay under the 48 KB static smem limit.
__global__ __launch_bounds__(256) void pdt_kernel(
    const float* __restrict__ Q, const float* __restrict__ Pos, float* __restrict__ PDT)
{
    const int bh = blockIdx.z;            // b*16+h
    const int b  = bh >> 4, h = bh & 15;
    const int I  = blockIdx.x * 64;       // query tile
    const int J  = blockIdx.y * 64;       // j2 tile
    if (J > I + 63) return;               // tile entirely above diagonal: never read

    __shared__ float Qs[64][33];          // Qs[i_local][d]  (half of d)
    __shared__ float Ps[127][33];         // pos slab rows 0..126 <-> pidx = pbase + s

    const int tid = threadIdx.x;
    const int pbase = J - I + (N_ - 1) - 63;   // = J - I + 1984

    const int tx = tid & 15, ty = tid >> 4;
    const int s0 = 4 * ty - 4 * tx + 63;  // slab index for (a=0,c=0); range [3,123]
    float acc[4][4] = {};

    const int qrow = tid >> 2;            // 0..63
    const int qc0  = (tid & 3) * 8;       // 0,8,16,24

#pragma unroll
    for (int kh = 0; kh < 2; ++kh) {
        const int dbase = kh * 32;
        // load Q half-tile (64 rows x 32 floats)
        {
            const float* src = Q + ((size_t)(b * N_ + I + qrow)) * DIM_ + h * DH_ + dbase + qc0;
#pragma unroll
            for (int u = 0; u < 2; ++u) {
                float4 v = *(const float4*)(src + u * 4);
                int d = qc0 + u * 4;
                Qs[qrow][d] = v.x; Qs[qrow][d + 1] = v.y; Qs[qrow][d + 2] = v.z; Qs[qrow][d + 3] = v.w;
            }
        }
        // load pos slab half (127 rows x 32 floats, zero-fill out-of-range)
        {
            for (int s = tid >> 2; s < 127; s += 64) {
                int pidx = pbase + s;
                bool ok = (pidx >= 0) && (pidx < N_);
                const float* src = Pos + (size_t)(ok ? pidx : 0) * DH_ + dbase + qc0;
#pragma unroll
                for (int u = 0; u < 2; ++u) {
                    float4 v = ok ? *(const float4*)(src + u * 4) : make_float4(0.f, 0.f, 0.f, 0.f);
                    int d = qc0 + u * 4;
                    Ps[s][d] = v.x; Ps[s][d + 1] = v.y; Ps[s][d + 2] = v.z; Ps[s][d + 3] = v.w;
                }
            }
        }
        __syncthreads();

#pragma unroll 4
        for (int d = 0; d < 32; ++d) {
            float qv[4], pv[7];
#pragma unroll
            for (int c = 0; c < 4; ++c) qv[c] = Qs[4 * tx + c][d];
#pragma unroll
            for (int t = 0; t < 7; ++t) pv[t] = Ps[s0 - 3 + t][d];
#pragma unroll
            for (int a = 0; a < 4; ++a)
#pragma unroll
                for (int c = 0; c < 4; ++c)
                    acc[a][c] += pv[a - c + 3] * qv[c];
        }
        __syncthreads();
    }

    float* base = PDT + ((size_t)bh << 22);   // bh * 2048 * 2048
#pragma unroll
    for (int a = 0; a < 4; ++a) {
        int j2 = J + 4 * ty + a;
        float4 o;
        o.x = SCALE_ * acc[a][0];
        o.y = SCALE_ * acc[a][1];
        o.z = SCALE_ * acc[a][2];
        o.w = SCALE_ * acc[a][3];
        *(float4*)(base + (size_t)j2 * N_ + I + 4 * tx) = o;
    }
}

// ---------------- fused online-softmax attention ----------------
// One thread per query row; block = 128 rows of one (b,h). K/V tiles staged in smem (broadcast reads).
__device__ __forceinline__ float dot64(const float4* __restrict__ q, const float4* __restrict__ k)
{
    float s = 0.f;
#pragma unroll
    for (int d = 0; d < 16; ++d) {
        float4 kk = k[d];
        s += q[d].x * kk.x + q[d].y * kk.y + q[d].z * kk.z + q[d].w * kk.w;
    }
    return s;
}

__device__ __forceinline__ void sm_update(float s, float em, float& m, float& l,
                                          float4* __restrict__ o, const float4* __restrict__ vrow)
{
    if (s > m) {                       // rare after warmup (~log(ctx) record maxima)
        float f = __expf(m - s);
        l *= f;
#pragma unroll
        for (int d = 0; d < 16; ++d) { o[d].x *= f; o[d].y *= f; o[d].z *= f; o[d].w *= f; }
        m = s;
    }
    float p = __expf(s - m);
    l += p;
    float pe = p * em;
#pragma unroll
    for (int d = 0; d < 16; ++d) {
        float4 v = vrow[d];
        o[d].x += pe * v.x; o[d].y += pe * v.y; o[d].z += pe * v.z; o[d].w += pe * v.w;
    }
}

__global__ __launch_bounds__(128) void attn_kernel(
    const float* __restrict__ Q, const float* __restrict__ KV,
    const float* __restrict__ PDT, const float* __restrict__ expire,
    float* __restrict__ O)
{
    const int b = blockIdx.z, h = blockIdx.y;
    const int tid = threadIdx.x;
    const int i = blockIdx.x * 128 + tid;

    __shared__ float4 ks[32][16];
    __shared__ float4 vs[32][16];

    float4 q[16], o[16];
    {
        const float4* qsrc = (const float4*)(Q + ((size_t)(b * N_ + i)) * DIM_ + h * DH_);
#pragma unroll
        for (int d = 0; d < 16; ++d) { q[d] = qsrc[d]; o[d] = make_float4(0.f, 0.f, 0.f, 0.f); }
    }
    float m = -1e30f, l = 0.f;

    const float* pdt = PDT + (((size_t)(b * H_ + h)) << 22) + i;   // + j2*2048
    const float* emp = expire + b * MEM_;

    const int jmax_block = blockIdx.x * 128 + 127 + MEM_;
    const int ntiles = (jmax_block + 32) / 32;

    for (int t = 0; t < ntiles; ++t) {
        const int j0 = t * 32;
        __syncthreads();
#pragma unroll
        for (int r = 0; r < 4; ++r) {
            int idx = tid + r * 128;
            int row = idx >> 4, c = idx & 15;
            const float4* src = (const float4*)(KV + ((size_t)(b * CTX_ + j0 + row)) * (2 * DIM_));
            ks[row][c] = src[h * 16 + c];
            vs[row][c] = src[256 + h * 16 + c];
        }
        __syncthreads();

        if (j0 + 32 <= MEM_) {
            // memory keys: no pos term, expire-mask weighting (all 32 valid: j < mem_len <= i+mem_len)
#pragma unroll 4
            for (int jj = 0; jj < 32; ++jj) {
                float s = dot64(q, &ks[jj][0]) * SCALE_;
                sm_update(s, emp[j0 + jj], m, l, o, &vs[jj][0]);
            }
        } else {
            // current-sequence keys: pos term, em=1, causal bound j <= i+mem_len
            int nvalid = i + MEM_ + 1 - j0;
            if (nvalid > 32) nvalid = 32;
            for (int jj = 0; jj < nvalid; ++jj) {
                float s = dot64(q, &ks[jj][0]) * SCALE_ + pdt[(size_t)(j0 + jj - MEM_) * N_];
                sm_update(s, 1.f, m, l, o, &vs[jj][0]);
            }
        }
    }

    float inv = 1.f / l;
    float4* dst = (float4*)(O + ((size_t)(b * N_ + i)) * DIM_ + h * DH_);
#pragma unroll
    for (int d = 0; d < 16; ++d) {
        float4 v; v.x = o[d].x * inv; v.y = o[d].y * inv; v.z = o[d].z * inv; v.w = o[d].w * inv;
        dst[d] = v;
    }
}

// ---------------- launcher ----------------
extern "C" void kernel_launch(void* const* d_in, const int* in_sizes, int n_in,
                              void* d_out, int out_size)
{
    const float* x       = (const float*)d_in[0];
    const float* pos_emb = (const float*)d_in[1];
    const float* mem     = (const float*)d_in[2];
    const float* expire  = (const float*)d_in[3];
    const float* Wq      = (const float*)d_in[4];
    const float* bq      = (const float*)d_in[5];
    const float* Wkv     = (const float*)d_in[6];
    const float* bkv     = (const float*)d_in[7];
    const float* Wo      = (const float*)d_in[8];
    const float* bo      = (const float*)d_in[9];
    const float* Wp      = (const float*)d_in[10];
    const float* bp      = (const float*)d_in[11];
    float* out = (float*)d_out;

    float *Q, *KV, *Pos, *PDT, *O;
    cudaGetSymbolAddress((void**)&Q,   g_Q);
    cudaGetSymbolAddress((void**)&KV,  g_KV);
    cudaGetSymbolAddress((void**)&Pos, g_pos);
    cudaGetSymbolAddress((void**)&PDT, g_PDT);
    cudaGetSymbolAddress((void**)&O,   g_O);

    // 1) Q = x @ Wq + bq                    [2,2048,1024]
    gemm_bias<<<dim3(DIM_ / 64, N_ / 64, B_), 256>>>(
        x, N_, (size_t)N_ * DIM_, x, (size_t)N_ * DIM_,
        Wq, bq, Q, (size_t)N_ * DIM_, N_, DIM_, DIM_);

    // 2) KV = concat(mem, x) @ Wkv + bkv    [2,3072,2048]
    gemm_bias<<<dim3(2 * DIM_ / 64, CTX_ / 64, B_), 256>>>(
        mem, MEM_, (size_t)MEM_ * DIM_, x, (size_t)N_ * DIM_,
        Wkv, bkv, KV, (size_t)CTX_ * 2 * DIM_, CTX_, 2 * DIM_, DIM_);

    // 3) pos' = pos_emb @ Wp + bp           [2048,64]
    gemm_bias<<<dim3(1, N_ / 64, 1), 256>>>(
        pos_emb, N_, 0, pos_emb, 0,
        Wp, bp, Pos, 0, N_, DH_, DIM_);

    // 4) PDT (shifted, transposed, pre-scaled pos dots)
    pdt_kernel<<<dim3(N_ / 64, N_ / 64, B_ * H_), 256>>>(Q, Pos, PDT);

    // 5) fused attention -> O               [2,2048,1024]
    attn_kernel<<<dim3(N_ / 128, H_, B_), 128>>>(Q, KV, PDT, expire, O);

    // 6) out = O @ Wo + bo                  [2,2048,1024]
    gemm_bias<<<dim3(DIM_ / 64, N_ / 64, B_), 256>>>(
        O, N_, (size_t)N_ * DIM_, O, (size_t)N_ * DIM_,
        Wo, bo, out, (size_t)N_ * DIM_, N_, DIM_, DIM_);
}

// round 4
// speedup vs baseline: 1.0455x; 1.0455x over previous
#include <cuda_runtime.h>
#include <cstdint>
#include <cstddef>

#define B_    2
#define N_    2048
#define DIM_  1024
#define H_    16
#define DH_   64
#define MEM_  1024
#define CTX_  3072
#define SCALE_ 0.125f

// ---------------- scratch (static device globals; no allocation) ----------------
__device__ float g_Q  [B_ * N_ * DIM_];          // 16 MB
__device__ float g_KV [B_ * CTX_ * 2 * DIM_];    // 48 MB
__device__ float g_pos[N_ * DH_];                // 512 KB
__device__ float g_PDT[134217728];               // 512 MB  PDT[b,h][j2][i]
__device__ float g_O  [B_ * N_ * DIM_];          // 16 MB

// =====================================================================
// Split-tf32 tensor-core GEMM:  C = A @ B + bias   (fp32-accurate, 3xTF32)
// Block 128x128, BK=16, 256 threads, 8 warps in 4(m) x 2(n), warp tile 32x64.
// A rows [0,MLo) from Alo, rows [MLo,M) from Ahi (handles concat(mem, x)).
// =====================================================================
__device__ __forceinline__ void mma_tf32(float* c, const float* a, const float* b)
{
    asm volatile(
        "mma.sync.aligned.m16n8k8.row.col.f32.tf32.tf32.f32 "
        "{%0,%1,%2,%3}, {%4,%5,%6,%7}, {%8,%9}, {%0,%1,%2,%3};\n"
        : "+f"(c[0]), "+f"(c[1]), "+f"(c[2]), "+f"(c[3])
        : "r"(__float_as_uint(a[0])), "r"(__float_as_uint(a[1])),
          "r"(__float_as_uint(a[2])), "r"(__float_as_uint(a[3])),
          "r"(__float_as_uint(b[0])), "r"(__float_as_uint(b[1])));
}

__device__ __forceinline__ void split1(float v, float& h, float& l)
{
    unsigned hu;
    asm("cvt.rna.tf32.f32 %0, %1;" : "=r"(hu) : "f"(v));
    h = __uint_as_float(hu);
    float r = v - h;
    unsigned lu;
    asm("cvt.rna.tf32.f32 %0, %1;" : "=r"(lu) : "f"(r));
    l = __uint_as_float(lu);
}

__device__ __forceinline__ void split4(float4 v, float4& h, float4& l)
{
    split1(v.x, h.x, l.x); split1(v.y, h.y, l.y);
    split1(v.z, h.z, l.z); split1(v.w, h.w, l.w);
}

__global__ __launch_bounds__(256) void gemm_tf32(
    const float* __restrict__ Alo, int MLo, size_t sAlo,
    const float* __restrict__ Ahi, size_t sAhi,
    const float* __restrict__ Bm, const float* __restrict__ bias,
    float* __restrict__ C, size_t sC,
    int N, int K)
{
    __shared__ __align__(16) float AsH[128][20];
    __shared__ __align__(16) float AsL[128][20];
    __shared__ __align__(16) float BsH[16][136];
    __shared__ __align__(16) float BsL[16][136];

    const int batch   = blockIdx.z;
    const int rowBase = blockIdx.y * 128;
    const int colBase = blockIdx.x * 128;
    const int tid  = threadIdx.x;
    const int wid  = tid >> 5, lane = tid & 31;
    const int wm   = wid & 3,  wn   = wid >> 2;
    const int g    = lane >> 2, q   = lane & 3;

    // ---- global load mapping ----
    const int ar = tid >> 2;            // A row 0..63 (+64 for second)
    const int ac = (tid & 3) * 4;       // A col within BK tile
    const float* aptr[2];
#pragma unroll
    for (int i = 0; i < 2; ++i) {
        int r = rowBase + ar + 64 * i;
        aptr[i] = ((r < MLo) ? (Alo + (size_t)batch * sAlo + (size_t)r * K)
                             : (Ahi + (size_t)batch * sAhi + (size_t)(r - MLo) * K)) + ac;
    }
    const int kr = tid >> 5;            // B k-row 0..7 (+8 for second)
    const int bc = (lane) * 4;          // B col 0..124
    const float* bptr[2];
#pragma unroll
    for (int i = 0; i < 2; ++i)
        bptr[i] = Bm + (size_t)(kr + 8 * i) * N + colBase + bc;

    float4 ga[2], gb[2];
#pragma unroll
    for (int i = 0; i < 2; ++i) { ga[i] = *(const float4*)(aptr[i]); gb[i] = *(const float4*)(bptr[i]); }

    float acc[2][8][4];
#pragma unroll
    for (int a = 0; a < 2; ++a)
#pragma unroll
        for (int b = 0; b < 8; ++b)
#pragma unroll
            for (int c = 0; c < 4; ++c) acc[a][b][c] = 0.f;

    for (int k0 = 0; k0 < K; k0 += 16) {
        // stage current regs -> smem (split hi/lo)
#pragma unroll
        for (int i = 0; i < 2; ++i) {
            float4 h, l;
            split4(ga[i], h, l);
            *(float4*)&AsH[ar + 64 * i][ac] = h;
            *(float4*)&AsL[ar + 64 * i][ac] = l;
            split4(gb[i], h, l);
            *(float4*)&BsH[kr + 8 * i][bc] = h;
            *(float4*)&BsL[kr + 8 * i][bc] = l;
        }
        __syncthreads();

        // prefetch next tile (A advances along k within the row; B advances k rows)
        if (k0 + 16 < K) {
#pragma unroll
            for (int i = 0; i < 2; ++i) {
                ga[i] = *(const float4*)(aptr[i] + k0 + 16);
                gb[i] = *(const float4*)(bptr[i] + (size_t)(k0 + 16) * N);
            }
        }

#pragma unroll
        for (int ks = 0; ks < 2; ++ks) {
            const int kk = ks * 8;
            float bH[8][2], bL[8][2];
#pragma unroll
            for (int tn = 0; tn < 8; ++tn) {
                int col = wn * 64 + tn * 8 + g;
                bH[tn][0] = BsH[kk + q][col];     bH[tn][1] = BsH[kk + q + 4][col];
                bL[tn][0] = BsL[kk + q][col];     bL[tn][1] = BsL[kk + q + 4][col];
            }
#pragma unroll
            for (int tm = 0; tm < 2; ++tm) {
                int r0 = wm * 32 + tm * 16 + g;
                float aH[4], aL[4];
                aH[0] = AsH[r0][kk + q];     aH[1] = AsH[r0 + 8][kk + q];
                aH[2] = AsH[r0][kk + q + 4]; aH[3] = AsH[r0 + 8][kk + q + 4];
                aL[0] = AsL[r0][kk + q];     aL[1] = AsL[r0 + 8][kk + q];
                aL[2] = AsL[r0][kk + q + 4]; aL[3] = AsL[r0 + 8][kk + q + 4];
#pragma unroll
                for (int tn = 0; tn < 8; ++tn) {
                    mma_tf32(acc[tm][tn], aH, bH[tn]);
                    mma_tf32(acc[tm][tn], aH, bL[tn]);
                    mma_tf32(acc[tm][tn], aL, bH[tn]);
                }
            }
        }
        __syncthreads();
    }

    // epilogue: C = acc + bias
    float* Cb = C + (size_t)batch * sC;
#pragma unroll
    for (int tm = 0; tm < 2; ++tm) {
#pragma unroll
        for (int tn = 0; tn < 8; ++tn) {
            int row = rowBase + wm * 32 + tm * 16 + g;
            int col = colBase + wn * 64 + tn * 8 + 2 * q;
            float b0 = bias[col], b1 = bias[col + 1];
            float2 v0 = make_float2(acc[tm][tn][0] + b0, acc[tm][tn][1] + b1);
            float2 v1 = make_float2(acc[tm][tn][2] + b0, acc[tm][tn][3] + b1);
            *(float2*)(Cb + (size_t)row * N + col) = v0;
            *(float2*)(Cb + (size_t)(row + 8) * N + col) = v1;
        }
    }
}

// ---------------- small scalar GEMM with bias (kept for pos': N=64) ----------------
__global__ __launch_bounds__(256) void gemm_bias(
    const float* __restrict__ A, const float* __restrict__ Bm, const float* __restrict__ bias,
    float* __restrict__ C, int M, int N, int K)
{
    __shared__ float As[16][65];
    __shared__ float Bs[16][64];

    const int rowBase = blockIdx.y * 64;
    const int colBase = blockIdx.x * 64;
    const int tid = threadIdx.x;
    const int tx = tid & 15, ty = tid >> 4;

    const int arow = tid >> 2;
    const int ac   = (tid & 3) * 4;
    const int brow = tid >> 4;
    const int bc   = (tid & 15) * 4;

    const float* Aptr = A + (size_t)(rowBase + arow) * K;
    float acc[4][4] = {};

    for (int k0 = 0; k0 < K; k0 += 16) {
        float4 av = *(const float4*)(Aptr + k0 + ac);
        float4 bv = *(const float4*)(Bm + (size_t)(k0 + brow) * N + colBase + bc);
        __syncthreads();
        As[ac + 0][arow] = av.x; As[ac + 1][arow] = av.y;
        As[ac + 2][arow] = av.z; As[ac + 3][arow] = av.w;
        *(float4*)&Bs[brow][bc] = bv;
        __syncthreads();
#pragma unroll
        for (int kk = 0; kk < 16; ++kk) {
            float a0 = As[kk][ty * 4 + 0], a1 = As[kk][ty * 4 + 1];
            float a2 = As[kk][ty * 4 + 2], a3 = As[kk][ty * 4 + 3];
            float4 b4 = *(const float4*)&Bs[kk][tx * 4];
            acc[0][0] += a0 * b4.x; acc[0][1] += a0 * b4.y; acc[0][2] += a0 * b4.z; acc[0][3] += a0 * b4.w;
            acc[1][0] += a1 * b4.x; acc[1][1] += a1 * b4.y; acc[1][2] += a1 * b4.z; acc[1][3] += a1 * b4.w;
            acc[2][0] += a2 * b4.x; acc[2][1] += a2 * b4.y; acc[2][2] += a2 * b4.z; acc[2][3] += a2 * b4.w;
            acc[3][0] += a3 * b4.x; acc[3][1] += a3 * b4.y; acc[3][2] += a3 * b4.z; acc[3][3] += a3 * b4.w;
        }
    }

    float4 bvv = *(const float4*)(bias + colBase + tx * 4);
#pragma unroll
    for (int a = 0; a < 4; ++a) {
        int row = rowBase + ty * 4 + a;
        float4 o;
        o.x = acc[a][0] + bvv.x; o.y = acc[a][1] + bvv.y;
        o.z = acc[a][2] + bvv.z; o.w = acc[a][3] + bvv.w;
        *(float4*)(C + (size_t)row * N + colBase + tx * 4) = o;
    }
}

// ---------------- skewed pos-dots GEMM (two d-passes, 25KB smem) ----------------
__global__ __launch_bounds__(256) void pdt_kernel(
    const float* __restrict__ Q, const float* __restrict__ Pos, float* __restrict__ PDT)
{
    const int bh = blockIdx.z;
    const int b  = bh >> 4, h = bh & 15;
    const int I  = blockIdx.x * 64;
    const int J  = blockIdx.y * 64;
    if (J > I + 63) return;

    __shared__ float Qs[64][33];
    __shared__ float Ps[127][33];

    const int tid = threadIdx.x;
    const int pbase = J - I + (N_ - 1) - 63;

    const int tx = tid & 15, ty = tid >> 4;
    const int s0 = 4 * ty - 4 * tx + 63;
    float acc[4][4] = {};

    const int qrow = tid >> 2;
    const int qc0  = (tid & 3) * 8;

#pragma unroll
    for (int kh = 0; kh < 2; ++kh) {
        const int dbase = kh * 32;
        {
            const float* src = Q + ((size_t)(b * N_ + I + qrow)) * DIM_ + h * DH_ + dbase + qc0;
#pragma unroll
            for (int u = 0; u < 2; ++u) {
                float4 v = *(const float4*)(src + u * 4);
                int d = qc0 + u * 4;
                Qs[qrow][d] = v.x; Qs[qrow][d + 1] = v.y; Qs[qrow][d + 2] = v.z; Qs[qrow][d + 3] = v.w;
            }
        }
        {
            for (int s = tid >> 2; s < 127; s += 64) {
                int pidx = pbase + s;
                bool ok = (pidx >= 0) && (pidx < N_);
                const float* src = Pos + (size_t)(ok ? pidx : 0) * DH_ + dbase + qc0;
#pragma unroll
                for (int u = 0; u < 2; ++u) {
                    float4 v = ok ? *(const float4*)(src + u * 4) : make_float4(0.f, 0.f, 0.f, 0.f);
                    int d = qc0 + u * 4;
                    Ps[s][d] = v.x; Ps[s][d + 1] = v.y; Ps[s][d + 2] = v.z; Ps[s][d + 3] = v.w;
                }
            }
        }
        __syncthreads();

#pragma unroll 4
        for (int d = 0; d < 32; ++d) {
            float qv[4], pv[7];
#pragma unroll
            for (int c = 0; c < 4; ++c) qv[c] = Qs[4 * tx + c][d];
#pragma unroll
            for (int t = 0; t < 7; ++t) pv[t] = Ps[s0 - 3 + t][d];
#pragma unroll
            for (int a = 0; a < 4; ++a)
#pragma unroll
                for (int c = 0; c < 4; ++c)
                    acc[a][c] += pv[a - c + 3] * qv[c];
        }
        __syncthreads();
    }

    float* base = PDT + ((size_t)bh << 22);
#pragma unroll
    for (int a = 0; a < 4; ++a) {
        int j2 = J + 4 * ty + a;
        float4 o;
        o.x = SCALE_ * acc[a][0]; o.y = SCALE_ * acc[a][1];
        o.z = SCALE_ * acc[a][2]; o.w = SCALE_ * acc[a][3];
        *(float4*)(base + (size_t)j2 * N_ + I + 4 * tx) = o;
    }
}

// ---------------- fused online-softmax attention ----------------
__device__ __forceinline__ float dot64(const float4* __restrict__ q, const float4* __restrict__ k)
{
    float s = 0.f;
#pragma unroll
    for (int d = 0; d < 16; ++d) {
        float4 kk = k[d];
        s += q[d].x * kk.x + q[d].y * kk.y + q[d].z * kk.z + q[d].w * kk.w;
    }
    return s;
}

__device__ __forceinline__ void sm_update(float s, float em, float& m, float& l,
                                          float4* __restrict__ o, const float4* __restrict__ vrow)
{
    if (s > m) {
        float f = __expf(m - s);
        l *= f;
#pragma unroll
        for (int d = 0; d < 16; ++d) { o[d].x *= f; o[d].y *= f; o[d].z *= f; o[d].w *= f; }
        m = s;
    }
    float p = __expf(s - m);
    l += p;
    float pe = p * em;
#pragma unroll
    for (int d = 0; d < 16; ++d) {
        float4 v = vrow[d];
        o[d].x += pe * v.x; o[d].y += pe * v.y; o[d].z += pe * v.z; o[d].w += pe * v.w;
    }
}

__global__ __launch_bounds__(128) void attn_kernel(
    const float* __restrict__ Q, const float* __restrict__ KV,
    const float* __restrict__ PDT, const float* __restrict__ expire,
    float* __restrict__ O)
{
    const int b = blockIdx.z, h = blockIdx.y;
    const int tid = threadIdx.x;
    const int i = blockIdx.x * 128 + tid;

    __shared__ float4 ks[32][16];
    __shared__ float4 vs[32][16];

    float4 q[16], o[16];
    {
        const float4* qsrc = (const float4*)(Q + ((size_t)(b * N_ + i)) * DIM_ + h * DH_);
#pragma unroll
        for (int d = 0; d < 16; ++d) { q[d] = qsrc[d]; o[d] = make_float4(0.f, 0.f, 0.f, 0.f); }
    }
    float m = -1e30f, l = 0.f;

    const float* pdt = PDT + (((size_t)(b * H_ + h)) << 22) + i;
    const float* emp = expire + b * MEM_;

    const int jmax_block = blockIdx.x * 128 + 127 + MEM_;
    const int ntiles = (jmax_block + 32) / 32;

    for (int t = 0; t < ntiles; ++t) {
        const int j0 = t * 32;
        __syncthreads();
#pragma unroll
        for (int r = 0; r < 4; ++r) {
            int idx = tid + r * 128;
            int row = idx >> 4, c = idx & 15;
            const float4* src = (const float4*)(KV + ((size_t)(b * CTX_ + j0 + row)) * (2 * DIM_));
            ks[row][c] = src[h * 16 + c];
            vs[row][c] = src[256 + h * 16 + c];
        }
        __syncthreads();

        if (j0 + 32 <= MEM_) {
#pragma unroll 4
            for (int jj = 0; jj < 32; ++jj) {
                float s = dot64(q, &ks[jj][0]) * SCALE_;
                sm_update(s, emp[j0 + jj], m, l, o, &vs[jj][0]);
            }
        } else {
            int nvalid = i + MEM_ + 1 - j0;
            if (nvalid > 32) nvalid = 32;
            for (int jj = 0; jj < nvalid; ++jj) {
                float s = dot64(q, &ks[jj][0]) * SCALE_ + pdt[(size_t)(j0 + jj - MEM_) * N_];
                sm_update(s, 1.f, m, l, o, &vs[jj][0]);
            }
        }
    }

    float inv = 1.f / l;
    float4* dst = (float4*)(O + ((size_t)(b * N_ + i)) * DIM_ + h * DH_);
#pragma unroll
    for (int d = 0; d < 16; ++d) {
        float4 v; v.x = o[d].x * inv; v.y = o[d].y * inv; v.z = o[d].z * inv; v.w = o[d].w * inv;
        dst[d] = v;
    }
}

// ---------------- launcher ----------------
extern "C" void kernel_launch(void* const* d_in, const int* in_sizes, int n_in,
                              void* d_out, int out_size)
{
    const float* x       = (const float*)d_in[0];
    const float* pos_emb = (const float*)d_in[1];
    const float* mem     = (const float*)d_in[2];
    const float* expire  = (const float*)d_in[3];
    const float* Wq      = (const float*)d_in[4];
    const float* bq      = (const float*)d_in[5];
    const float* Wkv     = (const float*)d_in[6];
    const float* bkv     = (const float*)d_in[7];
    const float* Wo      = (const float*)d_in[8];
    const float* bo      = (const float*)d_in[9];
    const float* Wp      = (const float*)d_in[10];
    const float* bp      = (const float*)d_in[11];
    float* out = (float*)d_out;

    float *Q, *KV, *Pos, *PDT, *O;
    cudaGetSymbolAddress((void**)&Q,   g_Q);
    cudaGetSymbolAddress((void**)&KV,  g_KV);
    cudaGetSymbolAddress((void**)&Pos, g_pos);
    cudaGetSymbolAddress((void**)&PDT, g_PDT);
    cudaGetSymbolAddress((void**)&O,   g_O);

    // 1) Q = x @ Wq + bq          (fold batch: M=4096, N=1024)
    gemm_tf32<<<dim3(DIM_ / 128, (B_ * N_) / 128, 1), 256>>>(
        x, B_ * N_, 0, x, 0, Wq, bq, Q, 0, DIM_, DIM_);

    // 2) KV = concat(mem, x) @ Wkv + bkv    (per batch: M=3072, N=2048)
    gemm_tf32<<<dim3(2 * DIM_ / 128, CTX_ / 128, B_), 256>>>(
        mem, MEM_, (size_t)MEM_ * DIM_, x, (size_t)N_ * DIM_,
        Wkv, bkv, KV, (size_t)CTX_ * 2 * DIM_, 2 * DIM_, DIM_);

    // 3) pos' = pos_emb @ Wp + bp           [2048,64]
    gemm_bias<<<dim3(1, N_ / 64, 1), 256>>>(pos_emb, Wp, bp, Pos, N_, DH_, DIM_);

    // 4) PDT (shifted, transposed, pre-scaled pos dots)
    pdt_kernel<<<dim3(N_ / 64, N_ / 64, B_ * H_), 256>>>(Q, Pos, PDT);

    // 5) fused attention -> O
    attn_kernel<<<dim3(N_ / 128, H_, B_), 128>>>(Q, KV, PDT, expire, O);

    // 6) out = O @ Wo + bo        (fold batch: M=4096, N=1024)
    gemm_tf32<<<dim3(DIM_ / 128, (B_ * N_) / 128, 1), 256>>>(
        O, B_ * N_, 0, O, 0, Wo, bo, out, 0, DIM_, DIM_);
}

// round 6
// speedup vs baseline: 1.6698x; 1.5972x over previous
#include <cuda_runtime.h>
#include <cstdint>
#include <cstddef>

#define B_    2
#define N_    2048
#define DIM_  1024
#define H_    16
#define DH_   64
#define MEM_  1024
#define CTX_  3072
#define SCALE_ 0.125f

// ---------------- scratch (static device globals; no allocation) ----------------
__device__ float g_Q  [B_ * N_ * DIM_];          // 16 MB
__device__ float g_KV [B_ * CTX_ * 2 * DIM_];    // 48 MB
__device__ float g_pos[N_ * DH_];                // 512 KB
__device__ float g_PDT[134217728];               // 512 MB  PDT[b,h][j2][i]
__device__ float g_O  [B_ * N_ * DIM_];          // 16 MB

// =====================================================================
// Split-tf32 tensor-core GEMM:  C = A @ B + bias   (fp32-accurate, 3xTF32)
// =====================================================================
__device__ __forceinline__ void mma_tf32(float* c, const float* a, const float* b)
{
    asm volatile(
        "mma.sync.aligned.m16n8k8.row.col.f32.tf32.tf32.f32 "
        "{%0,%1,%2,%3}, {%4,%5,%6,%7}, {%8,%9}, {%0,%1,%2,%3};\n"
        : "+f"(c[0]), "+f"(c[1]), "+f"(c[2]), "+f"(c[3])
        : "r"(__float_as_uint(a[0])), "r"(__float_as_uint(a[1])),
          "r"(__float_as_uint(a[2])), "r"(__float_as_uint(a[3])),
          "r"(__float_as_uint(b[0])), "r"(__float_as_uint(b[1])));
}

__device__ __forceinline__ void split1(float v, float& h, float& l)
{
    unsigned hu;
    asm("cvt.rna.tf32.f32 %0, %1;" : "=r"(hu) : "f"(v));
    h = __uint_as_float(hu);
    float r = v - h;
    unsigned lu;
    asm("cvt.rna.tf32.f32 %0, %1;" : "=r"(lu) : "f"(r));
    l = __uint_as_float(lu);
}

__device__ __forceinline__ void split4(float4 v, float4& h, float4& l)
{
    split1(v.x, h.x, l.x); split1(v.y, h.y, l.y);
    split1(v.z, h.z, l.z); split1(v.w, h.w, l.w);
}

__global__ __launch_bounds__(256) void gemm_tf32(
    const float* __restrict__ Alo, int MLo, size_t sAlo,
    const float* __restrict__ Ahi, size_t sAhi,
    const float* __restrict__ Bm, const float* __restrict__ bias,
    float* __restrict__ C, size_t sC,
    int N, int K)
{
    __shared__ __align__(16) float AsH[128][20];
    __shared__ __align__(16) float AsL[128][20];
    __shared__ __align__(16) float BsH[16][136];
    __shared__ __align__(16) float BsL[16][136];

    const int batch   = blockIdx.z;
    const int rowBase = blockIdx.y * 128;
    const int colBase = blockIdx.x * 128;
    const int tid  = threadIdx.x;
    const int wid  = tid >> 5, lane = tid & 31;
    const int wm   = wid & 3,  wn   = wid >> 2;
    const int g    = lane >> 2, q   = lane & 3;

    const int ar = tid >> 2;
    const int ac = (tid & 3) * 4;
    const float* aptr[2];
#pragma unroll
    for (int i = 0; i < 2; ++i) {
        int r = rowBase + ar + 64 * i;
        aptr[i] = ((r < MLo) ? (Alo + (size_t)batch * sAlo + (size_t)r * K)
                             : (Ahi + (size_t)batch * sAhi + (size_t)(r - MLo) * K)) + ac;
    }
    const int kr = tid >> 5;
    const int bc = (lane) * 4;
    const float* bptr[2];
#pragma unroll
    for (int i = 0; i < 2; ++i)
        bptr[i] = Bm + (size_t)(kr + 8 * i) * N + colBase + bc;

    float4 ga[2], gb[2];
#pragma unroll
    for (int i = 0; i < 2; ++i) { ga[i] = *(const float4*)(aptr[i]); gb[i] = *(const float4*)(bptr[i]); }

    float acc[2][8][4];
#pragma unroll
    for (int a = 0; a < 2; ++a)
#pragma unroll
        for (int b = 0; b < 8; ++b)
#pragma unroll
            for (int c = 0; c < 4; ++c) acc[a][b][c] = 0.f;

    for (int k0 = 0; k0 < K; k0 += 16) {
#pragma unroll
        for (int i = 0; i < 2; ++i) {
            float4 h, l;
            split4(ga[i], h, l);
            *(float4*)&AsH[ar + 64 * i][ac] = h;
            *(float4*)&AsL[ar + 64 * i][ac] = l;
            split4(gb[i], h, l);
            *(float4*)&BsH[kr + 8 * i][bc] = h;
            *(float4*)&BsL[kr + 8 * i][bc] = l;
        }
        __syncthreads();

        if (k0 + 16 < K) {
#pragma unroll
            for (int i = 0; i < 2; ++i) {
                ga[i] = *(const float4*)(aptr[i] + k0 + 16);
                gb[i] = *(const float4*)(bptr[i] + (size_t)(k0 + 16) * N);
            }
        }

#pragma unroll
        for (int ks = 0; ks < 2; ++ks) {
            const int kk = ks * 8;
            float bH[8][2], bL[8][2];
#pragma unroll
            for (int tn = 0; tn < 8; ++tn) {
                int col = wn * 64 + tn * 8 + g;
                bH[tn][0] = BsH[kk + q][col];     bH[tn][1] = BsH[kk + q + 4][col];
                bL[tn][0] = BsL[kk + q][col];     bL[tn][1] = BsL[kk + q + 4][col];
            }
#pragma unroll
            for (int tm = 0; tm < 2; ++tm) {
                int r0 = wm * 32 + tm * 16 + g;
                float aH[4], aL[4];
                aH[0] = AsH[r0][kk + q];     aH[1] = AsH[r0 + 8][kk + q];
                aH[2] = AsH[r0][kk + q + 4]; aH[3] = AsH[r0 + 8][kk + q + 4];
                aL[0] = AsL[r0][kk + q];     aL[1] = AsL[r0 + 8][kk + q];
                aL[2] = AsL[r0][kk + q + 4]; aL[3] = AsL[r0 + 8][kk + q + 4];
#pragma unroll
                for (int tn = 0; tn < 8; ++tn) {
                    mma_tf32(acc[tm][tn], aH, bH[tn]);
                    mma_tf32(acc[tm][tn], aH, bL[tn]);
                    mma_tf32(acc[tm][tn], aL, bH[tn]);
                }
            }
        }
        __syncthreads();
    }

    float* Cb = C + (size_t)batch * sC;
#pragma unroll
    for (int tm = 0; tm < 2; ++tm) {
#pragma unroll
        for (int tn = 0; tn < 8; ++tn) {
            int row = rowBase + wm * 32 + tm * 16 + g;
            int col = colBase + wn * 64 + tn * 8 + 2 * q;
            float b0 = bias[col], b1 = bias[col + 1];
            float2 v0 = make_float2(acc[tm][tn][0] + b0, acc[tm][tn][1] + b1);
            float2 v1 = make_float2(acc[tm][tn][2] + b0, acc[tm][tn][3] + b1);
            *(float2*)(Cb + (size_t)row * N + col) = v0;
            *(float2*)(Cb + (size_t)(row + 8) * N + col) = v1;
        }
    }
}

// ---------------- small scalar GEMM with bias (pos': N=64) ----------------
__global__ __launch_bounds__(256) void gemm_bias(
    const float* __restrict__ A, const float* __restrict__ Bm, const float* __restrict__ bias,
    float* __restrict__ C, int M, int N, int K)
{
    __shared__ float As[16][65];
    __shared__ float Bs[16][64];

    const int rowBase = blockIdx.y * 64;
    const int colBase = blockIdx.x * 64;
    const int tid = threadIdx.x;
    const int tx = tid & 15, ty = tid >> 4;

    const int arow = tid >> 2;
    const int ac   = (tid & 3) * 4;
    const int brow = tid >> 4;
    const int bc   = (tid & 15) * 4;

    const float* Aptr = A + (size_t)(rowBase + arow) * K;
    float acc[4][4] = {};

    for (int k0 = 0; k0 < K; k0 += 16) {
        float4 av = *(const float4*)(Aptr + k0 + ac);
        float4 bv = *(const float4*)(Bm + (size_t)(k0 + brow) * N + colBase + bc);
        __syncthreads();
        As[ac + 0][arow] = av.x; As[ac + 1][arow] = av.y;
        As[ac + 2][arow] = av.z; As[ac + 3][arow] = av.w;
        *(float4*)&Bs[brow][bc] = bv;
        __syncthreads();
#pragma unroll
        for (int kk = 0; kk < 16; ++kk) {
            float a0 = As[kk][ty * 4 + 0], a1 = As[kk][ty * 4 + 1];
            float a2 = As[kk][ty * 4 + 2], a3 = As[kk][ty * 4 + 3];
            float4 b4 = *(const float4*)&Bs[kk][tx * 4];
            acc[0][0] += a0 * b4.x; acc[0][1] += a0 * b4.y; acc[0][2] += a0 * b4.z; acc[0][3] += a0 * b4.w;
            acc[1][0] += a1 * b4.x; acc[1][1] += a1 * b4.y; acc[1][2] += a1 * b4.z; acc[1][3] += a1 * b4.w;
            acc[2][0] += a2 * b4.x; acc[2][1] += a2 * b4.y; acc[2][2] += a2 * b4.z; acc[2][3] += a2 * b4.w;
            acc[3][0] += a3 * b4.x; acc[3][1] += a3 * b4.y; acc[3][2] += a3 * b4.z; acc[3][3] += a3 * b4.w;
        }
    }

    float4 bvv = *(const float4*)(bias + colBase + tx * 4);
#pragma unroll
    for (int a = 0; a < 4; ++a) {
        int row = rowBase + ty * 4 + a;
        float4 o;
        o.x = acc[a][0] + bvv.x; o.y = acc[a][1] + bvv.y;
        o.z = acc[a][2] + bvv.z; o.w = acc[a][3] + bvv.w;
        *(float4*)(C + (size_t)row * N + colBase + tx * 4) = o;
    }
}

// ---------------- skewed pos-dots kernel v2 (fixed pbase) ----------------
// Tile: 256 (j2) x 64 (i), microtile 16x4 per thread, d in 4 passes of 16.
// PDT[b,h][j2][i] = SCALE * sum_d Q[b,i,h*64+d] * pos'[j2 - i + 2047][d]
// Slab row s maps to pidx = pbase + s with pbase = J - I + 1984
// (element slab row: s = 16*ty + a - 4*tx - c + 63 -> pidx = (j2 - i) + 2047).
__global__ __launch_bounds__(256) void pdt_kernel(
    const float* __restrict__ Q, const float* __restrict__ Pos, float* __restrict__ PDT)
{
    const int bh = blockIdx.z;
    const int b  = bh >> 4, h = bh & 15;
    const int I  = blockIdx.x * 64;
    const int J  = blockIdx.y * 256;
    if (J > I + 63) return;              // entire tile above diagonal: never read

    __shared__ float Qs[64][17];
    __shared__ float Ps[319][17];

    const int tid = threadIdx.x;
    const int pbase = J - I + 1984;      // pos index for slab row 0

    const int tx = tid & 15, ty = tid >> 4;
    const int s0 = 16 * ty - 4 * tx + 63;   // slab row for (a=0,c=0)
    float acc[16][4];
#pragma unroll
    for (int a = 0; a < 16; ++a)
#pragma unroll
        for (int c = 0; c < 4; ++c) acc[a][c] = 0.f;

    const int lrow = tid >> 2;            // 0..63
    const int lc4  = (tid & 3) * 4;       // 0,4,8,12

#pragma unroll
    for (int dp = 0; dp < 4; ++dp) {
        const int dbase = dp * 16;
        // load Q sub-tile (64 rows x 16 d)
        {
            const float* src = Q + ((size_t)(b * N_ + I + lrow)) * DIM_ + h * DH_ + dbase + lc4;
            float4 v = *(const float4*)src;
            Qs[lrow][lc4 + 0] = v.x; Qs[lrow][lc4 + 1] = v.y;
            Qs[lrow][lc4 + 2] = v.z; Qs[lrow][lc4 + 3] = v.w;
        }
        // load pos slab (319 rows x 16 d), zero-fill out-of-range
        for (int s = lrow; s < 319; s += 64) {
            int pidx = pbase + s;
            bool ok = (pidx >= 0) && (pidx < N_);
            const float* src = Pos + (size_t)(ok ? pidx : 0) * DH_ + dbase + lc4;
            float4 v = ok ? *(const float4*)src : make_float4(0.f, 0.f, 0.f, 0.f);
            Ps[s][lc4 + 0] = v.x; Ps[s][lc4 + 1] = v.y;
            Ps[s][lc4 + 2] = v.z; Ps[s][lc4 + 3] = v.w;
        }
        __syncthreads();

#pragma unroll 4
        for (int d = 0; d < 16; ++d) {
            float qv[4], pv[19];
#pragma unroll
            for (int c = 0; c < 4; ++c) qv[c] = Qs[4 * tx + c][d];
#pragma unroll
            for (int t = 0; t < 19; ++t) pv[t] = Ps[s0 - 3 + t][d];
#pragma unroll
            for (int a = 0; a < 16; ++a)
#pragma unroll
                for (int c = 0; c < 4; ++c)
                    acc[a][c] += pv[a - c + 3] * qv[c];
        }
        __syncthreads();
    }

    float* base = PDT + ((size_t)bh << 22);
#pragma unroll
    for (int a = 0; a < 16; ++a) {
        int j2 = J + 16 * ty + a;
        float4 o;
        o.x = SCALE_ * acc[a][0]; o.y = SCALE_ * acc[a][1];
        o.z = SCALE_ * acc[a][2]; o.w = SCALE_ * acc[a][3];
        *(float4*)(base + (size_t)j2 * N_ + I + 4 * tx) = o;
    }
}

// ---------------- fused online-softmax attention v2 ----------------
__device__ __forceinline__ void cp_async16(void* s, const void* g)
{
    unsigned a = (unsigned)__cvta_generic_to_shared(s);
    asm volatile("cp.async.cg.shared.global [%0], [%1], 16;" :: "r"(a), "l"(g));
}

__device__ __forceinline__ float dot64(const float4* __restrict__ q, const float4* __restrict__ k)
{
    float s = 0.f;
#pragma unroll
    for (int d = 0; d < 16; ++d) {
        float4 kk = k[d];
        s += q[d].x * kk.x + q[d].y * kk.y + q[d].z * kk.z + q[d].w * kk.w;
    }
    return s;
}

__device__ __forceinline__ void sm_update(float s, float em, float& m, float& l,
                                          float4* __restrict__ o, const float4* __restrict__ vrow)
{
    if (s > m) {
        float f = __expf(m - s);
        l *= f;
#pragma unroll
        for (int d = 0; d < 16; ++d) { o[d].x *= f; o[d].y *= f; o[d].z *= f; o[d].w *= f; }
        m = s;
    }
    float p = __expf(s - m);
    l += p;
    float pe = p * em;
#pragma unroll
    for (int d = 0; d < 16; ++d) {
        float4 v = vrow[d];
        o[d].x += pe * v.x; o[d].y += pe * v.y; o[d].z += pe * v.z; o[d].w += pe * v.w;
    }
}

__global__ __launch_bounds__(128) void attn_kernel(
    const float* __restrict__ Q, const float* __restrict__ KV,
    const float* __restrict__ PDT, const float* __restrict__ expire,
    float* __restrict__ O)
{
    const int b = blockIdx.z, h = blockIdx.y;
    const int tid = threadIdx.x;
    const int I0 = blockIdx.x * 128;
    const int i = I0 + tid;

    __shared__ float4 ks[2][32][16];
    __shared__ float4 vs[2][32][16];
    __shared__ float em_s[MEM_];

    // stage expire mask once (covered by first in-loop __syncthreads)
    {
        const float* emp = expire + b * MEM_;
#pragma unroll
        for (int u = 0; u < 2; ++u)
            *(float4*)&em_s[(tid + u * 128) * 4] = *(const float4*)(emp + (tid + u * 128) * 4);
    }

    float4 q[16], o[16];
    {
        const float4* qsrc = (const float4*)(Q + ((size_t)(b * N_ + i)) * DIM_ + h * DH_);
#pragma unroll
        for (int d = 0; d < 16; ++d) { q[d] = qsrc[d]; o[d] = make_float4(0.f, 0.f, 0.f, 0.f); }
    }
    float m = -1e30f, l = 0.f;

    const float* pdt = PDT + (((size_t)(b * H_ + h)) << 22) + i;
    const float* kvbase = KV + (size_t)b * CTX_ * (2 * DIM_) + h * DH_;
    const int ntiles = (I0 + 127 + MEM_) / 32 + 1;

    // prefetch tile 0
    {
#pragma unroll
        for (int r = 0; r < 4; ++r) {
            int idx = tid + r * 128;
            int row = idx >> 4, c = idx & 15;
            const float* src = kvbase + (size_t)row * (2 * DIM_) + c * 4;
            cp_async16(&ks[0][row][c], src);
            cp_async16(&vs[0][row][c], src + DIM_);
        }
    }
    asm volatile("cp.async.commit_group;");

    for (int t = 0; t < ntiles; ++t) {
        const int st = t & 1;
        const int j0 = t * 32;
        if (t + 1 < ntiles) {
            const int jn = j0 + 32;
#pragma unroll
            for (int r = 0; r < 4; ++r) {
                int idx = tid + r * 128;
                int row = idx >> 4, c = idx & 15;
                const float* src = kvbase + (size_t)(jn + row) * (2 * DIM_) + c * 4;
                cp_async16(&ks[st ^ 1][row][c], src);
                cp_async16(&vs[st ^ 1][row][c], src + DIM_);
            }
        }
        asm volatile("cp.async.commit_group;");
        asm volatile("cp.async.wait_group 1;");
        __syncthreads();

        const float4 (*kt)[16] = ks[st];
        const float4 (*vt)[16] = vs[st];

        if (j0 + 32 <= MEM_) {
            // memory keys: expire weight, no pos term, all valid
#pragma unroll 2
            for (int g4 = 0; g4 < 8; ++g4) {
                float s4[4];
#pragma unroll
                for (int u = 0; u < 4; ++u) s4[u] = dot64(q, kt[g4 * 4 + u]) * SCALE_;
#pragma unroll
                for (int u = 0; u < 4; ++u) sm_update(s4[u], em_s[j0 + g4 * 4 + u], m, l, o, vt[g4 * 4 + u]);
            }
        } else if (j0 - MEM_ + 31 <= I0) {
            // current keys, fully valid for every thread in block
#pragma unroll 2
            for (int g4 = 0; g4 < 8; ++g4) {
                float pd[4], s4[4];
#pragma unroll
                for (int u = 0; u < 4; ++u) pd[u] = pdt[(size_t)(j0 + g4 * 4 + u - MEM_) * N_];
#pragma unroll
                for (int u = 0; u < 4; ++u) s4[u] = dot64(q, kt[g4 * 4 + u]) * SCALE_ + pd[u];
#pragma unroll
                for (int u = 0; u < 4; ++u) sm_update(s4[u], 1.f, m, l, o, vt[g4 * 4 + u]);
            }
        } else {
            // boundary tiles (<=5 per block): per-thread valid count
            int nv = i + MEM_ + 1 - j0;
            nv = nv < 0 ? 0 : (nv > 32 ? 32 : nv);
            for (int jj = 0; jj < nv; ++jj) {
                float s = dot64(q, kt[jj]) * SCALE_ + pdt[(size_t)(j0 + jj - MEM_) * N_];
                sm_update(s, 1.f, m, l, o, vt[jj]);
            }
        }
        __syncthreads();
    }

    float inv = 1.f / l;
    float4* dst = (float4*)(O + ((size_t)(b * N_ + i)) * DIM_ + h * DH_);
#pragma unroll
    for (int d = 0; d < 16; ++d) {
        float4 v; v.x = o[d].x * inv; v.y = o[d].y * inv; v.z = o[d].z * inv; v.w = o[d].w * inv;
        dst[d] = v;
    }
}

// ---------------- launcher ----------------
extern "C" void kernel_launch(void* const* d_in, const int* in_sizes, int n_in,
                              void* d_out, int out_size)
{
    const float* x       = (const float*)d_in[0];
    const float* pos_emb = (const float*)d_in[1];
    const float* mem     = (const float*)d_in[2];
    const float* expire  = (const float*)d_in[3];
    const float* Wq      = (const float*)d_in[4];
    const float* bq      = (const float*)d_in[5];
    const float* Wkv     = (const float*)d_in[6];
    const float* bkv     = (const float*)d_in[7];
    const float* Wo      = (const float*)d_in[8];
    const float* bo      = (const float*)d_in[9];
    const float* Wp      = (const float*)d_in[10];
    const float* bp      = (const float*)d_in[11];
    float* out = (float*)d_out;

    float *Q, *KV, *Pos, *PDT, *O;
    cudaGetSymbolAddress((void**)&Q,   g_Q);
    cudaGetSymbolAddress((void**)&KV,  g_KV);
    cudaGetSymbolAddress((void**)&Pos, g_pos);
    cudaGetSymbolAddress((void**)&PDT, g_PDT);
    cudaGetSymbolAddress((void**)&O,   g_O);

    // 1) Q = x @ Wq + bq          (fold batch: M=4096, N=1024)
    gemm_tf32<<<dim3(DIM_ / 128, (B_ * N_) / 128, 1), 256>>>(
        x, B_ * N_, 0, x, 0, Wq, bq, Q, 0, DIM_, DIM_);

    // 2) KV = concat(mem, x) @ Wkv + bkv    (per batch: M=3072, N=2048)
    gemm_tf32<<<dim3(2 * DIM_ / 128, CTX_ / 128, B_), 256>>>(
        mem, MEM_, (size_t)MEM_ * DIM_, x, (size_t)N_ * DIM_,
        Wkv, bkv, KV, (size_t)CTX_ * 2 * DIM_, 2 * DIM_, DIM_);

    // 3) pos' = pos_emb @ Wp + bp           [2048,64]
    gemm_bias<<<dim3(1, N_ / 64, 1), 256>>>(pos_emb, Wp, bp, Pos, N_, DH_, DIM_);

    // 4) PDT (shifted, transposed, pre-scaled pos dots)
    pdt_kernel<<<dim3(N_ / 64, N_ / 256, B_ * H_), 256>>>(Q, Pos, PDT);

    // 5) fused attention -> O
    attn_kernel<<<dim3(N_ / 128, H_, B_), 128>>>(Q, KV, PDT, expire, O);

    // 6) out = O @ Wo + bo        (fold batch: M=4096, N=1024)
    gemm_tf32<<<dim3(DIM_ / 128, (B_ * N_) / 128, 1), 256>>>(
        O, B_ * N_, 0, O, 0, Wo, bo, out, 0, DIM_, DIM_);
}

// round 7
// speedup vs baseline: 2.6037x; 1.5593x over previous
#include <cuda_runtime.h>
#include <cstdint>
#include <cstddef>

#define B_    2
#define N_    2048
#define DIM_  1024
#define H_    16
#define DH_   64
#define MEM_  1024
#define CTX_  3072
#define SCALE_ 0.125f

// ---------------- scratch (static device globals; no allocation) ----------------
__device__ float g_Q  [B_ * N_ * DIM_];          // 16 MB
__device__ float g_KV [B_ * CTX_ * 2 * DIM_];    // 48 MB
__device__ float g_pos[N_ * DH_];                // 512 KB
__device__ float g_PDT[134217728];               // 512 MB  PDT[b,h][j2][i]
__device__ float g_O  [B_ * N_ * DIM_];          // 16 MB

// =====================================================================
// Common tf32 helpers (fragment layouts HW-verified by gemm_tf32)
// =====================================================================
__device__ __forceinline__ void mma_tf32(float* c, const float* a, const float* b)
{
    asm volatile(
        "mma.sync.aligned.m16n8k8.row.col.f32.tf32.tf32.f32 "
        "{%0,%1,%2,%3}, {%4,%5,%6,%7}, {%8,%9}, {%0,%1,%2,%3};\n"
        : "+f"(c[0]), "+f"(c[1]), "+f"(c[2]), "+f"(c[3])
        : "r"(__float_as_uint(a[0])), "r"(__float_as_uint(a[1])),
          "r"(__float_as_uint(a[2])), "r"(__float_as_uint(a[3])),
          "r"(__float_as_uint(b[0])), "r"(__float_as_uint(b[1])));
}

__device__ __forceinline__ void split1(float v, float& h, float& l)
{
    unsigned hu;
    asm("cvt.rna.tf32.f32 %0, %1;" : "=r"(hu) : "f"(v));
    h = __uint_as_float(hu);
    float r = v - h;
    unsigned lu;
    asm("cvt.rna.tf32.f32 %0, %1;" : "=r"(lu) : "f"(r));
    l = __uint_as_float(lu);
}

__device__ __forceinline__ void split4(float4 v, float4& h, float4& l)
{
    split1(v.x, h.x, l.x); split1(v.y, h.y, l.y);
    split1(v.z, h.z, l.z); split1(v.w, h.w, l.w);
}

__device__ __forceinline__ void cp_async16(void* s, const void* g)
{
    unsigned a = (unsigned)__cvta_generic_to_shared(s);
    asm volatile("cp.async.cg.shared.global [%0], [%1], 16;" :: "r"(a), "l"(g));
}

// =====================================================================
// Split-tf32 tensor-core GEMM:  C = A @ B + bias   (fp32-accurate, 3xTF32)
// =====================================================================
__global__ __launch_bounds__(256) void gemm_tf32(
    const float* __restrict__ Alo, int MLo, size_t sAlo,
    const float* __restrict__ Ahi, size_t sAhi,
    const float* __restrict__ Bm, const float* __restrict__ bias,
    float* __restrict__ C, size_t sC,
    int N, int K)
{
    __shared__ __align__(16) float AsH[128][20];
    __shared__ __align__(16) float AsL[128][20];
    __shared__ __align__(16) float BsH[16][136];
    __shared__ __align__(16) float BsL[16][136];

    const int batch   = blockIdx.z;
    const int rowBase = blockIdx.y * 128;
    const int colBase = blockIdx.x * 128;
    const int tid  = threadIdx.x;
    const int wid  = tid >> 5, lane = tid & 31;
    const int wm   = wid & 3,  wn   = wid >> 2;
    const int g    = lane >> 2, q   = lane & 3;

    const int ar = tid >> 2;
    const int ac = (tid & 3) * 4;
    const float* aptr[2];
#pragma unroll
    for (int i = 0; i < 2; ++i) {
        int r = rowBase + ar + 64 * i;
        aptr[i] = ((r < MLo) ? (Alo + (size_t)batch * sAlo + (size_t)r * K)
                             : (Ahi + (size_t)batch * sAhi + (size_t)(r - MLo) * K)) + ac;
    }
    const int kr = tid >> 5;
    const int bc = (lane) * 4;
    const float* bptr[2];
#pragma unroll
    for (int i = 0; i < 2; ++i)
        bptr[i] = Bm + (size_t)(kr + 8 * i) * N + colBase + bc;

    float4 ga[2], gb[2];
#pragma unroll
    for (int i = 0; i < 2; ++i) { ga[i] = *(const float4*)(aptr[i]); gb[i] = *(const float4*)(bptr[i]); }

    float acc[2][8][4];
#pragma unroll
    for (int a = 0; a < 2; ++a)
#pragma unroll
        for (int b = 0; b < 8; ++b)
#pragma unroll
            for (int c = 0; c < 4; ++c) acc[a][b][c] = 0.f;

    for (int k0 = 0; k0 < K; k0 += 16) {
#pragma unroll
        for (int i = 0; i < 2; ++i) {
            float4 h, l;
            split4(ga[i], h, l);
            *(float4*)&AsH[ar + 64 * i][ac] = h;
            *(float4*)&AsL[ar + 64 * i][ac] = l;
            split4(gb[i], h, l);
            *(float4*)&BsH[kr + 8 * i][bc] = h;
            *(float4*)&BsL[kr + 8 * i][bc] = l;
        }
        __syncthreads();

        if (k0 + 16 < K) {
#pragma unroll
            for (int i = 0; i < 2; ++i) {
                ga[i] = *(const float4*)(aptr[i] + k0 + 16);
                gb[i] = *(const float4*)(bptr[i] + (size_t)(k0 + 16) * N);
            }
        }

#pragma unroll
        for (int ks = 0; ks < 2; ++ks) {
            const int kk = ks * 8;
            float bH[8][2], bL[8][2];
#pragma unroll
            for (int tn = 0; tn < 8; ++tn) {
                int col = wn * 64 + tn * 8 + g;
                bH[tn][0] = BsH[kk + q][col];     bH[tn][1] = BsH[kk + q + 4][col];
                bL[tn][0] = BsL[kk + q][col];     bL[tn][1] = BsL[kk + q + 4][col];
            }
#pragma unroll
            for (int tm = 0; tm < 2; ++tm) {
                int r0 = wm * 32 + tm * 16 + g;
                float aH[4], aL[4];
                aH[0] = AsH[r0][kk + q];     aH[1] = AsH[r0 + 8][kk + q];
                aH[2] = AsH[r0][kk + q + 4]; aH[3] = AsH[r0 + 8][kk + q + 4];
                aL[0] = AsL[r0][kk + q];     aL[1] = AsL[r0 + 8][kk + q];
                aL[2] = AsL[r0][kk + q + 4]; aL[3] = AsL[r0 + 8][kk + q + 4];
#pragma unroll
                for (int tn = 0; tn < 8; ++tn) {
                    mma_tf32(acc[tm][tn], aH, bH[tn]);
                    mma_tf32(acc[tm][tn], aH, bL[tn]);
                    mma_tf32(acc[tm][tn], aL, bH[tn]);
                }
            }
        }
        __syncthreads();
    }

    float* Cb = C + (size_t)batch * sC;
#pragma unroll
    for (int tm = 0; tm < 2; ++tm) {
#pragma unroll
        for (int tn = 0; tn < 8; ++tn) {
            int row = rowBase + wm * 32 + tm * 16 + g;
            int col = colBase + wn * 64 + tn * 8 + 2 * q;
            float b0 = bias[col], b1 = bias[col + 1];
            float2 v0 = make_float2(acc[tm][tn][0] + b0, acc[tm][tn][1] + b1);
            float2 v1 = make_float2(acc[tm][tn][2] + b0, acc[tm][tn][3] + b1);
            *(float2*)(Cb + (size_t)row * N + col) = v0;
            *(float2*)(Cb + (size_t)(row + 8) * N + col) = v1;
        }
    }
}

// ---------------- small scalar GEMM with bias (pos': N=64) ----------------
__global__ __launch_bounds__(256) void gemm_bias(
    const float* __restrict__ A, const float* __restrict__ Bm, const float* __restrict__ bias,
    float* __restrict__ C, int M, int N, int K)
{
    __shared__ float As[16][65];
    __shared__ float Bs[16][64];

    const int rowBase = blockIdx.y * 64;
    const int colBase = blockIdx.x * 64;
    const int tid = threadIdx.x;
    const int tx = tid & 15, ty = tid >> 4;

    const int arow = tid >> 2;
    const int ac   = (tid & 3) * 4;
    const int brow = tid >> 4;
    const int bc   = (tid & 15) * 4;

    const float* Aptr = A + (size_t)(rowBase + arow) * K;
    float acc[4][4] = {};

    for (int k0 = 0; k0 < K; k0 += 16) {
        float4 av = *(const float4*)(Aptr + k0 + ac);
        float4 bv = *(const float4*)(Bm + (size_t)(k0 + brow) * N + colBase + bc);
        __syncthreads();
        As[ac + 0][arow] = av.x; As[ac + 1][arow] = av.y;
        As[ac + 2][arow] = av.z; As[ac + 3][arow] = av.w;
        *(float4*)&Bs[brow][bc] = bv;
        __syncthreads();
#pragma unroll
        for (int kk = 0; kk < 16; ++kk) {
            float a0 = As[kk][ty * 4 + 0], a1 = As[kk][ty * 4 + 1];
            float a2 = As[kk][ty * 4 + 2], a3 = As[kk][ty * 4 + 3];
            float4 b4 = *(const float4*)&Bs[kk][tx * 4];
            acc[0][0] += a0 * b4.x; acc[0][1] += a0 * b4.y; acc[0][2] += a0 * b4.z; acc[0][3] += a0 * b4.w;
            acc[1][0] += a1 * b4.x; acc[1][1] += a1 * b4.y; acc[1][2] += a1 * b4.z; acc[1][3] += a1 * b4.w;
            acc[2][0] += a2 * b4.x; acc[2][1] += a2 * b4.y; acc[2][2] += a2 * b4.z; acc[2][3] += a2 * b4.w;
            acc[3][0] += a3 * b4.x; acc[3][1] += a3 * b4.y; acc[3][2] += a3 * b4.z; acc[3][3] += a3 * b4.w;
        }
    }

    float4 bvv = *(const float4*)(bias + colBase + tx * 4);
#pragma unroll
    for (int a = 0; a < 4; ++a) {
        int row = rowBase + ty * 4 + a;
        float4 o;
        o.x = acc[a][0] + bvv.x; o.y = acc[a][1] + bvv.y;
        o.z = acc[a][2] + bvv.z; o.w = acc[a][3] + bvv.w;
        *(float4*)(C + (size_t)row * N + colBase + tx * 4) = o;
    }
}

// ---------------- skewed pos-dots kernel v2 ----------------
__global__ __launch_bounds__(256) void pdt_kernel(
    const float* __restrict__ Q, const float* __restrict__ Pos, float* __restrict__ PDT)
{
    const int bh = blockIdx.z;
    const int b  = bh >> 4, h = bh & 15;
    const int I  = blockIdx.x * 64;
    const int J  = blockIdx.y * 256;
    if (J > I + 63) return;

    __shared__ float Qs[64][17];
    __shared__ float Ps[319][17];

    const int tid = threadIdx.x;
    const int pbase = J - I + 1984;

    const int tx = tid & 15, ty = tid >> 4;
    const int s0 = 16 * ty - 4 * tx + 63;
    float acc[16][4];
#pragma unroll
    for (int a = 0; a < 16; ++a)
#pragma unroll
        for (int c = 0; c < 4; ++c) acc[a][c] = 0.f;

    const int lrow = tid >> 2;
    const int lc4  = (tid & 3) * 4;

#pragma unroll
    for (int dp = 0; dp < 4; ++dp) {
        const int dbase = dp * 16;
        {
            const float* src = Q + ((size_t)(b * N_ + I + lrow)) * DIM_ + h * DH_ + dbase + lc4;
            float4 v = *(const float4*)src;
            Qs[lrow][lc4 + 0] = v.x; Qs[lrow][lc4 + 1] = v.y;
            Qs[lrow][lc4 + 2] = v.z; Qs[lrow][lc4 + 3] = v.w;
        }
        for (int s = lrow; s < 319; s += 64) {
            int pidx = pbase + s;
            bool ok = (pidx >= 0) && (pidx < N_);
            const float* src = Pos + (size_t)(ok ? pidx : 0) * DH_ + dbase + lc4;
            float4 v = ok ? *(const float4*)src : make_float4(0.f, 0.f, 0.f, 0.f);
            Ps[s][lc4 + 0] = v.x; Ps[s][lc4 + 1] = v.y;
            Ps[s][lc4 + 2] = v.z; Ps[s][lc4 + 3] = v.w;
        }
        __syncthreads();

#pragma unroll 4
        for (int d = 0; d < 16; ++d) {
            float qv[4], pv[19];
#pragma unroll
            for (int c = 0; c < 4; ++c) qv[c] = Qs[4 * tx + c][d];
#pragma unroll
            for (int t = 0; t < 19; ++t) pv[t] = Ps[s0 - 3 + t][d];
#pragma unroll
            for (int a = 0; a < 16; ++a)
#pragma unroll
                for (int c = 0; c < 4; ++c)
                    acc[a][c] += pv[a - c + 3] * qv[c];
        }
        __syncthreads();
    }

    float* base = PDT + ((size_t)bh << 22);
#pragma unroll
    for (int a = 0; a < 16; ++a) {
        int j2 = J + 16 * ty + a;
        float4 o;
        o.x = SCALE_ * acc[a][0]; o.y = SCALE_ * acc[a][1];
        o.z = SCALE_ * acc[a][2]; o.w = SCALE_ * acc[a][3];
        *(float4*)(base + (size_t)j2 * N_ + I + 4 * tx) = o;
    }
}

// =====================================================================
// Tensor-core flash attention (split-tf32, 64 q-rows/block, 4 warps)
// =====================================================================
#define KVSTRIDE 76
#define PSTRIDE  36
#define SMEM_ATTN ((2 * 32 * KVSTRIDE * 3 + 2 * 64 * PSTRIDE + 1024) * 4)

__global__ __launch_bounds__(128) void attn_kernel(
    const float* __restrict__ Q, const float* __restrict__ KV,
    const float* __restrict__ PDT, const float* __restrict__ expire,
    float* __restrict__ O)
{
    extern __shared__ float smf[];
    float* Kb   = smf;                             // [2][32][76]
    float* Vb   = Kb + 2 * 32 * KVSTRIDE;          // [2][32][76]
    float* Pdm  = Vb + 2 * 32 * KVSTRIDE;          // [2][32][76]
    float* Ph   = Pdm + 2 * 32 * KVSTRIDE;         // [64][36]
    float* Pl   = Ph + 64 * PSTRIDE;               // [64][36]
    float* em_s = Pl + 64 * PSTRIDE;               // [1024]

    const int b = blockIdx.z, h = blockIdx.y;
    const int tid = threadIdx.x;
    const int I0 = blockIdx.x * 64;
    const int W = tid >> 5, lane = tid & 31;
    const int g = lane >> 2, qq = lane & 3;

    // stage expire mask
    {
        const float* emp = expire + b * MEM_;
        *(float4*)&em_s[tid * 8]     = *(const float4*)(emp + tid * 8);
        *(float4*)&em_s[tid * 8 + 4] = *(const float4*)(emp + tid * 8 + 4);
    }

    // Q fragments (pre-scaled by SCALE_, 3-split) in registers
    float aH[8][4], aL[8][4];
    {
        const float* q0 = Q + ((size_t)(b * N_) + I0 + W * 16 + g) * DIM_ + h * DH_;
        const float* q8 = q0 + 8 * DIM_;
#pragma unroll
        for (int ks = 0; ks < 8; ++ks) {
            split1(q0[ks * 8 + qq]     * SCALE_, aH[ks][0], aL[ks][0]);
            split1(q8[ks * 8 + qq]     * SCALE_, aH[ks][1], aL[ks][1]);
            split1(q0[ks * 8 + qq + 4] * SCALE_, aH[ks][2], aL[ks][2]);
            split1(q8[ks * 8 + qq + 4] * SCALE_, aH[ks][3], aL[ks][3]);
        }
    }

    float o[8][4];
#pragma unroll
    for (int t = 0; t < 8; ++t)
#pragma unroll
        for (int c = 0; c < 4; ++c) o[t][c] = 0.f;
    float m0 = -1e30f, m1 = -1e30f, l0 = 0.f, l1 = 0.f;

    const float* kvbase = KV + (size_t)b * CTX_ * (2 * DIM_) + h * DH_;
    const float* pdtb   = PDT + (((size_t)(b * H_ + h)) << 22);
    const int ntiles = (MEM_ + I0 + 64) / 32;

    // prefetch tile 0 (mem tile: K/V only)
#pragma unroll
    for (int u = 0; u < 4; ++u) {
        int e = u * 128 + tid, row = e >> 4, c = e & 15;
        const float* src = kvbase + (size_t)row * (2 * DIM_) + c * 4;
        cp_async16(Kb + row * KVSTRIDE + c * 4, src);
        cp_async16(Vb + row * KVSTRIDE + c * 4, src + DIM_);
    }
    asm volatile("cp.async.commit_group;");

    for (int t = 0; t < ntiles; ++t) {
        const int st = t & 1;
        const int j0 = t * 32;
        if (t + 1 < ntiles) {
            const int jn = j0 + 32;
            float* Kd = Kb + (st ^ 1) * 32 * KVSTRIDE;
            float* Vd = Vb + (st ^ 1) * 32 * KVSTRIDE;
#pragma unroll
            for (int u = 0; u < 4; ++u) {
                int e = u * 128 + tid, row = e >> 4, c = e & 15;
                const float* src = kvbase + (size_t)(jn + row) * (2 * DIM_) + c * 4;
                cp_async16(Kd + row * KVSTRIDE + c * 4, src);
                cp_async16(Vd + row * KVSTRIDE + c * 4, src + DIM_);
            }
            if (jn >= MEM_) {
                float* Pdd = Pdm + (st ^ 1) * 32 * KVSTRIDE;
#pragma unroll
                for (int u = 0; u < 4; ++u) {
                    int e = u * 128 + tid, row = e >> 4, c = e & 15;
                    cp_async16(Pdd + row * KVSTRIDE + c * 4,
                               pdtb + (size_t)(jn - MEM_ + row) * N_ + I0 + c * 4);
                }
            }
        }
        asm volatile("cp.async.commit_group;");
        asm volatile("cp.async.wait_group 1;");
        __syncthreads();

        const float* Kc = Kb + st * 32 * KVSTRIDE;
        const float* Vc = Vb + st * 32 * KVSTRIDE;
        const float* Pc = Pdm + st * 32 * KVSTRIDE;

        // ---- S = Q K^T (3-split) ----
        float s[4][4];
#pragma unroll
        for (int tt = 0; tt < 4; ++tt)
#pragma unroll
            for (int c = 0; c < 4; ++c) s[tt][c] = 0.f;

#pragma unroll
        for (int ks = 0; ks < 8; ++ks) {
#pragma unroll
            for (int tt = 0; tt < 4; ++tt) {
                float r0 = Kc[(tt * 8 + g) * KVSTRIDE + ks * 8 + qq];
                float r1 = Kc[(tt * 8 + g) * KVSTRIDE + ks * 8 + qq + 4];
                float bh[2], bl[2];
                split1(r0, bh[0], bl[0]);
                split1(r1, bh[1], bl[1]);
                mma_tf32(s[tt], aH[ks], bh);
                mma_tf32(s[tt], aH[ks], bl);
                mma_tf32(s[tt], aL[ks], bh);
            }
        }

        const bool isMem = (j0 < MEM_);
        if (!isMem) {
            const int il0 = W * 16 + g, il1 = il0 + 8;
#pragma unroll
            for (int tt = 0; tt < 4; ++tt) {
                int c0 = tt * 8 + 2 * qq;
                s[tt][0] += Pc[c0 * KVSTRIDE + il0];
                s[tt][1] += Pc[(c0 + 1) * KVSTRIDE + il0];
                s[tt][2] += Pc[c0 * KVSTRIDE + il1];
                s[tt][3] += Pc[(c0 + 1) * KVSTRIDE + il1];
            }
            if (j0 - MEM_ + 31 > I0) {
                const int jb = j0 - MEM_;
                const int r0 = I0 + W * 16 + g, r1 = r0 + 8;
#pragma unroll
                for (int tt = 0; tt < 4; ++tt) {
                    int c0 = jb + tt * 8 + 2 * qq;
                    if (c0     > r0) s[tt][0] = -1e30f;
                    if (c0 + 1 > r0) s[tt][1] = -1e30f;
                    if (c0     > r1) s[tt][2] = -1e30f;
                    if (c0 + 1 > r1) s[tt][3] = -1e30f;
                }
            }
        }

        // ---- online softmax (rows g / g+8) ----
        float mt0 = fmaxf(fmaxf(s[0][0], s[0][1]), fmaxf(s[1][0], s[1][1]));
        mt0 = fmaxf(mt0, fmaxf(fmaxf(s[2][0], s[2][1]), fmaxf(s[3][0], s[3][1])));
        float mt1 = fmaxf(fmaxf(s[0][2], s[0][3]), fmaxf(s[1][2], s[1][3]));
        mt1 = fmaxf(mt1, fmaxf(fmaxf(s[2][2], s[2][3]), fmaxf(s[3][2], s[3][3])));
        mt0 = fmaxf(mt0, __shfl_xor_sync(0xffffffffu, mt0, 1));
        mt0 = fmaxf(mt0, __shfl_xor_sync(0xffffffffu, mt0, 2));
        mt1 = fmaxf(mt1, __shfl_xor_sync(0xffffffffu, mt1, 1));
        mt1 = fmaxf(mt1, __shfl_xor_sync(0xffffffffu, mt1, 2));
        float mn0 = fmaxf(m0, mt0), mn1 = fmaxf(m1, mt1);
        float f0 = __expf(m0 - mn0), f1 = __expf(m1 - mn1);
        l0 *= f0; l1 *= f1;
#pragma unroll
        for (int tt = 0; tt < 8; ++tt) {
            o[tt][0] *= f0; o[tt][1] *= f0;
            o[tt][2] *= f1; o[tt][3] *= f1;
        }
        m0 = mn0; m1 = mn1;

        // p = exp(s-m); l += raw p; apply em (mem keys) after l; split-store to Ps
        const int pr0 = (W * 16 + g) * PSTRIDE, pr1 = pr0 + 8 * PSTRIDE;
#pragma unroll
        for (int tt = 0; tt < 4; ++tt) {
            float p0 = __expf(s[tt][0] - m0);
            float p1 = __expf(s[tt][1] - m0);
            float p2 = __expf(s[tt][2] - m1);
            float p3 = __expf(s[tt][3] - m1);
            l0 += p0 + p1; l1 += p2 + p3;
            if (isMem) {
                float e0 = em_s[j0 + tt * 8 + 2 * qq];
                float e1 = em_s[j0 + tt * 8 + 2 * qq + 1];
                p0 *= e0; p1 *= e1; p2 *= e0; p3 *= e1;
            }
            int c0 = tt * 8 + 2 * qq;
            float hh, ll;
            split1(p0, hh, ll); Ph[pr0 + c0] = hh;     Pl[pr0 + c0] = ll;
            split1(p1, hh, ll); Ph[pr0 + c0 + 1] = hh; Pl[pr0 + c0 + 1] = ll;
            split1(p2, hh, ll); Ph[pr1 + c0] = hh;     Pl[pr1 + c0] = ll;
            split1(p3, hh, ll); Ph[pr1 + c0 + 1] = hh; Pl[pr1 + c0 + 1] = ll;
        }
        __syncwarp();

        // ---- O += P V (3-split) ----
#pragma unroll
        for (int ks = 0; ks < 4; ++ks) {
            float ah[4], al[4];
            int pa0 = (W * 16 + g) * PSTRIDE + ks * 8 + qq;
            int pa1 = (W * 16 + g + 8) * PSTRIDE + ks * 8 + qq;
            ah[0] = Ph[pa0];     ah[1] = Ph[pa1];
            ah[2] = Ph[pa0 + 4]; ah[3] = Ph[pa1 + 4];
            al[0] = Pl[pa0];     al[1] = Pl[pa1];
            al[2] = Pl[pa0 + 4]; al[3] = Pl[pa1 + 4];
#pragma unroll
            for (int tt = 0; tt < 8; ++tt) {
                float r0 = Vc[(ks * 8 + qq) * KVSTRIDE + tt * 8 + g];
                float r1 = Vc[(ks * 8 + qq + 4) * KVSTRIDE + tt * 8 + g];
                float bh[2], bl[2];
                split1(r0, bh[0], bl[0]);
                split1(r1, bh[1], bl[1]);
                mma_tf32(o[tt], ah, bh);
                mma_tf32(o[tt], ah, bl);
                mma_tf32(o[tt], al, bh);
            }
        }
        __syncwarp();
        __syncthreads();
    }

    // final: reduce l across quad, normalize, write
    l0 += __shfl_xor_sync(0xffffffffu, l0, 1);
    l0 += __shfl_xor_sync(0xffffffffu, l0, 2);
    l1 += __shfl_xor_sync(0xffffffffu, l1, 1);
    l1 += __shfl_xor_sync(0xffffffffu, l1, 2);
    float inv0 = 1.f / l0, inv1 = 1.f / l1;

    float* ob0 = O + ((size_t)(b * N_) + I0 + W * 16 + g) * DIM_ + h * DH_;
    float* ob1 = ob0 + 8 * DIM_;
#pragma unroll
    for (int tt = 0; tt < 8; ++tt) {
        int c0 = tt * 8 + 2 * qq;
        *(float2*)(ob0 + c0) = make_float2(o[tt][0] * inv0, o[tt][1] * inv0);
        *(float2*)(ob1 + c0) = make_float2(o[tt][2] * inv1, o[tt][3] * inv1);
    }
}

// ---------------- launcher ----------------
extern "C" void kernel_launch(void* const* d_in, const int* in_sizes, int n_in,
                              void* d_out, int out_size)
{
    const float* x       = (const float*)d_in[0];
    const float* pos_emb = (const float*)d_in[1];
    const float* mem     = (const float*)d_in[2];
    const float* expire  = (const float*)d_in[3];
    const float* Wq      = (const float*)d_in[4];
    const float* bq      = (const float*)d_in[5];
    const float* Wkv     = (const float*)d_in[6];
    const float* bkv     = (const float*)d_in[7];
    const float* Wo      = (const float*)d_in[8];
    const float* bo      = (const float*)d_in[9];
    const float* Wp      = (const float*)d_in[10];
    const float* bp      = (const float*)d_in[11];
    float* out = (float*)d_out;

    float *Q, *KV, *Pos, *PDT, *O;
    cudaGetSymbolAddress((void**)&Q,   g_Q);
    cudaGetSymbolAddress((void**)&KV,  g_KV);
    cudaGetSymbolAddress((void**)&Pos, g_pos);
    cudaGetSymbolAddress((void**)&PDT, g_PDT);
    cudaGetSymbolAddress((void**)&O,   g_O);

    cudaFuncSetAttribute(attn_kernel, cudaFuncAttributeMaxDynamicSharedMemorySize, SMEM_ATTN);

    // 1) Q = x @ Wq + bq          (fold batch: M=4096, N=1024)
    gemm_tf32<<<dim3(DIM_ / 128, (B_ * N_) / 128, 1), 256>>>(
        x, B_ * N_, 0, x, 0, Wq, bq, Q, 0, DIM_, DIM_);

    // 2) KV = concat(mem, x) @ Wkv + bkv    (per batch: M=3072, N=2048)
    gemm_tf32<<<dim3(2 * DIM_ / 128, CTX_ / 128, B_), 256>>>(
        mem, MEM_, (size_t)MEM_ * DIM_, x, (size_t)N_ * DIM_,
        Wkv, bkv, KV, (size_t)CTX_ * 2 * DIM_, 2 * DIM_, DIM_);

    // 3) pos' = pos_emb @ Wp + bp           [2048,64]
    gemm_bias<<<dim3(1, N_ / 64, 1), 256>>>(pos_emb, Wp, bp, Pos, N_, DH_, DIM_);

    // 4) PDT (shifted, transposed, pre-scaled pos dots)
    pdt_kernel<<<dim3(N_ / 64, N_ / 256, B_ * H_), 256>>>(Q, Pos, PDT);

    // 5) tensor-core flash attention -> O
    attn_kernel<<<dim3(N_ / 64, H_, B_), 128, SMEM_ATTN>>>(Q, KV, PDT, expire, O);

    // 6) out = O @ Wo + bo        (fold batch: M=4096, N=1024)
    gemm_tf32<<<dim3(DIM_ / 128, (B_ * N_) / 128, 1), 256>>>(
        O, B_ * N_, 0, O, 0, Wo, bo, out, 0, DIM_, DIM_);
}

// round 8
// speedup vs baseline: 4.0829x; 1.5681x over previous
#include <cuda_runtime.h>
#include <cuda_bf16.h>
#include <cstdint>
#include <cstddef>

#define B_    2
#define N_    2048
#define DIM_  1024
#define H_    16
#define DH_   64
#define MEM_  1024
#define CTX_  3072
#define SCALE_ 0.125f

// ---------------- scratch (static device globals; no allocation) ----------------
__device__ float g_Q  [B_ * N_ * DIM_];          // 16 MB
__device__ float g_KV [B_ * CTX_ * 2 * DIM_];    // 48 MB
__device__ float g_pos[N_ * DH_];                // 512 KB
__device__ float g_PDT[134217728];               // 512 MB  PDT[b,h][j2][i]
__device__ float g_O  [B_ * N_ * DIM_];          // 16 MB

// =====================================================================
// bf16x3 helpers: v = hi + lo (bf16 each); D = aH*bH + aH*bL + aL*bH
// packed bf16x2: low half = first arg x, high half = second arg y
// =====================================================================
__device__ __forceinline__ void bsplit2(float x, float y, unsigned& h, unsigned& l)
{
    asm("cvt.rn.bf16x2.f32 %0, %1, %2;" : "=r"(h) : "f"(y), "f"(x));
    float xr = x - __uint_as_float(h << 16);
    float yr = y - __uint_as_float(h & 0xFFFF0000u);
    asm("cvt.rn.bf16x2.f32 %0, %1, %2;" : "=r"(l) : "f"(yr), "f"(xr));
}

__device__ __forceinline__ void mma_bf16(float* c, const unsigned* a, const unsigned* b)
{
    asm volatile(
        "mma.sync.aligned.m16n8k16.row.col.f32.bf16.bf16.f32 "
        "{%0,%1,%2,%3}, {%4,%5,%6,%7}, {%8,%9}, {%0,%1,%2,%3};\n"
        : "+f"(c[0]), "+f"(c[1]), "+f"(c[2]), "+f"(c[3])
        : "r"(a[0]), "r"(a[1]), "r"(a[2]), "r"(a[3]), "r"(b[0]), "r"(b[1]));
}

__device__ __forceinline__ void cp_async16(void* s, const void* g)
{
    unsigned a = (unsigned)__cvta_generic_to_shared(s);
    asm volatile("cp.async.cg.shared.global [%0], [%1], 16;" :: "r"(a), "l"(g));
}

// =====================================================================
// Split-bf16 tensor-core GEMM:  C = A @ B + bias   (bf16x3, m16n8k16)
// Block 128x128, BK=16, 256 threads, 8 warps (4m x 2n), warp tile 32x64.
// =====================================================================
__global__ __launch_bounds__(256) void gemm_bf16(
    const float* __restrict__ Alo, int MLo, size_t sAlo,
    const float* __restrict__ Ahi, size_t sAhi,
    const float* __restrict__ Bm, const float* __restrict__ bias,
    float* __restrict__ C, size_t sC,
    int N, int K)
{
    // packed bf16x2 tiles: A pairs along k (8 pairs per row), B pairs along k
    __shared__ __align__(16) unsigned AsH[128][12];
    __shared__ __align__(16) unsigned AsL[128][12];
    __shared__ __align__(16) unsigned BsH[8][136];
    __shared__ __align__(16) unsigned BsL[8][136];

    const int batch   = blockIdx.z;
    const int rowBase = blockIdx.y * 128;
    const int colBase = blockIdx.x * 128;
    const int tid  = threadIdx.x;
    const int wid  = tid >> 5, lane = tid & 31;
    const int wm   = wid & 3,  wn   = wid >> 2;
    const int g    = lane >> 2, qq  = lane & 3;

    // A loader: row = tid>>2 (+64), 4 consecutive k at (tid&3)*4
    const int ar = tid >> 2;
    const int ac = (tid & 3) * 4;
    const float* aptr[2];
#pragma unroll
    for (int i = 0; i < 2; ++i) {
        int r = rowBase + ar + 64 * i;
        aptr[i] = ((r < MLo) ? (Alo + (size_t)batch * sAlo + (size_t)r * K)
                             : (Ahi + (size_t)batch * sAhi + (size_t)(r - MLo) * K)) + ac;
    }
    // B loader: k-pair kp = tid>>5 (0..7), cols n0..n0+3
    const int kp = tid >> 5;
    const int n0 = (tid & 31) * 4;
    const float* bptr0 = Bm + (size_t)(2 * kp) * N + colBase + n0;
    const float* bptr1 = bptr0 + N;

    float4 ga[2], gb0, gb1;
#pragma unroll
    for (int i = 0; i < 2; ++i) ga[i] = *(const float4*)(aptr[i]);
    gb0 = *(const float4*)(bptr0);
    gb1 = *(const float4*)(bptr1);

    float acc[2][8][4];
#pragma unroll
    for (int a = 0; a < 2; ++a)
#pragma unroll
        for (int b = 0; b < 8; ++b)
#pragma unroll
            for (int c = 0; c < 4; ++c) acc[a][b][c] = 0.f;

    for (int k0 = 0; k0 < K; k0 += 16) {
        // stage: A pairs along k; B pairs across the two k-rows
#pragma unroll
        for (int i = 0; i < 2; ++i) {
            unsigned h0, l0, h1, l1;
            bsplit2(ga[i].x, ga[i].y, h0, l0);
            bsplit2(ga[i].z, ga[i].w, h1, l1);
            int r = ar + 64 * i, cpr = ac >> 1;
            AsH[r][cpr] = h0; AsH[r][cpr + 1] = h1;
            AsL[r][cpr] = l0; AsL[r][cpr + 1] = l1;
        }
        {
            uint4 bh, bl;
            bsplit2(gb0.x, gb1.x, bh.x, bl.x);
            bsplit2(gb0.y, gb1.y, bh.y, bl.y);
            bsplit2(gb0.z, gb1.z, bh.z, bl.z);
            bsplit2(gb0.w, gb1.w, bh.w, bl.w);
            *(uint4*)&BsH[kp][n0] = bh;
            *(uint4*)&BsL[kp][n0] = bl;
        }
        __syncthreads();

        if (k0 + 16 < K) {
#pragma unroll
            for (int i = 0; i < 2; ++i) ga[i] = *(const float4*)(aptr[i] + k0 + 16);
            gb0 = *(const float4*)(bptr0 + (size_t)(k0 + 16) * N);
            gb1 = *(const float4*)(bptr1 + (size_t)(k0 + 16) * N);
        }

        unsigned bH[8][2], bL[8][2];
#pragma unroll
        for (int tn = 0; tn < 8; ++tn) {
            int col = wn * 64 + tn * 8 + g;
            bH[tn][0] = BsH[qq][col]; bH[tn][1] = BsH[qq + 4][col];
            bL[tn][0] = BsL[qq][col]; bL[tn][1] = BsL[qq + 4][col];
        }
#pragma unroll
        for (int tm = 0; tm < 2; ++tm) {
            int r0 = wm * 32 + tm * 16 + g;
            unsigned aHf[4], aLf[4];
            aHf[0] = AsH[r0][qq];     aHf[1] = AsH[r0 + 8][qq];
            aHf[2] = AsH[r0][qq + 4]; aHf[3] = AsH[r0 + 8][qq + 4];
            aLf[0] = AsL[r0][qq];     aLf[1] = AsL[r0 + 8][qq];
            aLf[2] = AsL[r0][qq + 4]; aLf[3] = AsL[r0 + 8][qq + 4];
#pragma unroll
            for (int tn = 0; tn < 8; ++tn) {
                mma_bf16(acc[tm][tn], aHf, bH[tn]);
                mma_bf16(acc[tm][tn], aHf, bL[tn]);
                mma_bf16(acc[tm][tn], aLf, bH[tn]);
            }
        }
        __syncthreads();
    }

    float* Cb = C + (size_t)batch * sC;
#pragma unroll
    for (int tm = 0; tm < 2; ++tm) {
#pragma unroll
        for (int tn = 0; tn < 8; ++tn) {
            int row = rowBase + wm * 32 + tm * 16 + g;
            int col = colBase + wn * 64 + tn * 8 + 2 * qq;
            float b0 = bias[col], b1 = bias[col + 1];
            float2 v0 = make_float2(acc[tm][tn][0] + b0, acc[tm][tn][1] + b1);
            float2 v1 = make_float2(acc[tm][tn][2] + b0, acc[tm][tn][3] + b1);
            *(float2*)(Cb + (size_t)row * N + col) = v0;
            *(float2*)(Cb + (size_t)(row + 8) * N + col) = v1;
        }
    }
}

// ---------------- small scalar GEMM with bias (pos': N=64) ----------------
__global__ __launch_bounds__(256) void gemm_bias(
    const float* __restrict__ A, const float* __restrict__ Bm, const float* __restrict__ bias,
    float* __restrict__ C, int M, int N, int K)
{
    __shared__ float As[16][65];
    __shared__ float Bs[16][64];

    const int rowBase = blockIdx.y * 64;
    const int colBase = blockIdx.x * 64;
    const int tid = threadIdx.x;
    const int tx = tid & 15, ty = tid >> 4;

    const int arow = tid >> 2;
    const int ac   = (tid & 3) * 4;
    const int brow = tid >> 4;
    const int bc   = (tid & 15) * 4;

    const float* Aptr = A + (size_t)(rowBase + arow) * K;
    float acc[4][4] = {};

    for (int k0 = 0; k0 < K; k0 += 16) {
        float4 av = *(const float4*)(Aptr + k0 + ac);
        float4 bv = *(const float4*)(Bm + (size_t)(k0 + brow) * N + colBase + bc);
        __syncthreads();
        As[ac + 0][arow] = av.x; As[ac + 1][arow] = av.y;
        As[ac + 2][arow] = av.z; As[ac + 3][arow] = av.w;
        *(float4*)&Bs[brow][bc] = bv;
        __syncthreads();
#pragma unroll
        for (int kk = 0; kk < 16; ++kk) {
            float a0 = As[kk][ty * 4 + 0], a1 = As[kk][ty * 4 + 1];
            float a2 = As[kk][ty * 4 + 2], a3 = As[kk][ty * 4 + 3];
            float4 b4 = *(const float4*)&Bs[kk][tx * 4];
            acc[0][0] += a0 * b4.x; acc[0][1] += a0 * b4.y; acc[0][2] += a0 * b4.z; acc[0][3] += a0 * b4.w;
            acc[1][0] += a1 * b4.x; acc[1][1] += a1 * b4.y; acc[1][2] += a1 * b4.z; acc[1][3] += a1 * b4.w;
            acc[2][0] += a2 * b4.x; acc[2][1] += a2 * b4.y; acc[2][2] += a2 * b4.z; acc[2][3] += a2 * b4.w;
            acc[3][0] += a3 * b4.x; acc[3][1] += a3 * b4.y; acc[3][2] += a3 * b4.z; acc[3][3] += a3 * b4.w;
        }
    }

    float4 bvv = *(const float4*)(bias + colBase + tx * 4);
#pragma unroll
    for (int a = 0; a < 4; ++a) {
        int row = rowBase + ty * 4 + a;
        float4 o;
        o.x = acc[a][0] + bvv.x; o.y = acc[a][1] + bvv.y;
        o.z = acc[a][2] + bvv.z; o.w = acc[a][3] + bvv.w;
        *(float4*)(C + (size_t)row * N + colBase + tx * 4) = o;
    }
}

// ---------------- skewed pos-dots kernel (unchanged from R6) ----------------
__global__ __launch_bounds__(256) void pdt_kernel(
    const float* __restrict__ Q, const float* __restrict__ Pos, float* __restrict__ PDT)
{
    const int bh = blockIdx.z;
    const int b  = bh >> 4, h = bh & 15;
    const int I  = blockIdx.x * 64;
    const int J  = blockIdx.y * 256;
    if (J > I + 63) return;

    __shared__ float Qs[64][17];
    __shared__ float Ps[319][17];

    const int tid = threadIdx.x;
    const int pbase = J - I + 1984;

    const int tx = tid & 15, ty = tid >> 4;
    const int s0 = 16 * ty - 4 * tx + 63;
    float acc[16][4];
#pragma unroll
    for (int a = 0; a < 16; ++a)
#pragma unroll
        for (int c = 0; c < 4; ++c) acc[a][c] = 0.f;

    const int lrow = tid >> 2;
    const int lc4  = (tid & 3) * 4;

#pragma unroll
    for (int dp = 0; dp < 4; ++dp) {
        const int dbase = dp * 16;
        {
            const float* src = Q + ((size_t)(b * N_ + I + lrow)) * DIM_ + h * DH_ + dbase + lc4;
            float4 v = *(const float4*)src;
            Qs[lrow][lc4 + 0] = v.x; Qs[lrow][lc4 + 1] = v.y;
            Qs[lrow][lc4 + 2] = v.z; Qs[lrow][lc4 + 3] = v.w;
        }
        for (int s = lrow; s < 319; s += 64) {
            int pidx = pbase + s;
            bool ok = (pidx >= 0) && (pidx < N_);
            const float* src = Pos + (size_t)(ok ? pidx : 0) * DH_ + dbase + lc4;
            float4 v = ok ? *(const float4*)src : make_float4(0.f, 0.f, 0.f, 0.f);
            Ps[s][lc4 + 0] = v.x; Ps[s][lc4 + 1] = v.y;
            Ps[s][lc4 + 2] = v.z; Ps[s][lc4 + 3] = v.w;
        }
        __syncthreads();

#pragma unroll 4
        for (int d = 0; d < 16; ++d) {
            float qv[4], pv[19];
#pragma unroll
            for (int c = 0; c < 4; ++c) qv[c] = Qs[4 * tx + c][d];
#pragma unroll
            for (int t = 0; t < 19; ++t) pv[t] = Ps[s0 - 3 + t][d];
#pragma unroll
            for (int a = 0; a < 16; ++a)
#pragma unroll
                for (int c = 0; c < 4; ++c)
                    acc[a][c] += pv[a - c + 3] * qv[c];
        }
        __syncthreads();
    }

    float* base = PDT + ((size_t)bh << 22);
#pragma unroll
    for (int a = 0; a < 16; ++a) {
        int j2 = J + 16 * ty + a;
        float4 o;
        o.x = SCALE_ * acc[a][0]; o.y = SCALE_ * acc[a][1];
        o.z = SCALE_ * acc[a][2]; o.w = SCALE_ * acc[a][3];
        *(float4*)(base + (size_t)j2 * N_ + I + 4 * tx) = o;
    }
}

// =====================================================================
// Tensor-core flash attention (bf16x3, m16n8k16, P in registers)
// 64 q-rows/block, 4 warps, 3 CTAs/SM (64KB smem)
// =====================================================================
#define KST 72
#define VST 84
#define SMEM_ATTN ((2 * 32 * KST + 2 * 32 * VST + 2 * 32 * VST + 1024) * 4)

__global__ __launch_bounds__(128, 3) void attn_kernel(
    const float* __restrict__ Q, const float* __restrict__ KV,
    const float* __restrict__ PDT, const float* __restrict__ expire,
    float* __restrict__ O)
{
    extern __shared__ float smf[];
    float* Kb   = smf;                       // [2][32][72]
    float* Vb   = Kb + 2 * 32 * KST;         // [2][32][84]
    float* Pdm  = Vb + 2 * 32 * VST;         // [2][32][84]
    float* em_s = Pdm + 2 * 32 * VST;        // [1024]

    const int b = blockIdx.z, h = blockIdx.y;
    const int tid = threadIdx.x;
    const int I0 = blockIdx.x * 64;
    const int W = tid >> 5, lane = tid & 31;
    const int g = lane >> 2, qq = lane & 3;

    // stage expire mask
    {
        const float* emp = expire + b * MEM_;
        *(float4*)&em_s[tid * 8]     = *(const float4*)(emp + tid * 8);
        *(float4*)&em_s[tid * 8 + 4] = *(const float4*)(emp + tid * 8 + 4);
    }

    // Q fragments (x SCALE_, bf16 split, packed pairs) in registers
    unsigned aH[4][4], aL[4][4];
    {
        const float* q0 = Q + ((size_t)(b * N_) + I0 + W * 16 + g) * DIM_ + h * DH_;
        const float* q8 = q0 + 8 * DIM_;
#pragma unroll
        for (int ks = 0; ks < 4; ++ks) {
            float2 xa = *(const float2*)(q0 + ks * 16 + 2 * qq);
            float2 xb = *(const float2*)(q0 + ks * 16 + 2 * qq + 8);
            float2 ya = *(const float2*)(q8 + ks * 16 + 2 * qq);
            float2 yb = *(const float2*)(q8 + ks * 16 + 2 * qq + 8);
            bsplit2(xa.x * SCALE_, xa.y * SCALE_, aH[ks][0], aL[ks][0]);
            bsplit2(ya.x * SCALE_, ya.y * SCALE_, aH[ks][1], aL[ks][1]);
            bsplit2(xb.x * SCALE_, xb.y * SCALE_, aH[ks][2], aL[ks][2]);
            bsplit2(yb.x * SCALE_, yb.y * SCALE_, aH[ks][3], aL[ks][3]);
        }
    }

    float o[8][4];
#pragma unroll
    for (int t = 0; t < 8; ++t)
#pragma unroll
        for (int c = 0; c < 4; ++c) o[t][c] = 0.f;
    float m0 = -1e30f, m1 = -1e30f, l0 = 0.f, l1 = 0.f;

    const float* kvbase = KV + (size_t)b * CTX_ * (2 * DIM_) + h * DH_;
    const float* pdtb   = PDT + (((size_t)(b * H_ + h)) << 22);
    const int ntiles = (MEM_ + I0 + 64) / 32;

    // prefetch tile 0 (mem tile: K/V only)
#pragma unroll
    for (int u = 0; u < 4; ++u) {
        int e = u * 128 + tid, row = e >> 4, c = e & 15;
        const float* src = kvbase + (size_t)row * (2 * DIM_) + c * 4;
        cp_async16(Kb + row * KST + c * 4, src);
        cp_async16(Vb + row * VST + c * 4, src + DIM_);
    }
    asm volatile("cp.async.commit_group;");

    for (int t = 0; t < ntiles; ++t) {
        const int st = t & 1;
        const int j0 = t * 32;
        if (t + 1 < ntiles) {
            const int jn = j0 + 32;
            float* Kd = Kb + (st ^ 1) * 32 * KST;
            float* Vd = Vb + (st ^ 1) * 32 * VST;
#pragma unroll
            for (int u = 0; u < 4; ++u) {
                int e = u * 128 + tid, row = e >> 4, c = e & 15;
                const float* src = kvbase + (size_t)(jn + row) * (2 * DIM_) + c * 4;
                cp_async16(Kd + row * KST + c * 4, src);
                cp_async16(Vd + row * VST + c * 4, src + DIM_);
            }
            if (jn >= MEM_) {
                float* Pdd = Pdm + (st ^ 1) * 32 * VST;
#pragma unroll
                for (int u = 0; u < 4; ++u) {
                    int e = u * 128 + tid, row = e >> 4, c = e & 15;
                    cp_async16(Pdd + row * VST + c * 4,
                               pdtb + (size_t)(jn - MEM_ + row) * N_ + I0 + c * 4);
                }
            }
        }
        asm volatile("cp.async.commit_group;");
        asm volatile("cp.async.wait_group 1;");
        __syncthreads();

        const float* Kc = Kb + st * 32 * KST;
        const float* Vc = Vb + st * 32 * VST;
        const float* Pc = Pdm + st * 32 * VST;

        // ---- S = Q K^T (bf16x3, m16n8k16) ----
        float s[4][4];
#pragma unroll
        for (int tt = 0; tt < 4; ++tt)
#pragma unroll
            for (int c = 0; c < 4; ++c) s[tt][c] = 0.f;

#pragma unroll
        for (int ks = 0; ks < 4; ++ks) {
#pragma unroll
            for (int tt = 0; tt < 4; ++tt) {
                const float* kr = Kc + (tt * 8 + g) * KST + ks * 16 + 2 * qq;
                float2 k0 = *(const float2*)kr;
                float2 k1 = *(const float2*)(kr + 8);
                unsigned bh[2], bl[2];
                bsplit2(k0.x, k0.y, bh[0], bl[0]);
                bsplit2(k1.x, k1.y, bh[1], bl[1]);
                mma_bf16(s[tt], aH[ks], bh);
                mma_bf16(s[tt], aH[ks], bl);
                mma_bf16(s[tt], aL[ks], bh);
            }
        }

        const bool isMem = (j0 < MEM_);
        if (!isMem) {
            const int il0 = W * 16 + g, il1 = il0 + 8;
#pragma unroll
            for (int tt = 0; tt < 4; ++tt) {
                int c0 = tt * 8 + 2 * qq;
                s[tt][0] += Pc[c0 * VST + il0];
                s[tt][1] += Pc[(c0 + 1) * VST + il0];
                s[tt][2] += Pc[c0 * VST + il1];
                s[tt][3] += Pc[(c0 + 1) * VST + il1];
            }
            if (j0 - MEM_ + 31 > I0) {
                const int jb = j0 - MEM_;
                const int r0 = I0 + W * 16 + g, r1 = r0 + 8;
#pragma unroll
                for (int tt = 0; tt < 4; ++tt) {
                    int c0 = jb + tt * 8 + 2 * qq;
                    if (c0     > r0) s[tt][0] = -1e30f;
                    if (c0 + 1 > r0) s[tt][1] = -1e30f;
                    if (c0     > r1) s[tt][2] = -1e30f;
                    if (c0 + 1 > r1) s[tt][3] = -1e30f;
                }
            }
        }

        // ---- online softmax (rows g / g+8) ----
        float mt0 = fmaxf(fmaxf(s[0][0], s[0][1]), fmaxf(s[1][0], s[1][1]));
        mt0 = fmaxf(mt0, fmaxf(fmaxf(s[2][0], s[2][1]), fmaxf(s[3][0], s[3][1])));
        float mt1 = fmaxf(fmaxf(s[0][2], s[0][3]), fmaxf(s[1][2], s[1][3]));
        mt1 = fmaxf(mt1, fmaxf(fmaxf(s[2][2], s[2][3]), fmaxf(s[3][2], s[3][3])));
        mt0 = fmaxf(mt0, __shfl_xor_sync(0xffffffffu, mt0, 1));
        mt0 = fmaxf(mt0, __shfl_xor_sync(0xffffffffu, mt0, 2));
        mt1 = fmaxf(mt1, __shfl_xor_sync(0xffffffffu, mt1, 1));
        mt1 = fmaxf(mt1, __shfl_xor_sync(0xffffffffu, mt1, 2));
        float mn0 = fmaxf(m0, mt0), mn1 = fmaxf(m1, mt1);
        float f0 = __expf(m0 - mn0), f1 = __expf(m1 - mn1);
        l0 *= f0; l1 *= f1;
#pragma unroll
        for (int tt = 0; tt < 8; ++tt) {
            o[tt][0] *= f0; o[tt][1] *= f0;
            o[tt][2] *= f1; o[tt][3] *= f1;
        }
        m0 = mn0; m1 = mn1;

        // p = exp(s-m); l += raw p; em (mem keys) after l; pack bf16 splits to regs
        unsigned pAh[4], pAl[4], pBh[4], pBl[4];
#pragma unroll
        for (int tt = 0; tt < 4; ++tt) {
            float p0 = __expf(s[tt][0] - m0);
            float p1 = __expf(s[tt][1] - m0);
            float p2 = __expf(s[tt][2] - m1);
            float p3 = __expf(s[tt][3] - m1);
            l0 += p0 + p1; l1 += p2 + p3;
            if (isMem) {
                float e0 = em_s[j0 + tt * 8 + 2 * qq];
                float e1 = em_s[j0 + tt * 8 + 2 * qq + 1];
                p0 *= e0; p1 *= e1; p2 *= e0; p3 *= e1;
            }
            bsplit2(p0, p1, pAh[tt], pAl[tt]);
            bsplit2(p2, p3, pBh[tt], pBl[tt]);
        }

        // ---- O += P V (bf16x3; A fragment straight from registers) ----
#pragma unroll
        for (int ks = 0; ks < 2; ++ks) {
            unsigned ah[4] = { pAh[2 * ks], pBh[2 * ks], pAh[2 * ks + 1], pBh[2 * ks + 1] };
            unsigned al[4] = { pAl[2 * ks], pBl[2 * ks], pAl[2 * ks + 1], pBl[2 * ks + 1] };
#pragma unroll
            for (int tt = 0; tt < 8; ++tt) {
                int col = tt * 8 + g;
                float v00 = Vc[(ks * 16 + 2 * qq) * VST + col];
                float v01 = Vc[(ks * 16 + 2 * qq + 1) * VST + col];
                float v10 = Vc[(ks * 16 + 2 * qq + 8) * VST + col];
                float v11 = Vc[(ks * 16 + 2 * qq + 9) * VST + col];
                unsigned bh[2], bl[2];
                bsplit2(v00, v01, bh[0], bl[0]);
                bsplit2(v10, v11, bh[1], bl[1]);
                mma_bf16(o[tt], ah, bh);
                mma_bf16(o[tt], ah, bl);
                mma_bf16(o[tt], al, bh);
            }
        }
        __syncthreads();
    }

    // final: reduce l across quad, normalize, write
    l0 += __shfl_xor_sync(0xffffffffu, l0, 1);
    l0 += __shfl_xor_sync(0xffffffffu, l0, 2);
    l1 += __shfl_xor_sync(0xffffffffu, l1, 1);
    l1 += __shfl_xor_sync(0xffffffffu, l1, 2);
    float inv0 = 1.f / l0, inv1 = 1.f / l1;

    float* ob0 = O + ((size_t)(b * N_) + I0 + W * 16 + g) * DIM_ + h * DH_;
    float* ob1 = ob0 + 8 * DIM_;
#pragma unroll
    for (int tt = 0; tt < 8; ++tt) {
        int c0 = tt * 8 + 2 * qq;
        *(float2*)(ob0 + c0) = make_float2(o[tt][0] * inv0, o[tt][1] * inv0);
        *(float2*)(ob1 + c0) = make_float2(o[tt][2] * inv1, o[tt][3] * inv1);
    }
}

// ---------------- launcher ----------------
extern "C" void kernel_launch(void* const* d_in, const int* in_sizes, int n_in,
                              void* d_out, int out_size)
{
    const float* x       = (const float*)d_in[0];
    const float* pos_emb = (const float*)d_in[1];
    const float* mem     = (const float*)d_in[2];
    const float* expire  = (const float*)d_in[3];
    const float* Wq      = (const float*)d_in[4];
    const float* bq      = (const float*)d_in[5];
    const float* Wkv     = (const float*)d_in[6];
    const float* bkv     = (const float*)d_in[7];
    const float* Wo      = (const float*)d_in[8];
    const float* bo      = (const float*)d_in[9];
    const float* Wp      = (const float*)d_in[10];
    const float* bp      = (const float*)d_in[11];
    float* out = (float*)d_out;

    float *Q, *KV, *Pos, *PDT, *O;
    cudaGetSymbolAddress((void**)&Q,   g_Q);
    cudaGetSymbolAddress((void**)&KV,  g_KV);
    cudaGetSymbolAddress((void**)&Pos, g_pos);
    cudaGetSymbolAddress((void**)&PDT, g_PDT);
    cudaGetSymbolAddress((void**)&O,   g_O);

    cudaFuncSetAttribute(attn_kernel, cudaFuncAttributeMaxDynamicSharedMemorySize, SMEM_ATTN);

    // 1) Q = x @ Wq + bq          (fold batch: M=4096, N=1024)
    gemm_bf16<<<dim3(DIM_ / 128, (B_ * N_) / 128, 1), 256>>>(
        x, B_ * N_, 0, x, 0, Wq, bq, Q, 0, DIM_, DIM_);

    // 2) KV = concat(mem, x) @ Wkv + bkv    (per batch: M=3072, N=2048)
    gemm_bf16<<<dim3(2 * DIM_ / 128, CTX_ / 128, B_), 256>>>(
        mem, MEM_, (size_t)MEM_ * DIM_, x, (size_t)N_ * DIM_,
        Wkv, bkv, KV, (size_t)CTX_ * 2 * DIM_, 2 * DIM_, DIM_);

    // 3) pos' = pos_emb @ Wp + bp           [2048,64]
    gemm_bias<<<dim3(1, N_ / 64, 1), 256>>>(pos_emb, Wp, bp, Pos, N_, DH_, DIM_);

    // 4) PDT (shifted, transposed, pre-scaled pos dots)
    pdt_kernel<<<dim3(N_ / 64, N_ / 256, B_ * H_), 256>>>(Q, Pos, PDT);

    // 5) tensor-core flash attention -> O
    attn_kernel<<<dim3(N_ / 64, H_, B_), 128, SMEM_ATTN>>>(Q, KV, PDT, expire, O);

    // 6) out = O @ Wo + bo        (fold batch: M=4096, N=1024)
    gemm_bf16<<<dim3(DIM_ / 128, (B_ * N_) / 128, 1), 256>>>(
        O, B_ * N_, 0, O, 0, Wo, bo, out, 0, DIM_, DIM_);
}

// round 9
// speedup vs baseline: 5.5824x; 1.3672x over previous
#include <cuda_runtime.h>
#include <cuda_bf16.h>
#include <cstdint>
#include <cstddef>

#define B_    2
#define N_    2048
#define DIM_  1024
#define H_    16
#define DH_   64
#define MEM_  1024
#define CTX_  3072
#define SCALE_ 0.125f

// ---------------- scratch (static device globals; no allocation) ----------------
__device__ float g_Q  [B_ * N_ * DIM_];          // 16 MB
__device__ float g_KV [B_ * CTX_ * 2 * DIM_];    // 48 MB
__device__ float g_pos[N_ * DH_];                // 512 KB
__device__ float g_RD [134217728];               // 512 MB  RD[b,h][i][p] = SCALE*q_i.pos'_p
__device__ float g_O  [B_ * N_ * DIM_];          // 16 MB

// =====================================================================
// bf16x3 helpers: v = hi + lo (bf16 each); D = aH*bH + aH*bL + aL*bH
// =====================================================================
__device__ __forceinline__ void bsplit2(float x, float y, unsigned& h, unsigned& l)
{
    asm("cvt.rn.bf16x2.f32 %0, %1, %2;" : "=r"(h) : "f"(y), "f"(x));
    float xr = x - __uint_as_float(h << 16);
    float yr = y - __uint_as_float(h & 0xFFFF0000u);
    asm("cvt.rn.bf16x2.f32 %0, %1, %2;" : "=r"(l) : "f"(yr), "f"(xr));
}

__device__ __forceinline__ void mma_bf16(float* c, const unsigned* a, const unsigned* b)
{
    asm volatile(
        "mma.sync.aligned.m16n8k16.row.col.f32.bf16.bf16.f32 "
        "{%0,%1,%2,%3}, {%4,%5,%6,%7}, {%8,%9}, {%0,%1,%2,%3};\n"
        : "+f"(c[0]), "+f"(c[1]), "+f"(c[2]), "+f"(c[3])
        : "r"(a[0]), "r"(a[1]), "r"(a[2]), "r"(a[3]), "r"(b[0]), "r"(b[1]));
}

__device__ __forceinline__ void cp_async16(void* s, const void* g)
{
    unsigned a = (unsigned)__cvta_generic_to_shared(s);
    asm volatile("cp.async.cg.shared.global [%0], [%1], 16;" :: "r"(a), "l"(g));
}

// =====================================================================
// Split-bf16 tensor-core GEMM:  C = A @ B + bias   (bf16x3, m16n8k16)
// =====================================================================
__global__ __launch_bounds__(256) void gemm_bf16(
    const float* __restrict__ Alo, int MLo, size_t sAlo,
    const float* __restrict__ Ahi, size_t sAhi,
    const float* __restrict__ Bm, const float* __restrict__ bias,
    float* __restrict__ C, size_t sC,
    int N, int K)
{
    __shared__ __align__(16) unsigned AsH[128][12];
    __shared__ __align__(16) unsigned AsL[128][12];
    __shared__ __align__(16) unsigned BsH[8][136];
    __shared__ __align__(16) unsigned BsL[8][136];

    const int batch   = blockIdx.z;
    const int rowBase = blockIdx.y * 128;
    const int colBase = blockIdx.x * 128;
    const int tid  = threadIdx.x;
    const int wid  = tid >> 5, lane = tid & 31;
    const int wm   = wid & 3,  wn   = wid >> 2;
    const int g    = lane >> 2, qq  = lane & 3;

    const int ar = tid >> 2;
    const int ac = (tid & 3) * 4;
    const float* aptr[2];
#pragma unroll
    for (int i = 0; i < 2; ++i) {
        int r = rowBase + ar + 64 * i;
        aptr[i] = ((r < MLo) ? (Alo + (size_t)batch * sAlo + (size_t)r * K)
                             : (Ahi + (size_t)batch * sAhi + (size_t)(r - MLo) * K)) + ac;
    }
    const int kp = tid >> 5;
    const int n0 = (tid & 31) * 4;
    const float* bptr0 = Bm + (size_t)(2 * kp) * N + colBase + n0;
    const float* bptr1 = bptr0 + N;

    float4 ga[2], gb0, gb1;
#pragma unroll
    for (int i = 0; i < 2; ++i) ga[i] = *(const float4*)(aptr[i]);
    gb0 = *(const float4*)(bptr0);
    gb1 = *(const float4*)(bptr1);

    float acc[2][8][4];
#pragma unroll
    for (int a = 0; a < 2; ++a)
#pragma unroll
        for (int b = 0; b < 8; ++b)
#pragma unroll
            for (int c = 0; c < 4; ++c) acc[a][b][c] = 0.f;

    for (int k0 = 0; k0 < K; k0 += 16) {
#pragma unroll
        for (int i = 0; i < 2; ++i) {
            unsigned h0, l0, h1, l1;
            bsplit2(ga[i].x, ga[i].y, h0, l0);
            bsplit2(ga[i].z, ga[i].w, h1, l1);
            int r = ar + 64 * i, cpr = ac >> 1;
            AsH[r][cpr] = h0; AsH[r][cpr + 1] = h1;
            AsL[r][cpr] = l0; AsL[r][cpr + 1] = l1;
        }
        {
            uint4 bh, bl;
            bsplit2(gb0.x, gb1.x, bh.x, bl.x);
            bsplit2(gb0.y, gb1.y, bh.y, bl.y);
            bsplit2(gb0.z, gb1.z, bh.z, bl.z);
            bsplit2(gb0.w, gb1.w, bh.w, bl.w);
            *(uint4*)&BsH[kp][n0] = bh;
            *(uint4*)&BsL[kp][n0] = bl;
        }
        __syncthreads();

        if (k0 + 16 < K) {
#pragma unroll
            for (int i = 0; i < 2; ++i) ga[i] = *(const float4*)(aptr[i] + k0 + 16);
            gb0 = *(const float4*)(bptr0 + (size_t)(k0 + 16) * N);
            gb1 = *(const float4*)(bptr1 + (size_t)(k0 + 16) * N);
        }

        unsigned bH[8][2], bL[8][2];
#pragma unroll
        for (int tn = 0; tn < 8; ++tn) {
            int col = wn * 64 + tn * 8 + g;
            bH[tn][0] = BsH[qq][col]; bH[tn][1] = BsH[qq + 4][col];
            bL[tn][0] = BsL[qq][col]; bL[tn][1] = BsL[qq + 4][col];
        }
#pragma unroll
        for (int tm = 0; tm < 2; ++tm) {
            int r0 = wm * 32 + tm * 16 + g;
            unsigned aHf[4], aLf[4];
            aHf[0] = AsH[r0][qq];     aHf[1] = AsH[r0 + 8][qq];
            aHf[2] = AsH[r0][qq + 4]; aHf[3] = AsH[r0 + 8][qq + 4];
            aLf[0] = AsL[r0][qq];     aLf[1] = AsL[r0 + 8][qq];
            aLf[2] = AsL[r0][qq + 4]; aLf[3] = AsL[r0 + 8][qq + 4];
#pragma unroll
            for (int tn = 0; tn < 8; ++tn) {
                mma_bf16(acc[tm][tn], aHf, bH[tn]);
                mma_bf16(acc[tm][tn], aHf, bL[tn]);
                mma_bf16(acc[tm][tn], aLf, bH[tn]);
            }
        }
        __syncthreads();
    }

    float* Cb = C + (size_t)batch * sC;
#pragma unroll
    for (int tm = 0; tm < 2; ++tm) {
#pragma unroll
        for (int tn = 0; tn < 8; ++tn) {
            int row = rowBase + wm * 32 + tm * 16 + g;
            int col = colBase + wn * 64 + tn * 8 + 2 * qq;
            float b0 = bias[col], b1 = bias[col + 1];
            float2 v0 = make_float2(acc[tm][tn][0] + b0, acc[tm][tn][1] + b1);
            float2 v1 = make_float2(acc[tm][tn][2] + b0, acc[tm][tn][3] + b1);
            *(float2*)(Cb + (size_t)row * N + col) = v0;
            *(float2*)(Cb + (size_t)(row + 8) * N + col) = v1;
        }
    }
}

// ---------------- small scalar GEMM with bias (pos': N=64) ----------------
__global__ __launch_bounds__(256) void gemm_bias(
    const float* __restrict__ A, const float* __restrict__ Bm, const float* __restrict__ bias,
    float* __restrict__ C, int M, int N, int K)
{
    __shared__ float As[16][65];
    __shared__ float Bs[16][64];

    const int rowBase = blockIdx.y * 64;
    const int colBase = blockIdx.x * 64;
    const int tid = threadIdx.x;
    const int tx = tid & 15, ty = tid >> 4;

    const int arow = tid >> 2;
    const int ac   = (tid & 3) * 4;
    const int brow = tid >> 4;
    const int bc   = (tid & 15) * 4;

    const float* Aptr = A + (size_t)(rowBase + arow) * K;
    float acc[4][4] = {};

    for (int k0 = 0; k0 < K; k0 += 16) {
        float4 av = *(const float4*)(Aptr + k0 + ac);
        float4 bv = *(const float4*)(Bm + (size_t)(k0 + brow) * N + colBase + bc);
        __syncthreads();
        As[ac + 0][arow] = av.x; As[ac + 1][arow] = av.y;
        As[ac + 2][arow] = av.z; As[ac + 3][arow] = av.w;
        *(float4*)&Bs[brow][bc] = bv;
        __syncthreads();
#pragma unroll
        for (int kk = 0; kk < 16; ++kk) {
            float a0 = As[kk][ty * 4 + 0], a1 = As[kk][ty * 4 + 1];
            float a2 = As[kk][ty * 4 + 2], a3 = As[kk][ty * 4 + 3];
            float4 b4 = *(const float4*)&Bs[kk][tx * 4];
            acc[0][0] += a0 * b4.x; acc[0][1] += a0 * b4.y; acc[0][2] += a0 * b4.z; acc[0][3] += a0 * b4.w;
            acc[1][0] += a1 * b4.x; acc[1][1] += a1 * b4.y; acc[1][2] += a1 * b4.z; acc[1][3] += a1 * b4.w;
            acc[2][0] += a2 * b4.x; acc[2][1] += a2 * b4.y; acc[2][2] += a2 * b4.z; acc[2][3] += a2 * b4.w;
            acc[3][0] += a3 * b4.x; acc[3][1] += a3 * b4.y; acc[3][2] += a3 * b4.z; acc[3][3] += a3 * b4.w;
        }
    }

    float4 bvv = *(const float4*)(bias + colBase + tx * 4);
#pragma unroll
    for (int a = 0; a < 4; ++a) {
        int row = rowBase + ty * 4 + a;
        float4 o;
        o.x = acc[a][0] + bvv.x; o.y = acc[a][1] + bvv.y;
        o.z = acc[a][2] + bvv.z; o.w = acc[a][3] + bvv.w;
        *(float4*)(C + (size_t)row * N + colBase + tx * 4) = o;
    }
}

// =====================================================================
// rd_kernel: RD[b,h][i][p] = SCALE * q_i . pos'_p   (bf16x3 NT GEMM)
// Block 128(i) x 128(p), K=64 single pass. Only tiles with p_max+i_max>=2047.
// =====================================================================
__global__ __launch_bounds__(256) void rd_kernel(
    const float* __restrict__ Q, const float* __restrict__ Pos, float* __restrict__ RD)
{
    const int I0 = blockIdx.y * 128;
    const int P0 = blockIdx.x * 128;
    if (I0 + P0 + 254 < 2047) return;          // tile entirely below used band

    const int bh = blockIdx.z;
    const int b  = bh >> 4, h = bh & 15;

    __shared__ unsigned PsH[128][36];
    __shared__ unsigned PsL[128][36];

    const int tid  = threadIdx.x;
    const int wid  = tid >> 5, lane = tid & 31;
    const int wm   = wid & 3,  wn   = wid >> 2;
    const int g    = lane >> 2, qq  = lane & 3;

    // stage pos tile [128 p][64 d] as bf16 hi/lo pairs
#pragma unroll
    for (int u = 0; u < 8; ++u) {
        int idx = tid + u * 256;
        int prow = idx >> 4, c4 = (idx & 15) * 4;
        float4 v = *(const float4*)(Pos + (size_t)(P0 + prow) * DH_ + c4);
        unsigned h0, l0, h1, l1;
        bsplit2(v.x, v.y, h0, l0);
        bsplit2(v.z, v.w, h1, l1);
        int pc = (idx & 15) * 2;
        PsH[prow][pc] = h0; PsH[prow][pc + 1] = h1;
        PsL[prow][pc] = l0; PsL[prow][pc + 1] = l1;
    }

    // A (Q) fragments direct from global (layout HW-verified in attn_kernel)
    unsigned aH[2][4][4], aL[2][4][4];
#pragma unroll
    for (int tm = 0; tm < 2; ++tm) {
        const float* q0 = Q + ((size_t)(b * N_) + I0 + wm * 32 + tm * 16 + g) * DIM_ + h * DH_;
        const float* q8 = q0 + 8 * DIM_;
#pragma unroll
        for (int ks = 0; ks < 4; ++ks) {
            float2 xa = *(const float2*)(q0 + ks * 16 + 2 * qq);
            float2 xb = *(const float2*)(q0 + ks * 16 + 2 * qq + 8);
            float2 ya = *(const float2*)(q8 + ks * 16 + 2 * qq);
            float2 yb = *(const float2*)(q8 + ks * 16 + 2 * qq + 8);
            bsplit2(xa.x, xa.y, aH[tm][ks][0], aL[tm][ks][0]);
            bsplit2(ya.x, ya.y, aH[tm][ks][1], aL[tm][ks][1]);
            bsplit2(xb.x, xb.y, aH[tm][ks][2], aL[tm][ks][2]);
            bsplit2(yb.x, yb.y, aH[tm][ks][3], aL[tm][ks][3]);
        }
    }
    __syncthreads();

    float acc[2][8][4];
#pragma unroll
    for (int a = 0; a < 2; ++a)
#pragma unroll
        for (int t = 0; t < 8; ++t)
#pragma unroll
            for (int c = 0; c < 4; ++c) acc[a][t][c] = 0.f;

#pragma unroll
    for (int ks = 0; ks < 4; ++ks) {
#pragma unroll
        for (int tn = 0; tn < 8; ++tn) {
            int col = wn * 64 + tn * 8 + g;
            unsigned bh2[2], bl2[2];
            bh2[0] = PsH[col][8 * ks + qq];     bh2[1] = PsH[col][8 * ks + qq + 4];
            bl2[0] = PsL[col][8 * ks + qq];     bl2[1] = PsL[col][8 * ks + qq + 4];
#pragma unroll
            for (int tm = 0; tm < 2; ++tm) {
                mma_bf16(acc[tm][tn], aH[tm][ks], bh2);
                mma_bf16(acc[tm][tn], aH[tm][ks], bl2);
                mma_bf16(acc[tm][tn], aL[tm][ks], bh2);
            }
        }
    }

    float* base = RD + ((size_t)bh << 22);
#pragma unroll
    for (int tm = 0; tm < 2; ++tm) {
#pragma unroll
        for (int tn = 0; tn < 8; ++tn) {
            int row = I0 + wm * 32 + tm * 16 + g;
            int col = P0 + wn * 64 + tn * 8 + 2 * qq;
            float* dst = base + (size_t)row * N_ + col;
            *(float2*)dst = make_float2(acc[tm][tn][0] * SCALE_, acc[tm][tn][1] * SCALE_);
            *(float2*)(dst + 8 * N_) = make_float2(acc[tm][tn][2] * SCALE_, acc[tm][tn][3] * SCALE_);
        }
    }
}

// =====================================================================
// Tensor-core flash attention (bf16x3, m16n8k16, P in registers,
// pos term read directly from RD at p = j2 - i + 2047)
// =====================================================================
#define KST 72
#define VST 84
#define SMEM_ATTN ((2 * 32 * KST + 2 * 32 * VST + 1024) * 4)

__global__ __launch_bounds__(128, 3) void attn_kernel(
    const float* __restrict__ Q, const float* __restrict__ KV,
    const float* __restrict__ RD, const float* __restrict__ expire,
    float* __restrict__ O)
{
    extern __shared__ float smf[];
    float* Kb   = smf;                       // [2][32][72]
    float* Vb   = Kb + 2 * 32 * KST;         // [2][32][84]
    float* em_s = Vb + 2 * 32 * VST;         // [1024]

    const int b = blockIdx.z, h = blockIdx.y;
    const int tid = threadIdx.x;
    const int I0 = blockIdx.x * 64;
    const int W = tid >> 5, lane = tid & 31;
    const int g = lane >> 2, qq = lane & 3;

    {
        const float* emp = expire + b * MEM_;
        *(float4*)&em_s[tid * 8]     = *(const float4*)(emp + tid * 8);
        *(float4*)&em_s[tid * 8 + 4] = *(const float4*)(emp + tid * 8 + 4);
    }

    unsigned aH[4][4], aL[4][4];
    {
        const float* q0 = Q + ((size_t)(b * N_) + I0 + W * 16 + g) * DIM_ + h * DH_;
        const float* q8 = q0 + 8 * DIM_;
#pragma unroll
        for (int ks = 0; ks < 4; ++ks) {
            float2 xa = *(const float2*)(q0 + ks * 16 + 2 * qq);
            float2 xb = *(const float2*)(q0 + ks * 16 + 2 * qq + 8);
            float2 ya = *(const float2*)(q8 + ks * 16 + 2 * qq);
            float2 yb = *(const float2*)(q8 + ks * 16 + 2 * qq + 8);
            bsplit2(xa.x * SCALE_, xa.y * SCALE_, aH[ks][0], aL[ks][0]);
            bsplit2(ya.x * SCALE_, ya.y * SCALE_, aH[ks][1], aL[ks][1]);
            bsplit2(xb.x * SCALE_, xb.y * SCALE_, aH[ks][2], aL[ks][2]);
            bsplit2(yb.x * SCALE_, yb.y * SCALE_, aH[ks][3], aL[ks][3]);
        }
    }

    float o[8][4];
#pragma unroll
    for (int t = 0; t < 8; ++t)
#pragma unroll
        for (int c = 0; c < 4; ++c) o[t][c] = 0.f;
    float m0 = -1e30f, m1 = -1e30f, l0 = 0.f, l1 = 0.f;

    const float* kvbase = KV + (size_t)b * CTX_ * (2 * DIM_) + h * DH_;
    const float* rdb    = RD + (((size_t)(b * H_ + h)) << 22);
    const int ntiles = (MEM_ + I0 + 64) / 32;

#pragma unroll
    for (int u = 0; u < 4; ++u) {
        int e = u * 128 + tid, row = e >> 4, c = e & 15;
        const float* src = kvbase + (size_t)row * (2 * DIM_) + c * 4;
        cp_async16(Kb + row * KST + c * 4, src);
        cp_async16(Vb + row * VST + c * 4, src + DIM_);
    }
    asm volatile("cp.async.commit_group;");

    for (int t = 0; t < ntiles; ++t) {
        const int st = t & 1;
        const int j0 = t * 32;
        if (t + 1 < ntiles) {
            const int jn = j0 + 32;
            float* Kd = Kb + (st ^ 1) * 32 * KST;
            float* Vd = Vb + (st ^ 1) * 32 * VST;
#pragma unroll
            for (int u = 0; u < 4; ++u) {
                int e = u * 128 + tid, row = e >> 4, c = e & 15;
                const float* src = kvbase + (size_t)(jn + row) * (2 * DIM_) + c * 4;
                cp_async16(Kd + row * KST + c * 4, src);
                cp_async16(Vd + row * VST + c * 4, src + DIM_);
            }
        }
        asm volatile("cp.async.commit_group;");
        asm volatile("cp.async.wait_group 1;");
        __syncthreads();

        const float* Kc = Kb + st * 32 * KST;
        const float* Vc = Vb + st * 32 * VST;

        // ---- S = Q K^T ----
        float s[4][4];
#pragma unroll
        for (int tt = 0; tt < 4; ++tt)
#pragma unroll
            for (int c = 0; c < 4; ++c) s[tt][c] = 0.f;

#pragma unroll
        for (int ks = 0; ks < 4; ++ks) {
#pragma unroll
            for (int tt = 0; tt < 4; ++tt) {
                const float* kr = Kc + (tt * 8 + g) * KST + ks * 16 + 2 * qq;
                float2 k0 = *(const float2*)kr;
                float2 k1 = *(const float2*)(kr + 8);
                unsigned bh[2], bl[2];
                bsplit2(k0.x, k0.y, bh[0], bl[0]);
                bsplit2(k1.x, k1.y, bh[1], bl[1]);
                mma_bf16(s[tt], aH[ks], bh);
                mma_bf16(s[tt], aH[ks], bl);
                mma_bf16(s[tt], aL[ks], bh);
            }
        }

        const bool isMem = (j0 < MEM_);
        if (!isMem) {
            const int jb = j0 - MEM_;
            const int i0g = I0 + W * 16 + g;
            const float* rd0 = rdb + (size_t)i0g * N_;
            const float* rd1 = rd0 + 8 * N_;
            const int D0 = jb + 2047 - i0g;
            const int D1 = D0 - 8;
#pragma unroll
            for (int tt = 0; tt < 4; ++tt) {
                int c0 = tt * 8 + 2 * qq;
                int p00 = D0 + c0;     p00 = p00 > 2047 ? 2047 : p00;
                int p01 = D0 + c0 + 1; p01 = p01 > 2047 ? 2047 : p01;
                int p10 = D1 + c0;     p10 = p10 > 2047 ? 2047 : p10;
                int p11 = D1 + c0 + 1; p11 = p11 > 2047 ? 2047 : p11;
                s[tt][0] += rd0[p00];
                s[tt][1] += rd0[p01];
                s[tt][2] += rd1[p10];
                s[tt][3] += rd1[p11];
            }
            if (jb + 31 > I0) {
                const int r0 = i0g, r1 = i0g + 8;
#pragma unroll
                for (int tt = 0; tt < 4; ++tt) {
                    int c0 = jb + tt * 8 + 2 * qq;
                    if (c0     > r0) s[tt][0] = -1e30f;
                    if (c0 + 1 > r0) s[tt][1] = -1e30f;
                    if (c0     > r1) s[tt][2] = -1e30f;
                    if (c0 + 1 > r1) s[tt][3] = -1e30f;
                }
            }
        }

        // ---- online softmax ----
        float mt0 = fmaxf(fmaxf(s[0][0], s[0][1]), fmaxf(s[1][0], s[1][1]));
        mt0 = fmaxf(mt0, fmaxf(fmaxf(s[2][0], s[2][1]), fmaxf(s[3][0], s[3][1])));
        float mt1 = fmaxf(fmaxf(s[0][2], s[0][3]), fmaxf(s[1][2], s[1][3]));
        mt1 = fmaxf(mt1, fmaxf(fmaxf(s[2][2], s[2][3]), fmaxf(s[3][2], s[3][3])));
        mt0 = fmaxf(mt0, __shfl_xor_sync(0xffffffffu, mt0, 1));
        mt0 = fmaxf(mt0, __shfl_xor_sync(0xffffffffu, mt0, 2));
        mt1 = fmaxf(mt1, __shfl_xor_sync(0xffffffffu, mt1, 1));
        mt1 = fmaxf(mt1, __shfl_xor_sync(0xffffffffu, mt1, 2));
        float mn0 = fmaxf(m0, mt0), mn1 = fmaxf(m1, mt1);
        float f0 = __expf(m0 - mn0), f1 = __expf(m1 - mn1);
        l0 *= f0; l1 *= f1;
#pragma unroll
        for (int tt = 0; tt < 8; ++tt) {
            o[tt][0] *= f0; o[tt][1] *= f0;
            o[tt][2] *= f1; o[tt][3] *= f1;
        }
        m0 = mn0; m1 = mn1;

        unsigned pAh[4], pAl[4], pBh[4], pBl[4];
#pragma unroll
        for (int tt = 0; tt < 4; ++tt) {
            float p0 = __expf(s[tt][0] - m0);
            float p1 = __expf(s[tt][1] - m0);
            float p2 = __expf(s[tt][2] - m1);
            float p3 = __expf(s[tt][3] - m1);
            l0 += p0 + p1; l1 += p2 + p3;
            if (isMem) {
                float e0 = em_s[j0 + tt * 8 + 2 * qq];
                float e1 = em_s[j0 + tt * 8 + 2 * qq + 1];
                p0 *= e0; p1 *= e1; p2 *= e0; p3 *= e1;
            }
            bsplit2(p0, p1, pAh[tt], pAl[tt]);
            bsplit2(p2, p3, pBh[tt], pBl[tt]);
        }

        // ---- O += P V ----
#pragma unroll
        for (int ks = 0; ks < 2; ++ks) {
            unsigned ah[4] = { pAh[2 * ks], pBh[2 * ks], pAh[2 * ks + 1], pBh[2 * ks + 1] };
            unsigned al[4] = { pAl[2 * ks], pBl[2 * ks], pAl[2 * ks + 1], pBl[2 * ks + 1] };
#pragma unroll
            for (int tt = 0; tt < 8; ++tt) {
                int col = tt * 8 + g;
                float v00 = Vc[(ks * 16 + 2 * qq) * VST + col];
                float v01 = Vc[(ks * 16 + 2 * qq + 1) * VST + col];
                float v10 = Vc[(ks * 16 + 2 * qq + 8) * VST + col];
                float v11 = Vc[(ks * 16 + 2 * qq + 9) * VST + col];
                unsigned bh[2], bl[2];
                bsplit2(v00, v01, bh[0], bl[0]);
                bsplit2(v10, v11, bh[1], bl[1]);
                mma_bf16(o[tt], ah, bh);
                mma_bf16(o[tt], ah, bl);
                mma_bf16(o[tt], al, bh);
            }
        }
        __syncthreads();
    }

    l0 += __shfl_xor_sync(0xffffffffu, l0, 1);
    l0 += __shfl_xor_sync(0xffffffffu, l0, 2);
    l1 += __shfl_xor_sync(0xffffffffu, l1, 1);
    l1 += __shfl_xor_sync(0xffffffffu, l1, 2);
    float inv0 = 1.f / l0, inv1 = 1.f / l1;

    float* ob0 = O + ((size_t)(b * N_) + I0 + W * 16 + g) * DIM_ + h * DH_;
    float* ob1 = ob0 + 8 * DIM_;
#pragma unroll
    for (int tt = 0; tt < 8; ++tt) {
        int c0 = tt * 8 + 2 * qq;
        *(float2*)(ob0 + c0) = make_float2(o[tt][0] * inv0, o[tt][1] * inv0);
        *(float2*)(ob1 + c0) = make_float2(o[tt][2] * inv1, o[tt][3] * inv1);
    }
}

// ---------------- launcher ----------------
extern "C" void kernel_launch(void* const* d_in, const int* in_sizes, int n_in,
                              void* d_out, int out_size)
{
    const float* x       = (const float*)d_in[0];
    const float* pos_emb = (const float*)d_in[1];
    const float* mem     = (const float*)d_in[2];
    const float* expire  = (const float*)d_in[3];
    const float* Wq      = (const float*)d_in[4];
    const float* bq      = (const float*)d_in[5];
    const float* Wkv     = (const float*)d_in[6];
    const float* bkv     = (const float*)d_in[7];
    const float* Wo      = (const float*)d_in[8];
    const float* bo      = (const float*)d_in[9];
    const float* Wp      = (const float*)d_in[10];
    const float* bp      = (const float*)d_in[11];
    float* out = (float*)d_out;

    float *Q, *KV, *Pos, *RD, *O;
    cudaGetSymbolAddress((void**)&Q,   g_Q);
    cudaGetSymbolAddress((void**)&KV,  g_KV);
    cudaGetSymbolAddress((void**)&Pos, g_pos);
    cudaGetSymbolAddress((void**)&RD,  g_RD);
    cudaGetSymbolAddress((void**)&O,   g_O);

    cudaFuncSetAttribute(attn_kernel, cudaFuncAttributeMaxDynamicSharedMemorySize, SMEM_ATTN);

    // 1) Q = x @ Wq + bq
    gemm_bf16<<<dim3(DIM_ / 128, (B_ * N_) / 128, 1), 256>>>(
        x, B_ * N_, 0, x, 0, Wq, bq, Q, 0, DIM_, DIM_);

    // 2) KV = concat(mem, x) @ Wkv + bkv
    gemm_bf16<<<dim3(2 * DIM_ / 128, CTX_ / 128, B_), 256>>>(
        mem, MEM_, (size_t)MEM_ * DIM_, x, (size_t)N_ * DIM_,
        Wkv, bkv, KV, (size_t)CTX_ * 2 * DIM_, 2 * DIM_, DIM_);

    // 3) pos' = pos_emb @ Wp + bp
    gemm_bias<<<dim3(1, N_ / 64, 1), 256>>>(pos_emb, Wp, bp, Pos, N_, DH_, DIM_);

    // 4) RD = SCALE * Q_head @ pos'^T  (tensor-core, band-culled)
    rd_kernel<<<dim3(16, 16, B_ * H_), 256>>>(Q, Pos, RD);

    // 5) tensor-core flash attention -> O
    attn_kernel<<<dim3(N_ / 64, H_, B_), 128, SMEM_ATTN>>>(Q, KV, RD, expire, O);

    // 6) out = O @ Wo + bo
    gemm_bf16<<<dim3(DIM_ / 128, (B_ * N_) / 128, 1), 256>>>(
        O, B_ * N_, 0, O, 0, Wo, bo, out, 0, DIM_, DIM_);
}

// round 10
// speedup vs baseline: 5.9831x; 1.0718x over previous
#include <cuda_runtime.h>
#include <cuda_bf16.h>
#include <cstdint>
#include <cstddef>

#define B_    2
#define N_    2048
#define DIM_  1024
#define H_    16
#define DH_   64
#define MEM_  1024
#define CTX_  3072
#define SCALE_ 0.125f

// ---------------- scratch (static device globals; no allocation) ----------------
__device__ float    g_Q  [B_ * N_ * DIM_];         // 16 MB
__device__ float    g_KV [B_ * CTX_ * 2 * DIM_];   // 48 MB
__device__ float    g_pos[N_ * DH_];               // 512 KB
__device__ float    g_RD [134217728];              // 512 MB RD[b,h][i][p]
__device__ float    g_O  [B_ * N_ * DIM_];         // 16 MB
__device__ unsigned g_Kh [B_ * CTX_ * 512];        // 12.6 MB K hi (bf16x2, feature pairs)
__device__ unsigned g_Kl [B_ * CTX_ * 512];        // 12.6 MB K lo
__device__ unsigned g_Vth[B_ * H_ * DH_ * (CTX_/2)]; // 12.6 MB V^T hi (key pairs)
__device__ unsigned g_Vtl[B_ * H_ * DH_ * (CTX_/2)]; // 12.6 MB V^T lo

// =====================================================================
// bf16x3 helpers
// =====================================================================
__device__ __forceinline__ void bsplit2(float x, float y, unsigned& h, unsigned& l)
{
    asm("cvt.rn.bf16x2.f32 %0, %1, %2;" : "=r"(h) : "f"(y), "f"(x));
    float xr = x - __uint_as_float(h << 16);
    float yr = y - __uint_as_float(h & 0xFFFF0000u);
    asm("cvt.rn.bf16x2.f32 %0, %1, %2;" : "=r"(l) : "f"(yr), "f"(xr));
}

__device__ __forceinline__ void mma_bf16(float* c, const unsigned* a, const unsigned* b)
{
    asm volatile(
        "mma.sync.aligned.m16n8k16.row.col.f32.bf16.bf16.f32 "
        "{%0,%1,%2,%3}, {%4,%5,%6,%7}, {%8,%9}, {%0,%1,%2,%3};\n"
        : "+f"(c[0]), "+f"(c[1]), "+f"(c[2]), "+f"(c[3])
        : "r"(a[0]), "r"(a[1]), "r"(a[2]), "r"(a[3]), "r"(b[0]), "r"(b[1]));
}

__device__ __forceinline__ void cp_async16(void* s, const void* g)
{
    unsigned a = (unsigned)__cvta_generic_to_shared(s);
    asm volatile("cp.async.cg.shared.global [%0], [%1], 16;" :: "r"(a), "l"(g));
}

// =====================================================================
// Split-bf16 tensor-core GEMM:  C = A @ B + bias  (bf16x3, m16n8k16)
// If Kh != null, cols < kcols additionally written as packed bf16 hi/lo.
// =====================================================================
__global__ __launch_bounds__(256) void gemm_bf16(
    const float* __restrict__ Alo, int MLo, size_t sAlo,
    const float* __restrict__ Ahi, size_t sAhi,
    const float* __restrict__ Bm, const float* __restrict__ bias,
    float* __restrict__ C, size_t sC,
    int N, int K,
    unsigned* __restrict__ Kh, unsigned* __restrict__ Kl, int kcols)
{
    __shared__ __align__(16) unsigned AsH[128][12];
    __shared__ __align__(16) unsigned AsL[128][12];
    __shared__ __align__(16) unsigned BsH[8][136];
    __shared__ __align__(16) unsigned BsL[8][136];

    const int batch   = blockIdx.z;
    const int rowBase = blockIdx.y * 128;
    const int colBase = blockIdx.x * 128;
    const int tid  = threadIdx.x;
    const int wid  = tid >> 5, lane = tid & 31;
    const int wm   = wid & 3,  wn   = wid >> 2;
    const int g    = lane >> 2, qq  = lane & 3;

    const int ar = tid >> 2;
    const int ac = (tid & 3) * 4;
    const float* aptr[2];
#pragma unroll
    for (int i = 0; i < 2; ++i) {
        int r = rowBase + ar + 64 * i;
        aptr[i] = ((r < MLo) ? (Alo + (size_t)batch * sAlo + (size_t)r * K)
                             : (Ahi + (size_t)batch * sAhi + (size_t)(r - MLo) * K)) + ac;
    }
    const int kp = tid >> 5;
    const int n0 = (tid & 31) * 4;
    const float* bptr0 = Bm + (size_t)(2 * kp) * N + colBase + n0;
    const float* bptr1 = bptr0 + N;

    float4 ga[2], gb0, gb1;
#pragma unroll
    for (int i = 0; i < 2; ++i) ga[i] = *(const float4*)(aptr[i]);
    gb0 = *(const float4*)(bptr0);
    gb1 = *(const float4*)(bptr1);

    float acc[2][8][4];
#pragma unroll
    for (int a = 0; a < 2; ++a)
#pragma unroll
        for (int b = 0; b < 8; ++b)
#pragma unroll
            for (int c = 0; c < 4; ++c) acc[a][b][c] = 0.f;

    for (int k0 = 0; k0 < K; k0 += 16) {
#pragma unroll
        for (int i = 0; i < 2; ++i) {
            unsigned h0, l0, h1, l1;
            bsplit2(ga[i].x, ga[i].y, h0, l0);
            bsplit2(ga[i].z, ga[i].w, h1, l1);
            int r = ar + 64 * i, cpr = ac >> 1;
            AsH[r][cpr] = h0; AsH[r][cpr + 1] = h1;
            AsL[r][cpr] = l0; AsL[r][cpr + 1] = l1;
        }
        {
            uint4 bh, bl;
            bsplit2(gb0.x, gb1.x, bh.x, bl.x);
            bsplit2(gb0.y, gb1.y, bh.y, bl.y);
            bsplit2(gb0.z, gb1.z, bh.z, bl.z);
            bsplit2(gb0.w, gb1.w, bh.w, bl.w);
            *(uint4*)&BsH[kp][n0] = bh;
            *(uint4*)&BsL[kp][n0] = bl;
        }
        __syncthreads();

        if (k0 + 16 < K) {
#pragma unroll
            for (int i = 0; i < 2; ++i) ga[i] = *(const float4*)(aptr[i] + k0 + 16);
            gb0 = *(const float4*)(bptr0 + (size_t)(k0 + 16) * N);
            gb1 = *(const float4*)(bptr1 + (size_t)(k0 + 16) * N);
        }

        unsigned bH[8][2], bL[8][2];
#pragma unroll
        for (int tn = 0; tn < 8; ++tn) {
            int col = wn * 64 + tn * 8 + g;
            bH[tn][0] = BsH[qq][col]; bH[tn][1] = BsH[qq + 4][col];
            bL[tn][0] = BsL[qq][col]; bL[tn][1] = BsL[qq + 4][col];
        }
#pragma unroll
        for (int tm = 0; tm < 2; ++tm) {
            int r0 = wm * 32 + tm * 16 + g;
            unsigned aHf[4], aLf[4];
            aHf[0] = AsH[r0][qq];     aHf[1] = AsH[r0 + 8][qq];
            aHf[2] = AsH[r0][qq + 4]; aHf[3] = AsH[r0 + 8][qq + 4];
            aLf[0] = AsL[r0][qq];     aLf[1] = AsL[r0 + 8][qq];
            aLf[2] = AsL[r0][qq + 4]; aLf[3] = AsL[r0 + 8][qq + 4];
#pragma unroll
            for (int tn = 0; tn < 8; ++tn) {
                mma_bf16(acc[tm][tn], aHf, bH[tn]);
                mma_bf16(acc[tm][tn], aHf, bL[tn]);
                mma_bf16(acc[tm][tn], aLf, bH[tn]);
            }
        }
        __syncthreads();
    }

    float* Cb = C + (size_t)batch * sC;
#pragma unroll
    for (int tm = 0; tm < 2; ++tm) {
#pragma unroll
        for (int tn = 0; tn < 8; ++tn) {
            int row = rowBase + wm * 32 + tm * 16 + g;
            int col = colBase + wn * 64 + tn * 8 + 2 * qq;
            float b0 = bias[col], b1 = bias[col + 1];
            float2 v0 = make_float2(acc[tm][tn][0] + b0, acc[tm][tn][1] + b1);
            float2 v1 = make_float2(acc[tm][tn][2] + b0, acc[tm][tn][3] + b1);
            *(float2*)(Cb + (size_t)row * N + col) = v0;
            *(float2*)(Cb + (size_t)(row + 8) * N + col) = v1;
            if (Kh != nullptr && col < kcols) {
                unsigned hh, ll;
                size_t kr = ((size_t)batch * CTX_ + row) * (kcols >> 1) + (col >> 1);
                bsplit2(v0.x, v0.y, hh, ll);
                Kh[kr] = hh; Kl[kr] = ll;
                bsplit2(v1.x, v1.y, hh, ll);
                size_t kr2 = kr + (size_t)8 * (kcols >> 1);
                Kh[kr2] = hh; Kl[kr2] = ll;
            }
        }
    }
}

// ---------------- small scalar GEMM with bias (pos': N=64) ----------------
__global__ __launch_bounds__(256) void gemm_bias(
    const float* __restrict__ A, const float* __restrict__ Bm, const float* __restrict__ bias,
    float* __restrict__ C, int M, int N, int K)
{
    __shared__ float As[16][65];
    __shared__ float Bs[16][64];

    const int rowBase = blockIdx.y * 64;
    const int colBase = blockIdx.x * 64;
    const int tid = threadIdx.x;
    const int tx = tid & 15, ty = tid >> 4;

    const int arow = tid >> 2;
    const int ac   = (tid & 3) * 4;
    const int brow = tid >> 4;
    const int bc   = (tid & 15) * 4;

    const float* Aptr = A + (size_t)(rowBase + arow) * K;
    float acc[4][4] = {};

    for (int k0 = 0; k0 < K; k0 += 16) {
        float4 av = *(const float4*)(Aptr + k0 + ac);
        float4 bv = *(const float4*)(Bm + (size_t)(k0 + brow) * N + colBase + bc);
        __syncthreads();
        As[ac + 0][arow] = av.x; As[ac + 1][arow] = av.y;
        As[ac + 2][arow] = av.z; As[ac + 3][arow] = av.w;
        *(float4*)&Bs[brow][bc] = bv;
        __syncthreads();
#pragma unroll
        for (int kk = 0; kk < 16; ++kk) {
            float a0 = As[kk][ty * 4 + 0], a1 = As[kk][ty * 4 + 1];
            float a2 = As[kk][ty * 4 + 2], a3 = As[kk][ty * 4 + 3];
            float4 b4 = *(const float4*)&Bs[kk][tx * 4];
            acc[0][0] += a0 * b4.x; acc[0][1] += a0 * b4.y; acc[0][2] += a0 * b4.z; acc[0][3] += a0 * b4.w;
            acc[1][0] += a1 * b4.x; acc[1][1] += a1 * b4.y; acc[1][2] += a1 * b4.z; acc[1][3] += a1 * b4.w;
            acc[2][0] += a2 * b4.x; acc[2][1] += a2 * b4.y; acc[2][2] += a2 * b4.z; acc[2][3] += a2 * b4.w;
            acc[3][0] += a3 * b4.x; acc[3][1] += a3 * b4.y; acc[3][2] += a3 * b4.z; acc[3][3] += a3 * b4.w;
        }
    }

    float4 bvv = *(const float4*)(bias + colBase + tx * 4);
#pragma unroll
    for (int a = 0; a < 4; ++a) {
        int row = rowBase + ty * 4 + a;
        float4 o;
        o.x = acc[a][0] + bvv.x; o.y = acc[a][1] + bvv.y;
        o.z = acc[a][2] + bvv.z; o.w = acc[a][3] + bvv.w;
        *(float4*)(C + (size_t)row * N + colBase + tx * 4) = o;
    }
}

// =====================================================================
// vt_kernel: V^T split — Vth/Vtl[bh][d][j/2] = packed(V[j][d], V[j+1][d])
// =====================================================================
__global__ __launch_bounds__(256) void vt_kernel(
    const float* __restrict__ KV, unsigned* __restrict__ Vth, unsigned* __restrict__ Vtl)
{
    const int bh = blockIdx.y;
    const int b = bh >> 4, h = bh & 15;
    const int J0 = blockIdx.x * 64;
    __shared__ float Vs[64][65];
    const int tid = threadIdx.x;

#pragma unroll
    for (int u = 0; u < 4; ++u) {
        int idx = u * 256 + tid;
        int row = idx >> 4, c4 = (idx & 15) * 4;
        float4 v = *(const float4*)(KV + ((size_t)b * CTX_ + J0 + row) * (2 * DIM_) + DIM_ + h * DH_ + c4);
        Vs[row][c4] = v.x; Vs[row][c4 + 1] = v.y; Vs[row][c4 + 2] = v.z; Vs[row][c4 + 3] = v.w;
    }
    __syncthreads();

#pragma unroll
    for (int u = 0; u < 8; ++u) {
        int idx = u * 256 + tid;
        int d = idx >> 5, jp = idx & 31;
        unsigned hh, ll;
        bsplit2(Vs[2 * jp][d], Vs[2 * jp + 1][d], hh, ll);
        size_t o = ((size_t)bh * DH_ + d) * (CTX_ / 2) + (J0 >> 1) + jp;
        Vth[o] = hh; Vtl[o] = ll;
    }
}

// =====================================================================
// rd_kernel: RD[b,h][i][p] = SCALE * q_i . pos'_p  (bf16x3, band-culled)
// =====================================================================
__global__ __launch_bounds__(256) void rd_kernel(
    const float* __restrict__ Q, const float* __restrict__ Pos, float* __restrict__ RD)
{
    const int I0 = blockIdx.y * 128;
    const int P0 = blockIdx.x * 128;
    if (I0 + P0 + 254 < 2047) return;

    const int bh = blockIdx.z;
    const int b  = bh >> 4, h = bh & 15;

    __shared__ unsigned PsH[128][36];
    __shared__ unsigned PsL[128][36];

    const int tid  = threadIdx.x;
    const int wid  = tid >> 5, lane = tid & 31;
    const int wm   = wid & 3,  wn   = wid >> 2;
    const int g    = lane >> 2, qq  = lane & 3;

#pragma unroll
    for (int u = 0; u < 8; ++u) {
        int idx = tid + u * 256;
        int prow = idx >> 4, c4 = (idx & 15) * 4;
        float4 v = *(const float4*)(Pos + (size_t)(P0 + prow) * DH_ + c4);
        unsigned h0, l0, h1, l1;
        bsplit2(v.x, v.y, h0, l0);
        bsplit2(v.z, v.w, h1, l1);
        int pc = (idx & 15) * 2;
        PsH[prow][pc] = h0; PsH[prow][pc + 1] = h1;
        PsL[prow][pc] = l0; PsL[prow][pc + 1] = l1;
    }

    unsigned aH[2][4][4], aL[2][4][4];
#pragma unroll
    for (int tm = 0; tm < 2; ++tm) {
        const float* q0 = Q + ((size_t)(b * N_) + I0 + wm * 32 + tm * 16 + g) * DIM_ + h * DH_;
        const float* q8 = q0 + 8 * DIM_;
#pragma unroll
        for (int ks = 0; ks < 4; ++ks) {
            float2 xa = *(const float2*)(q0 + ks * 16 + 2 * qq);
            float2 xb = *(const float2*)(q0 + ks * 16 + 2 * qq + 8);
            float2 ya = *(const float2*)(q8 + ks * 16 + 2 * qq);
            float2 yb = *(const float2*)(q8 + ks * 16 + 2 * qq + 8);
            bsplit2(xa.x, xa.y, aH[tm][ks][0], aL[tm][ks][0]);
            bsplit2(ya.x, ya.y, aH[tm][ks][1], aL[tm][ks][1]);
            bsplit2(xb.x, xb.y, aH[tm][ks][2], aL[tm][ks][2]);
            bsplit2(yb.x, yb.y, aH[tm][ks][3], aL[tm][ks][3]);
        }
    }
    __syncthreads();

    float acc[2][8][4];
#pragma unroll
    for (int a = 0; a < 2; ++a)
#pragma unroll
        for (int t = 0; t < 8; ++t)
#pragma unroll
            for (int c = 0; c < 4; ++c) acc[a][t][c] = 0.f;

#pragma unroll
    for (int ks = 0; ks < 4; ++ks) {
#pragma unroll
        for (int tn = 0; tn < 8; ++tn) {
            int col = wn * 64 + tn * 8 + g;
            unsigned bh2[2], bl2[2];
            bh2[0] = PsH[col][8 * ks + qq];     bh2[1] = PsH[col][8 * ks + qq + 4];
            bl2[0] = PsL[col][8 * ks + qq];     bl2[1] = PsL[col][8 * ks + qq + 4];
#pragma unroll
            for (int tm = 0; tm < 2; ++tm) {
                mma_bf16(acc[tm][tn], aH[tm][ks], bh2);
                mma_bf16(acc[tm][tn], aH[tm][ks], bl2);
                mma_bf16(acc[tm][tn], aL[tm][ks], bh2);
            }
        }
    }

    float* base = RD + ((size_t)bh << 22);
#pragma unroll
    for (int tm = 0; tm < 2; ++tm) {
#pragma unroll
        for (int tn = 0; tn < 8; ++tn) {
            int row = I0 + wm * 32 + tm * 16 + g;
            int col = P0 + wn * 64 + tn * 8 + 2 * qq;
            float* dst = base + (size_t)row * N_ + col;
            *(float2*)dst = make_float2(acc[tm][tn][0] * SCALE_, acc[tm][tn][1] * SCALE_);
            *(float2*)(dst + 8 * N_) = make_float2(acc[tm][tn][2] * SCALE_, acc[tm][tn][3] * SCALE_);
        }
    }
}

// =====================================================================
// Tensor-core flash attention (bf16x3; K/V pre-split, zero runtime splits)
// =====================================================================
#define KW   36
#define SM_K (32 * KW)          // 1152 words per K stage
#define SM_V (64 * KW)          // 2304 words per Vt stage
#define OFF_KL 2304
#define OFF_VH 4608
#define OFF_VL 9216
#define OFF_EM 13824
#define SMEM_ATTN ((OFF_EM + 1024) * 4)   // 59392 B

__device__ __forceinline__ void load_kv_stage(
    unsigned* smu, int sb, int jt, int tid, int b, int bh64,
    const unsigned* __restrict__ Khg, const unsigned* __restrict__ Klg,
    const unsigned* __restrict__ Vthg, const unsigned* __restrict__ Vtlg, int h)
{
    unsigned* KhD = smu + sb * SM_K;
    unsigned* KlD = smu + OFF_KL + sb * SM_K;
    unsigned* VhD = smu + OFF_VH + sb * SM_V;
    unsigned* VlD = smu + OFF_VL + sb * SM_V;
#pragma unroll
    for (int u = 0; u < 2; ++u) {
        int e = u * 128 + tid;
        int row = e >> 3, part = e & 7;
        size_t srk = ((size_t)b * CTX_ + jt + row) * 512 + h * 32 + part * 4;
        cp_async16(KhD + row * KW + part * 4, Khg + srk);
        cp_async16(KlD + row * KW + part * 4, Klg + srk);
    }
#pragma unroll
    for (int u = 0; u < 2; ++u) {
        int e = u * 128 + tid;
        int row = e >> 2, part = e & 3;
        size_t srv = ((size_t)bh64 + row) * (CTX_ / 2) + (jt >> 1) + part * 4;
        cp_async16(VhD + row * KW + part * 4, Vthg + srv);
        cp_async16(VlD + row * KW + part * 4, Vtlg + srv);
    }
}

__global__ __launch_bounds__(128, 3) void attn_kernel(
    const float* __restrict__ Q,
    const unsigned* __restrict__ Khg, const unsigned* __restrict__ Klg,
    const unsigned* __restrict__ Vthg, const unsigned* __restrict__ Vtlg,
    const float* __restrict__ RD, const float* __restrict__ expire,
    float* __restrict__ O)
{
    extern __shared__ unsigned smu[];
    float* em_s = (float*)(smu + OFF_EM);

    const int b = blockIdx.z, h = blockIdx.y;
    const int tid = threadIdx.x;
    const int I0 = blockIdx.x * 64;
    const int W = tid >> 5, lane = tid & 31;
    const int g = lane >> 2, qq = lane & 3;
    const int bh64 = (b * H_ + h) * DH_;

    {
        const float* emp = expire + b * MEM_;
        *(float4*)&em_s[tid * 8]     = *(const float4*)(emp + tid * 8);
        *(float4*)&em_s[tid * 8 + 4] = *(const float4*)(emp + tid * 8 + 4);
    }

    unsigned aH[4][4], aL[4][4];
    {
        const float* q0 = Q + ((size_t)(b * N_) + I0 + W * 16 + g) * DIM_ + h * DH_;
        const float* q8 = q0 + 8 * DIM_;
#pragma unroll
        for (int ks = 0; ks < 4; ++ks) {
            float2 xa = *(const float2*)(q0 + ks * 16 + 2 * qq);
            float2 xb = *(const float2*)(q0 + ks * 16 + 2 * qq + 8);
            float2 ya = *(const float2*)(q8 + ks * 16 + 2 * qq);
            float2 yb = *(const float2*)(q8 + ks * 16 + 2 * qq + 8);
            bsplit2(xa.x * SCALE_, xa.y * SCALE_, aH[ks][0], aL[ks][0]);
            bsplit2(ya.x * SCALE_, ya.y * SCALE_, aH[ks][1], aL[ks][1]);
            bsplit2(xb.x * SCALE_, xb.y * SCALE_, aH[ks][2], aL[ks][2]);
            bsplit2(yb.x * SCALE_, yb.y * SCALE_, aH[ks][3], aL[ks][3]);
        }
    }

    float o[8][4];
#pragma unroll
    for (int t = 0; t < 8; ++t)
#pragma unroll
        for (int c = 0; c < 4; ++c) o[t][c] = 0.f;
    float m0 = -1e30f, m1 = -1e30f, l0 = 0.f, l1 = 0.f;

    const float* rdb = RD + (((size_t)(b * H_ + h)) << 22);
    const int ntiles = (MEM_ + I0 + 64) / 32;

    load_kv_stage(smu, 0, 0, tid, b, bh64, Khg, Klg, Vthg, Vtlg, h);
    asm volatile("cp.async.commit_group;");

    for (int t = 0; t < ntiles; ++t) {
        const int st = t & 1;
        const int j0 = t * 32;
        if (t + 1 < ntiles)
            load_kv_stage(smu, st ^ 1, j0 + 32, tid, b, bh64, Khg, Klg, Vthg, Vtlg, h);
        asm volatile("cp.async.commit_group;");
        asm volatile("cp.async.wait_group 1;");
        __syncthreads();

        const unsigned* KhC = smu + st * SM_K;
        const unsigned* KlC = smu + OFF_KL + st * SM_K;
        const unsigned* VhC = smu + OFF_VH + st * SM_V;
        const unsigned* VlC = smu + OFF_VL + st * SM_V;

        // ---- S = Q K^T ----
        float s[4][4];
#pragma unroll
        for (int tt = 0; tt < 4; ++tt)
#pragma unroll
            for (int c = 0; c < 4; ++c) s[tt][c] = 0.f;

#pragma unroll
        for (int ks = 0; ks < 4; ++ks) {
#pragma unroll
            for (int tt = 0; tt < 4; ++tt) {
                int base = (tt * 8 + g) * KW + ks * 8 + qq;
                unsigned bhf[2] = { KhC[base], KhC[base + 4] };
                unsigned blf[2] = { KlC[base], KlC[base + 4] };
                mma_bf16(s[tt], aH[ks], bhf);
                mma_bf16(s[tt], aH[ks], blf);
                mma_bf16(s[tt], aL[ks], bhf);
            }
        }

        const bool isMem = (j0 < MEM_);
        if (!isMem) {
            const int jb = j0 - MEM_;
            const int i0g = I0 + W * 16 + g;
            const float* rd0 = rdb + (size_t)i0g * N_;
            const float* rd1 = rd0 + 8 * N_;
            const int D0 = jb + 2047 - i0g;
            const int D1 = D0 - 8;
#pragma unroll
            for (int tt = 0; tt < 4; ++tt) {
                int c0 = tt * 8 + 2 * qq;
                int p00 = D0 + c0;     p00 = p00 > 2047 ? 2047 : p00;
                int p01 = D0 + c0 + 1; p01 = p01 > 2047 ? 2047 : p01;
                int p10 = D1 + c0;     p10 = p10 > 2047 ? 2047 : p10;
                int p11 = D1 + c0 + 1; p11 = p11 > 2047 ? 2047 : p11;
                s[tt][0] += rd0[p00];
                s[tt][1] += rd0[p01];
                s[tt][2] += rd1[p10];
                s[tt][3] += rd1[p11];
            }
            if (jb + 31 > I0) {
                const int r0 = i0g, r1 = i0g + 8;
#pragma unroll
                for (int tt = 0; tt < 4; ++tt) {
                    int c0 = jb + tt * 8 + 2 * qq;
                    if (c0     > r0) s[tt][0] = -1e30f;
                    if (c0 + 1 > r0) s[tt][1] = -1e30f;
                    if (c0     > r1) s[tt][2] = -1e30f;
                    if (c0 + 1 > r1) s[tt][3] = -1e30f;
                }
            }
        }

        // ---- online softmax ----
        float mt0 = fmaxf(fmaxf(s[0][0], s[0][1]), fmaxf(s[1][0], s[1][1]));
        mt0 = fmaxf(mt0, fmaxf(fmaxf(s[2][0], s[2][1]), fmaxf(s[3][0], s[3][1])));
        float mt1 = fmaxf(fmaxf(s[0][2], s[0][3]), fmaxf(s[1][2], s[1][3]));
        mt1 = fmaxf(mt1, fmaxf(fmaxf(s[2][2], s[2][3]), fmaxf(s[3][2], s[3][3])));
        mt0 = fmaxf(mt0, __shfl_xor_sync(0xffffffffu, mt0, 1));
        mt0 = fmaxf(mt0, __shfl_xor_sync(0xffffffffu, mt0, 2));
        mt1 = fmaxf(mt1, __shfl_xor_sync(0xffffffffu, mt1, 1));
        mt1 = fmaxf(mt1, __shfl_xor_sync(0xffffffffu, mt1, 2));
        float mn0 = fmaxf(m0, mt0), mn1 = fmaxf(m1, mt1);
        float f0 = __expf(m0 - mn0), f1 = __expf(m1 - mn1);
        l0 *= f0; l1 *= f1;
#pragma unroll
        for (int tt = 0; tt < 8; ++tt) {
            o[tt][0] *= f0; o[tt][1] *= f0;
            o[tt][2] *= f1; o[tt][3] *= f1;
        }
        m0 = mn0; m1 = mn1;

        unsigned pAh[4], pAl[4], pBh[4], pBl[4];
#pragma unroll
        for (int tt = 0; tt < 4; ++tt) {
            float p0 = __expf(s[tt][0] - m0);
            float p1 = __expf(s[tt][1] - m0);
            float p2 = __expf(s[tt][2] - m1);
            float p3 = __expf(s[tt][3] - m1);
            l0 += p0 + p1; l1 += p2 + p3;
            if (isMem) {
                float e0 = em_s[j0 + tt * 8 + 2 * qq];
                float e1 = em_s[j0 + tt * 8 + 2 * qq + 1];
                p0 *= e0; p1 *= e1; p2 *= e0; p3 *= e1;
            }
            bsplit2(p0, p1, pAh[tt], pAl[tt]);
            bsplit2(p2, p3, pBh[tt], pBl[tt]);
        }

        // ---- O += P V ----
#pragma unroll
        for (int ks = 0; ks < 2; ++ks) {
            unsigned ah[4] = { pAh[2 * ks], pBh[2 * ks], pAh[2 * ks + 1], pBh[2 * ks + 1] };
            unsigned al[4] = { pAl[2 * ks], pBl[2 * ks], pAl[2 * ks + 1], pBl[2 * ks + 1] };
#pragma unroll
            for (int tt = 0; tt < 8; ++tt) {
                int base = (tt * 8 + g) * KW + ks * 8 + qq;
                unsigned bhf[2] = { VhC[base], VhC[base + 4] };
                unsigned blf[2] = { VlC[base], VlC[base + 4] };
                mma_bf16(o[tt], ah, bhf);
                mma_bf16(o[tt], ah, blf);
                mma_bf16(o[tt], al, bhf);
            }
        }
        __syncthreads();
    }

    l0 += __shfl_xor_sync(0xffffffffu, l0, 1);
    l0 += __shfl_xor_sync(0xffffffffu, l0, 2);
    l1 += __shfl_xor_sync(0xffffffffu, l1, 1);
    l1 += __shfl_xor_sync(0xffffffffu, l1, 2);
    float inv0 = 1.f / l0, inv1 = 1.f / l1;

    float* ob0 = O + ((size_t)(b * N_) + I0 + W * 16 + g) * DIM_ + h * DH_;
    float* ob1 = ob0 + 8 * DIM_;
#pragma unroll
    for (int tt = 0; tt < 8; ++tt) {
        int c0 = tt * 8 + 2 * qq;
        *(float2*)(ob0 + c0) = make_float2(o[tt][0] * inv0, o[tt][1] * inv0);
        *(float2*)(ob1 + c0) = make_float2(o[tt][2] * inv1, o[tt][3] * inv1);
    }
}

// ---------------- launcher ----------------
extern "C" void kernel_launch(void* const* d_in, const int* in_sizes, int n_in,
                              void* d_out, int out_size)
{
    const float* x       = (const float*)d_in[0];
    const float* pos_emb = (const float*)d_in[1];
    const float* mem     = (const float*)d_in[2];
    const float* expire  = (const float*)d_in[3];
    const float* Wq      = (const float*)d_in[4];
    const float* bq      = (const float*)d_in[5];
    const float* Wkv     = (const float*)d_in[6];
    const float* bkv     = (const float*)d_in[7];
    const float* Wo      = (const float*)d_in[8];
    const float* bo      = (const float*)d_in[9];
    const float* Wp      = (const float*)d_in[10];
    const float* bp      = (const float*)d_in[11];
    float* out = (float*)d_out;

    float *Q, *KV, *Pos, *RD, *O;
    unsigned *Kh, *Kl, *Vth, *Vtl;
    cudaGetSymbolAddress((void**)&Q,   g_Q);
    cudaGetSymbolAddress((void**)&KV,  g_KV);
    cudaGetSymbolAddress((void**)&Pos, g_pos);
    cudaGetSymbolAddress((void**)&RD,  g_RD);
    cudaGetSymbolAddress((void**)&O,   g_O);
    cudaGetSymbolAddress((void**)&Kh,  g_Kh);
    cudaGetSymbolAddress((void**)&Kl,  g_Kl);
    cudaGetSymbolAddress((void**)&Vth, g_Vth);
    cudaGetSymbolAddress((void**)&Vtl, g_Vtl);

    cudaFuncSetAttribute(attn_kernel, cudaFuncAttributeMaxDynamicSharedMemorySize, SMEM_ATTN);

    // 1) Q = x @ Wq + bq
    gemm_bf16<<<dim3(DIM_ / 128, (B_ * N_) / 128, 1), 256>>>(
        x, B_ * N_, 0, x, 0, Wq, bq, Q, 0, DIM_, DIM_, nullptr, nullptr, 0);

    // 2) KV = concat(mem, x) @ Wkv + bkv  (also emits packed-bf16 K)
    gemm_bf16<<<dim3(2 * DIM_ / 128, CTX_ / 128, B_), 256>>>(
        mem, MEM_, (size_t)MEM_ * DIM_, x, (size_t)N_ * DIM_,
        Wkv, bkv, KV, (size_t)CTX_ * 2 * DIM_, 2 * DIM_, DIM_, Kh, Kl, DIM_);

    // 3) V^T split for attention PV fragments
    vt_kernel<<<dim3(CTX_ / 64, B_ * H_), 256>>>(KV, Vth, Vtl);

    // 4) pos' = pos_emb @ Wp + bp
    gemm_bias<<<dim3(1, N_ / 64, 1), 256>>>(pos_emb, Wp, bp, Pos, N_, DH_, DIM_);

    // 5) RD = SCALE * Q_head @ pos'^T  (band-culled)
    rd_kernel<<<dim3(16, 16, B_ * H_), 256>>>(Q, Pos, RD);

    // 6) tensor-core flash attention -> O
    attn_kernel<<<dim3(N_ / 64, H_, B_), 128, SMEM_ATTN>>>(
        Q, Kh, Kl, Vth, Vtl, RD, expire, O);

    // 7) out = O @ Wo + bo
    gemm_bf16<<<dim3(DIM_ / 128, (B_ * N_) / 128, 1), 256>>>(
        O, B_ * N_, 0, O, 0, Wo, bo, out, 0, DIM_, DIM_, nullptr, nullptr, 0);
}

// round 11
// speedup vs baseline: 6.3442x; 1.0604x over previous
#include <cuda_runtime.h>
#include <cuda_bf16.h>
#include <cstdint>
#include <cstddef>

#define B_    2
#define N_    2048
#define DIM_  1024
#define H_    16
#define DH_   64
#define MEM_  1024
#define CTX_  3072
#define SCALE_ 0.125f

// ---------------- scratch (static device globals; no allocation) ----------------
__device__ float    g_Q  [B_ * N_ * DIM_];         // 16 MB
__device__ float    g_KV [B_ * CTX_ * 2 * DIM_];   // 48 MB
__device__ float    g_pos[N_ * DH_];               // 512 KB
__device__ float    g_posp[8 * N_ * DH_];          // 4 MB  split-K partials
__device__ float    g_RD [134217728];              // 512 MB RD[b,h][i][p]
__device__ float    g_O  [B_ * N_ * DIM_];         // 16 MB
__device__ unsigned g_Kh [B_ * CTX_ * 512];        // 12.6 MB K hi (bf16x2, feature pairs)
__device__ unsigned g_Kl [B_ * CTX_ * 512];        // 12.6 MB K lo
__device__ unsigned g_Vth[B_ * H_ * DH_ * (CTX_/2)]; // 12.6 MB V^T hi (key pairs)
__device__ unsigned g_Vtl[B_ * H_ * DH_ * (CTX_/2)]; // 12.6 MB V^T lo

// =====================================================================
// bf16x3 helpers
// =====================================================================
__device__ __forceinline__ void bsplit2(float x, float y, unsigned& h, unsigned& l)
{
    asm("cvt.rn.bf16x2.f32 %0, %1, %2;" : "=r"(h) : "f"(y), "f"(x));
    float xr = x - __uint_as_float(h << 16);
    float yr = y - __uint_as_float(h & 0xFFFF0000u);
    asm("cvt.rn.bf16x2.f32 %0, %1, %2;" : "=r"(l) : "f"(yr), "f"(xr));
}

__device__ __forceinline__ void mma_bf16(float* c, const unsigned* a, const unsigned* b)
{
    asm volatile(
        "mma.sync.aligned.m16n8k16.row.col.f32.bf16.bf16.f32 "
        "{%0,%1,%2,%3}, {%4,%5,%6,%7}, {%8,%9}, {%0,%1,%2,%3};\n"
        : "+f"(c[0]), "+f"(c[1]), "+f"(c[2]), "+f"(c[3])
        : "r"(a[0]), "r"(a[1]), "r"(a[2]), "r"(a[3]), "r"(b[0]), "r"(b[1]));
}

__device__ __forceinline__ void cp_async16(void* s, const void* g)
{
    unsigned a = (unsigned)__cvta_generic_to_shared(s);
    asm volatile("cp.async.cg.shared.global [%0], [%1], 16;" :: "r"(a), "l"(g));
}

// =====================================================================
// Split-bf16 tensor-core GEMM:  C = A @ B + bias  (bf16x3, m16n8k16)
// Pass-major mma order: consecutive mmas hit independent accumulators.
// =====================================================================
__global__ __launch_bounds__(256) void gemm_bf16(
    const float* __restrict__ Alo, int MLo, size_t sAlo,
    const float* __restrict__ Ahi, size_t sAhi,
    const float* __restrict__ Bm, const float* __restrict__ bias,
    float* __restrict__ C, size_t sC,
    int N, int K,
    unsigned* __restrict__ Kh, unsigned* __restrict__ Kl, int kcols)
{
    __shared__ __align__(16) unsigned AsH[128][12];
    __shared__ __align__(16) unsigned AsL[128][12];
    __shared__ __align__(16) unsigned BsH[8][136];
    __shared__ __align__(16) unsigned BsL[8][136];

    const int batch   = blockIdx.z;
    const int rowBase = blockIdx.y * 128;
    const int colBase = blockIdx.x * 128;
    const int tid  = threadIdx.x;
    const int wid  = tid >> 5, lane = tid & 31;
    const int wm   = wid & 3,  wn   = wid >> 2;
    const int g    = lane >> 2, qq  = lane & 3;

    const int ar = tid >> 2;
    const int ac = (tid & 3) * 4;
    const float* aptr[2];
#pragma unroll
    for (int i = 0; i < 2; ++i) {
        int r = rowBase + ar + 64 * i;
        aptr[i] = ((r < MLo) ? (Alo + (size_t)batch * sAlo + (size_t)r * K)
                             : (Ahi + (size_t)batch * sAhi + (size_t)(r - MLo) * K)) + ac;
    }
    const int kp = tid >> 5;
    const int n0 = (tid & 31) * 4;
    const float* bptr0 = Bm + (size_t)(2 * kp) * N + colBase + n0;
    const float* bptr1 = bptr0 + N;

    float4 ga[2], gb0, gb1;
#pragma unroll
    for (int i = 0; i < 2; ++i) ga[i] = *(const float4*)(aptr[i]);
    gb0 = *(const float4*)(bptr0);
    gb1 = *(const float4*)(bptr1);

    float acc[2][8][4];
#pragma unroll
    for (int a = 0; a < 2; ++a)
#pragma unroll
        for (int b = 0; b < 8; ++b)
#pragma unroll
            for (int c = 0; c < 4; ++c) acc[a][b][c] = 0.f;

    for (int k0 = 0; k0 < K; k0 += 16) {
#pragma unroll
        for (int i = 0; i < 2; ++i) {
            unsigned h0, l0, h1, l1;
            bsplit2(ga[i].x, ga[i].y, h0, l0);
            bsplit2(ga[i].z, ga[i].w, h1, l1);
            int r = ar + 64 * i, cpr = ac >> 1;
            AsH[r][cpr] = h0; AsH[r][cpr + 1] = h1;
            AsL[r][cpr] = l0; AsL[r][cpr + 1] = l1;
        }
        {
            uint4 bh, bl;
            bsplit2(gb0.x, gb1.x, bh.x, bl.x);
            bsplit2(gb0.y, gb1.y, bh.y, bl.y);
            bsplit2(gb0.z, gb1.z, bh.z, bl.z);
            bsplit2(gb0.w, gb1.w, bh.w, bl.w);
            *(uint4*)&BsH[kp][n0] = bh;
            *(uint4*)&BsL[kp][n0] = bl;
        }
        __syncthreads();

        if (k0 + 16 < K) {
#pragma unroll
            for (int i = 0; i < 2; ++i) ga[i] = *(const float4*)(aptr[i] + k0 + 16);
            gb0 = *(const float4*)(bptr0 + (size_t)(k0 + 16) * N);
            gb1 = *(const float4*)(bptr1 + (size_t)(k0 + 16) * N);
        }

        unsigned bH[8][2], bL[8][2];
#pragma unroll
        for (int tn = 0; tn < 8; ++tn) {
            int col = wn * 64 + tn * 8 + g;
            bH[tn][0] = BsH[qq][col]; bH[tn][1] = BsH[qq + 4][col];
            bL[tn][0] = BsL[qq][col]; bL[tn][1] = BsL[qq + 4][col];
        }
#pragma unroll
        for (int tm = 0; tm < 2; ++tm) {
            int r0 = wm * 32 + tm * 16 + g;
            unsigned aHf[4], aLf[4];
            aHf[0] = AsH[r0][qq];     aHf[1] = AsH[r0 + 8][qq];
            aHf[2] = AsH[r0][qq + 4]; aHf[3] = AsH[r0 + 8][qq + 4];
            aLf[0] = AsL[r0][qq];     aLf[1] = AsL[r0 + 8][qq];
            aLf[2] = AsL[r0][qq + 4]; aLf[3] = AsL[r0 + 8][qq + 4];
            // pass-major: 8 independent accumulators between touches of the same one
#pragma unroll
            for (int tn = 0; tn < 8; ++tn) mma_bf16(acc[tm][tn], aHf, bH[tn]);
#pragma unroll
            for (int tn = 0; tn < 8; ++tn) mma_bf16(acc[tm][tn], aHf, bL[tn]);
#pragma unroll
            for (int tn = 0; tn < 8; ++tn) mma_bf16(acc[tm][tn], aLf, bH[tn]);
        }
        __syncthreads();
    }

    float* Cb = C + (size_t)batch * sC;
#pragma unroll
    for (int tm = 0; tm < 2; ++tm) {
#pragma unroll
        for (int tn = 0; tn < 8; ++tn) {
            int row = rowBase + wm * 32 + tm * 16 + g;
            int col = colBase + wn * 64 + tn * 8 + 2 * qq;
            float b0 = bias[col], b1 = bias[col + 1];
            float2 v0 = make_float2(acc[tm][tn][0] + b0, acc[tm][tn][1] + b1);
            float2 v1 = make_float2(acc[tm][tn][2] + b0, acc[tm][tn][3] + b1);
            *(float2*)(Cb + (size_t)row * N + col) = v0;
            *(float2*)(Cb + (size_t)(row + 8) * N + col) = v1;
            if (Kh != nullptr && col < kcols) {
                unsigned hh, ll;
                size_t kr = ((size_t)batch * CTX_ + row) * (kcols >> 1) + (col >> 1);
                bsplit2(v0.x, v0.y, hh, ll);
                Kh[kr] = hh; Kl[kr] = ll;
                bsplit2(v1.x, v1.y, hh, ll);
                size_t kr2 = kr + (size_t)8 * (kcols >> 1);
                Kh[kr2] = hh; Kl[kr2] = ll;
            }
        }
    }
}

// =====================================================================
// pos' split-K: stage 1 partials (grid 8 ksplit x 32 rowtiles), stage 2 reduce
// =====================================================================
__global__ __launch_bounds__(256) void pos_part(
    const float* __restrict__ A, const float* __restrict__ Bm, float* __restrict__ Cp)
{
    __shared__ float As[16][65];
    __shared__ float Bs[16][64];

    const int kOff    = blockIdx.x * 128;
    const int rowBase = blockIdx.y * 64;
    const int tid = threadIdx.x;
    const int tx = tid & 15, ty = tid >> 4;

    const int arow = tid >> 2;
    const int ac   = (tid & 3) * 4;
    const int brow = tid >> 4;
    const int bc   = (tid & 15) * 4;

    const float* Aptr = A + (size_t)(rowBase + arow) * DIM_ + kOff;
    float acc[4][4] = {};

    for (int k0 = 0; k0 < 128; k0 += 16) {
        float4 av = *(const float4*)(Aptr + k0 + ac);
        float4 bv = *(const float4*)(Bm + (size_t)(kOff + k0 + brow) * DH_ + bc);
        __syncthreads();
        As[ac + 0][arow] = av.x; As[ac + 1][arow] = av.y;
        As[ac + 2][arow] = av.z; As[ac + 3][arow] = av.w;
        *(float4*)&Bs[brow][bc] = bv;
        __syncthreads();
#pragma unroll
        for (int kk = 0; kk < 16; ++kk) {
            float a0 = As[kk][ty * 4 + 0], a1 = As[kk][ty * 4 + 1];
            float a2 = As[kk][ty * 4 + 2], a3 = As[kk][ty * 4 + 3];
            float4 b4 = *(const float4*)&Bs[kk][tx * 4];
            acc[0][0] += a0 * b4.x; acc[0][1] += a0 * b4.y; acc[0][2] += a0 * b4.z; acc[0][3] += a0 * b4.w;
            acc[1][0] += a1 * b4.x; acc[1][1] += a1 * b4.y; acc[1][2] += a1 * b4.z; acc[1][3] += a1 * b4.w;
            acc[2][0] += a2 * b4.x; acc[2][1] += a2 * b4.y; acc[2][2] += a2 * b4.z; acc[2][3] += a2 * b4.w;
            acc[3][0] += a3 * b4.x; acc[3][1] += a3 * b4.y; acc[3][2] += a3 * b4.z; acc[3][3] += a3 * b4.w;
        }
    }

    float* Cb = Cp + (size_t)blockIdx.x * (N_ * DH_);
#pragma unroll
    for (int a = 0; a < 4; ++a) {
        int row = rowBase + ty * 4 + a;
        *(float4*)(Cb + (size_t)row * DH_ + tx * 4) =
            make_float4(acc[a][0], acc[a][1], acc[a][2], acc[a][3]);
    }
}

__global__ __launch_bounds__(256) void pos_reduce(
    const float* __restrict__ Cp, const float* __restrict__ bias, float* __restrict__ C)
{
    int i4 = blockIdx.x * 256 + threadIdx.x;     // over 32768 float4s
    float4 s = ((const float4*)Cp)[i4];
#pragma unroll
    for (int k = 1; k < 8; ++k) {
        float4 t = ((const float4*)(Cp + (size_t)k * (N_ * DH_)))[i4];
        s.x += t.x; s.y += t.y; s.z += t.z; s.w += t.w;
    }
    int col = (i4 & 15) * 4;
    float4 bv = *(const float4*)(bias + col);
    s.x += bv.x; s.y += bv.y; s.z += bv.z; s.w += bv.w;
    ((float4*)C)[i4] = s;
}

// =====================================================================
// vt_kernel: V^T split — Vth/Vtl[bh][d][j/2] = packed(V[j][d], V[j+1][d])
// =====================================================================
__global__ __launch_bounds__(256) void vt_kernel(
    const float* __restrict__ KV, unsigned* __restrict__ Vth, unsigned* __restrict__ Vtl)
{
    const int bh = blockIdx.y;
    const int b = bh >> 4, h = bh & 15;
    const int J0 = blockIdx.x * 64;
    __shared__ float Vs[64][65];
    const int tid = threadIdx.x;

#pragma unroll
    for (int u = 0; u < 4; ++u) {
        int idx = u * 256 + tid;
        int row = idx >> 4, c4 = (idx & 15) * 4;
        float4 v = *(const float4*)(KV + ((size_t)b * CTX_ + J0 + row) * (2 * DIM_) + DIM_ + h * DH_ + c4);
        Vs[row][c4] = v.x; Vs[row][c4 + 1] = v.y; Vs[row][c4 + 2] = v.z; Vs[row][c4 + 3] = v.w;
    }
    __syncthreads();

#pragma unroll
    for (int u = 0; u < 8; ++u) {
        int idx = u * 256 + tid;
        int d = idx >> 5, jp = idx & 31;
        unsigned hh, ll;
        bsplit2(Vs[2 * jp][d], Vs[2 * jp + 1][d], hh, ll);
        size_t o = ((size_t)bh * DH_ + d) * (CTX_ / 2) + (J0 >> 1) + jp;
        Vth[o] = hh; Vtl[o] = ll;
    }
}

// =====================================================================
// rd_kernel: RD[b,h][i][p] = SCALE * q_i . pos'_p  (bf16x3, band-culled)
// =====================================================================
__global__ __launch_bounds__(256) void rd_kernel(
    const float* __restrict__ Q, const float* __restrict__ Pos, float* __restrict__ RD)
{
    const int I0 = blockIdx.y * 128;
    const int P0 = blockIdx.x * 128;
    if (I0 + P0 + 254 < 2047) return;

    const int bh = blockIdx.z;
    const int b  = bh >> 4, h = bh & 15;

    __shared__ unsigned PsH[128][36];
    __shared__ unsigned PsL[128][36];

    const int tid  = threadIdx.x;
    const int wid  = tid >> 5, lane = tid & 31;
    const int wm   = wid & 3,  wn   = wid >> 2;
    const int g    = lane >> 2, qq  = lane & 3;

#pragma unroll
    for (int u = 0; u < 8; ++u) {
        int idx = tid + u * 256;
        int prow = idx >> 4, c4 = (idx & 15) * 4;
        float4 v = *(const float4*)(Pos + (size_t)(P0 + prow) * DH_ + c4);
        unsigned h0, l0, h1, l1;
        bsplit2(v.x, v.y, h0, l0);
        bsplit2(v.z, v.w, h1, l1);
        int pc = (idx & 15) * 2;
        PsH[prow][pc] = h0; PsH[prow][pc + 1] = h1;
        PsL[prow][pc] = l0; PsL[prow][pc + 1] = l1;
    }

    unsigned aH[2][4][4], aL[2][4][4];
#pragma unroll
    for (int tm = 0; tm < 2; ++tm) {
        const float* q0 = Q + ((size_t)(b * N_) + I0 + wm * 32 + tm * 16 + g) * DIM_ + h * DH_;
        const float* q8 = q0 + 8 * DIM_;
#pragma unroll
        for (int ks = 0; ks < 4; ++ks) {
            float2 xa = *(const float2*)(q0 + ks * 16 + 2 * qq);
            float2 xb = *(const float2*)(q0 + ks * 16 + 2 * qq + 8);
            float2 ya = *(const float2*)(q8 + ks * 16 + 2 * qq);
            float2 yb = *(const float2*)(q8 + ks * 16 + 2 * qq + 8);
            bsplit2(xa.x, xa.y, aH[tm][ks][0], aL[tm][ks][0]);
            bsplit2(ya.x, ya.y, aH[tm][ks][1], aL[tm][ks][1]);
            bsplit2(xb.x, xb.y, aH[tm][ks][2], aL[tm][ks][2]);
            bsplit2(yb.x, yb.y, aH[tm][ks][3], aL[tm][ks][3]);
        }
    }
    __syncthreads();

    float acc[2][8][4];
#pragma unroll
    for (int a = 0; a < 2; ++a)
#pragma unroll
        for (int t = 0; t < 8; ++t)
#pragma unroll
            for (int c = 0; c < 4; ++c) acc[a][t][c] = 0.f;

#pragma unroll
    for (int ks = 0; ks < 4; ++ks) {
#pragma unroll
        for (int tn = 0; tn < 8; ++tn) {
            int col = wn * 64 + tn * 8 + g;
            unsigned bh2[2], bl2[2];
            bh2[0] = PsH[col][8 * ks + qq];     bh2[1] = PsH[col][8 * ks + qq + 4];
            bl2[0] = PsL[col][8 * ks + qq];     bl2[1] = PsL[col][8 * ks + qq + 4];
            // tm-inner per pass: chain spacing 2
            mma_bf16(acc[0][tn], aH[0][ks], bh2);
            mma_bf16(acc[1][tn], aH[1][ks], bh2);
            mma_bf16(acc[0][tn], aH[0][ks], bl2);
            mma_bf16(acc[1][tn], aH[1][ks], bl2);
            mma_bf16(acc[0][tn], aL[0][ks], bh2);
            mma_bf16(acc[1][tn], aL[1][ks], bh2);
        }
    }

    float* base = RD + ((size_t)bh << 22);
#pragma unroll
    for (int tm = 0; tm < 2; ++tm) {
#pragma unroll
        for (int tn = 0; tn < 8; ++tn) {
            int row = I0 + wm * 32 + tm * 16 + g;
            int col = P0 + wn * 64 + tn * 8 + 2 * qq;
            float* dst = base + (size_t)row * N_ + col;
            *(float2*)dst = make_float2(acc[tm][tn][0] * SCALE_, acc[tm][tn][1] * SCALE_);
            *(float2*)(dst + 8 * N_) = make_float2(acc[tm][tn][2] * SCALE_, acc[tm][tn][3] * SCALE_);
        }
    }
}

// =====================================================================
// Tensor-core flash attention (bf16x3; K/V pre-split; pass-major mma)
// =====================================================================
#define KW   36
#define SM_K (32 * KW)
#define SM_V (64 * KW)
#define OFF_KL 2304
#define OFF_VH 4608
#define OFF_VL 9216
#define OFF_EM 13824
#define SMEM_ATTN ((OFF_EM + 1024) * 4)   // 59392 B

__device__ __forceinline__ void load_kv_stage(
    unsigned* smu, int sb, int jt, int tid, int b, int bh64,
    const unsigned* __restrict__ Khg, const unsigned* __restrict__ Klg,
    const unsigned* __restrict__ Vthg, const unsigned* __restrict__ Vtlg, int h)
{
    unsigned* KhD = smu + sb * SM_K;
    unsigned* KlD = smu + OFF_KL + sb * SM_K;
    unsigned* VhD = smu + OFF_VH + sb * SM_V;
    unsigned* VlD = smu + OFF_VL + sb * SM_V;
#pragma unroll
    for (int u = 0; u < 2; ++u) {
        int e = u * 128 + tid;
        int row = e >> 3, part = e & 7;
        size_t srk = ((size_t)b * CTX_ + jt + row) * 512 + h * 32 + part * 4;
        cp_async16(KhD + row * KW + part * 4, Khg + srk);
        cp_async16(KlD + row * KW + part * 4, Klg + srk);
    }
#pragma unroll
    for (int u = 0; u < 2; ++u) {
        int e = u * 128 + tid;
        int row = e >> 2, part = e & 3;
        size_t srv = ((size_t)bh64 + row) * (CTX_ / 2) + (jt >> 1) + part * 4;
        cp_async16(VhD + row * KW + part * 4, Vthg + srv);
        cp_async16(VlD + row * KW + part * 4, Vtlg + srv);
    }
}

__global__ __launch_bounds__(128, 3) void attn_kernel(
    const float* __restrict__ Q,
    const unsigned* __restrict__ Khg, const unsigned* __restrict__ Klg,
    const unsigned* __restrict__ Vthg, const unsigned* __restrict__ Vtlg,
    const float* __restrict__ RD, const float* __restrict__ expire,
    float* __restrict__ O)
{
    extern __shared__ unsigned smu[];
    float* em_s = (float*)(smu + OFF_EM);

    const int b = blockIdx.z, h = blockIdx.y;
    const int tid = threadIdx.x;
    const int I0 = blockIdx.x * 64;
    const int W = tid >> 5, lane = tid & 31;
    const int g = lane >> 2, qq = lane & 3;
    const int bh64 = (b * H_ + h) * DH_;

    {
        const float* emp = expire + b * MEM_;
        *(float4*)&em_s[tid * 8]     = *(const float4*)(emp + tid * 8);
        *(float4*)&em_s[tid * 8 + 4] = *(const float4*)(emp + tid * 8 + 4);
    }

    unsigned aH[4][4], aL[4][4];
    {
        const float* q0 = Q + ((size_t)(b * N_) + I0 + W * 16 + g) * DIM_ + h * DH_;
        const float* q8 = q0 + 8 * DIM_;
#pragma unroll
        for (int ks = 0; ks < 4; ++ks) {
            float2 xa = *(const float2*)(q0 + ks * 16 + 2 * qq);
            float2 xb = *(const float2*)(q0 + ks * 16 + 2 * qq + 8);
            float2 ya = *(const float2*)(q8 + ks * 16 + 2 * qq);
            float2 yb = *(const float2*)(q8 + ks * 16 + 2 * qq + 8);
            bsplit2(xa.x * SCALE_, xa.y * SCALE_, aH[ks][0], aL[ks][0]);
            bsplit2(ya.x * SCALE_, ya.y * SCALE_, aH[ks][1], aL[ks][1]);
            bsplit2(xb.x * SCALE_, xb.y * SCALE_, aH[ks][2], aL[ks][2]);
            bsplit2(yb.x * SCALE_, yb.y * SCALE_, aH[ks][3], aL[ks][3]);
        }
    }

    float o[8][4];
#pragma unroll
    for (int t = 0; t < 8; ++t)
#pragma unroll
        for (int c = 0; c < 4; ++c) o[t][c] = 0.f;
    float m0 = -1e30f, m1 = -1e30f, l0 = 0.f, l1 = 0.f;

    const float* rdb = RD + (((size_t)(b * H_ + h)) << 22);
    const int ntiles = (MEM_ + I0 + 64) / 32;

    load_kv_stage(smu, 0, 0, tid, b, bh64, Khg, Klg, Vthg, Vtlg, h);
    asm volatile("cp.async.commit_group;");

    for (int t = 0; t < ntiles; ++t) {
        const int st = t & 1;
        const int j0 = t * 32;
        if (t + 1 < ntiles)
            load_kv_stage(smu, st ^ 1, j0 + 32, tid, b, bh64, Khg, Klg, Vthg, Vtlg, h);
        asm volatile("cp.async.commit_group;");
        asm volatile("cp.async.wait_group 1;");
        __syncthreads();

        const unsigned* KhC = smu + st * SM_K;
        const unsigned* KlC = smu + OFF_KL + st * SM_K;
        const unsigned* VhC = smu + OFF_VH + st * SM_V;
        const unsigned* VlC = smu + OFF_VL + st * SM_V;

        // ---- S = Q K^T (pass-major, 4 independent accumulators) ----
        float s[4][4];
#pragma unroll
        for (int tt = 0; tt < 4; ++tt)
#pragma unroll
            for (int c = 0; c < 4; ++c) s[tt][c] = 0.f;

#pragma unroll
        for (int ks = 0; ks < 4; ++ks) {
            unsigned bhf[4][2], blf[4][2];
#pragma unroll
            for (int tt = 0; tt < 4; ++tt) {
                int base = (tt * 8 + g) * KW + ks * 8 + qq;
                bhf[tt][0] = KhC[base]; bhf[tt][1] = KhC[base + 4];
                blf[tt][0] = KlC[base]; blf[tt][1] = KlC[base + 4];
            }
#pragma unroll
            for (int tt = 0; tt < 4; ++tt) mma_bf16(s[tt], aH[ks], bhf[tt]);
#pragma unroll
            for (int tt = 0; tt < 4; ++tt) mma_bf16(s[tt], aH[ks], blf[tt]);
#pragma unroll
            for (int tt = 0; tt < 4; ++tt) mma_bf16(s[tt], aL[ks], bhf[tt]);
        }

        const bool isMem = (j0 < MEM_);
        if (!isMem) {
            const int jb = j0 - MEM_;
            const int i0g = I0 + W * 16 + g;
            const float* rd0 = rdb + (size_t)i0g * N_;
            const float* rd1 = rd0 + 8 * N_;
            const int D0 = jb + 2047 - i0g;
            const int D1 = D0 - 8;
#pragma unroll
            for (int tt = 0; tt < 4; ++tt) {
                int c0 = tt * 8 + 2 * qq;
                int p00 = D0 + c0;     p00 = p00 > 2047 ? 2047 : p00;
                int p01 = D0 + c0 + 1; p01 = p01 > 2047 ? 2047 : p01;
                int p10 = D1 + c0;     p10 = p10 > 2047 ? 2047 : p10;
                int p11 = D1 + c0 + 1; p11 = p11 > 2047 ? 2047 : p11;
                s[tt][0] += rd0[p00];
                s[tt][1] += rd0[p01];
                s[tt][2] += rd1[p10];
                s[tt][3] += rd1[p11];
            }
            if (jb + 31 > I0) {
                const int r0 = i0g, r1 = i0g + 8;
#pragma unroll
                for (int tt = 0; tt < 4; ++tt) {
                    int c0 = jb + tt * 8 + 2 * qq;
                    if (c0     > r0) s[tt][0] = -1e30f;
                    if (c0 + 1 > r0) s[tt][1] = -1e30f;
                    if (c0     > r1) s[tt][2] = -1e30f;
                    if (c0 + 1 > r1) s[tt][3] = -1e30f;
                }
            }
        }

        // ---- online softmax ----
        float mt0 = fmaxf(fmaxf(s[0][0], s[0][1]), fmaxf(s[1][0], s[1][1]));
        mt0 = fmaxf(mt0, fmaxf(fmaxf(s[2][0], s[2][1]), fmaxf(s[3][0], s[3][1])));
        float mt1 = fmaxf(fmaxf(s[0][2], s[0][3]), fmaxf(s[1][2], s[1][3]));
        mt1 = fmaxf(mt1, fmaxf(fmaxf(s[2][2], s[2][3]), fmaxf(s[3][2], s[3][3])));
        mt0 = fmaxf(mt0, __shfl_xor_sync(0xffffffffu, mt0, 1));
        mt0 = fmaxf(mt0, __shfl_xor_sync(0xffffffffu, mt0, 2));
        mt1 = fmaxf(mt1, __shfl_xor_sync(0xffffffffu, mt1, 1));
        mt1 = fmaxf(mt1, __shfl_xor_sync(0xffffffffu, mt1, 2));
        float mn0 = fmaxf(m0, mt0), mn1 = fmaxf(m1, mt1);
        float f0 = __expf(m0 - mn0), f1 = __expf(m1 - mn1);
        l0 *= f0; l1 *= f1;
#pragma unroll
        for (int tt = 0; tt < 8; ++tt) {
            o[tt][0] *= f0; o[tt][1] *= f0;
            o[tt][2] *= f1; o[tt][3] *= f1;
        }
        m0 = mn0; m1 = mn1;

        unsigned pAh[4], pAl[4], pBh[4], pBl[4];
#pragma unroll
        for (int tt = 0; tt < 4; ++tt) {
            float p0 = __expf(s[tt][0] - m0);
            float p1 = __expf(s[tt][1] - m0);
            float p2 = __expf(s[tt][2] - m1);
            float p3 = __expf(s[tt][3] - m1);
            l0 += p0 + p1; l1 += p2 + p3;
            if (isMem) {
                float e0 = em_s[j0 + tt * 8 + 2 * qq];
                float e1 = em_s[j0 + tt * 8 + 2 * qq + 1];
                p0 *= e0; p1 *= e1; p2 *= e0; p3 *= e1;
            }
            bsplit2(p0, p1, pAh[tt], pAl[tt]);
            bsplit2(p2, p3, pBh[tt], pBl[tt]);
        }

        // ---- O += P V (pass-major, 8 independent accumulators) ----
#pragma unroll
        for (int ks = 0; ks < 2; ++ks) {
            unsigned ah[4] = { pAh[2 * ks], pBh[2 * ks], pAh[2 * ks + 1], pBh[2 * ks + 1] };
            unsigned al[4] = { pAl[2 * ks], pBl[2 * ks], pAl[2 * ks + 1], pBl[2 * ks + 1] };
            unsigned bhf[8][2], blf[8][2];
#pragma unroll
            for (int tt = 0; tt < 8; ++tt) {
                int base = (tt * 8 + g) * KW + ks * 8 + qq;
                bhf[tt][0] = VhC[base]; bhf[tt][1] = VhC[base + 4];
                blf[tt][0] = VlC[base]; blf[tt][1] = VlC[base + 4];
            }
#pragma unroll
            for (int tt = 0; tt < 8; ++tt) mma_bf16(o[tt], ah, bhf[tt]);
#pragma unroll
            for (int tt = 0; tt < 8; ++tt) mma_bf16(o[tt], ah, blf[tt]);
#pragma unroll
            for (int tt = 0; tt < 8; ++tt) mma_bf16(o[tt], al, bhf[tt]);
        }
        __syncthreads();
    }

    l0 += __shfl_xor_sync(0xffffffffu, l0, 1);
    l0 += __shfl_xor_sync(0xffffffffu, l0, 2);
    l1 += __shfl_xor_sync(0xffffffffu, l1, 1);
    l1 += __shfl_xor_sync(0xffffffffu, l1, 2);
    float inv0 = 1.f / l0, inv1 = 1.f / l1;

    float* ob0 = O + ((size_t)(b * N_) + I0 + W * 16 + g) * DIM_ + h * DH_;
    float* ob1 = ob0 + 8 * DIM_;
#pragma unroll
    for (int tt = 0; tt < 8; ++tt) {
        int c0 = tt * 8 + 2 * qq;
        *(float2*)(ob0 + c0) = make_float2(o[tt][0] * inv0, o[tt][1] * inv0);
        *(float2*)(ob1 + c0) = make_float2(o[tt][2] * inv1, o[tt][3] * inv1);
    }
}

// ---------------- launcher ----------------
extern "C" void kernel_launch(void* const* d_in, const int* in_sizes, int n_in,
                              void* d_out, int out_size)
{
    const float* x       = (const float*)d_in[0];
    const float* pos_emb = (const float*)d_in[1];
    const float* mem     = (const float*)d_in[2];
    const float* expire  = (const float*)d_in[3];
    const float* Wq      = (const float*)d_in[4];
    const float* bq      = (const float*)d_in[5];
    const float* Wkv     = (const float*)d_in[6];
    const float* bkv     = (const float*)d_in[7];
    const float* Wo      = (const float*)d_in[8];
    const float* bo      = (const float*)d_in[9];
    const float* Wp      = (const float*)d_in[10];
    const float* bp      = (const float*)d_in[11];
    float* out = (float*)d_out;

    float *Q, *KV, *Pos, *Posp, *RD, *O;
    unsigned *Kh, *Kl, *Vth, *Vtl;
    cudaGetSymbolAddress((void**)&Q,    g_Q);
    cudaGetSymbolAddress((void**)&KV,   g_KV);
    cudaGetSymbolAddress((void**)&Pos,  g_pos);
    cudaGetSymbolAddress((void**)&Posp, g_posp);
    cudaGetSymbolAddress((void**)&RD,   g_RD);
    cudaGetSymbolAddress((void**)&O,    g_O);
    cudaGetSymbolAddress((void**)&Kh,   g_Kh);
    cudaGetSymbolAddress((void**)&Kl,   g_Kl);
    cudaGetSymbolAddress((void**)&Vth,  g_Vth);
    cudaGetSymbolAddress((void**)&Vtl,  g_Vtl);

    cudaFuncSetAttribute(attn_kernel, cudaFuncAttributeMaxDynamicSharedMemorySize, SMEM_ATTN);

    // 1) Q = x @ Wq + bq
    gemm_bf16<<<dim3(DIM_ / 128, (B_ * N_) / 128, 1), 256>>>(
        x, B_ * N_, 0, x, 0, Wq, bq, Q, 0, DIM_, DIM_, nullptr, nullptr, 0);

    // 2) KV = concat(mem, x) @ Wkv + bkv  (also emits packed-bf16 K)
    gemm_bf16<<<dim3(2 * DIM_ / 128, CTX_ / 128, B_), 256>>>(
        mem, MEM_, (size_t)MEM_ * DIM_, x, (size_t)N_ * DIM_,
        Wkv, bkv, KV, (size_t)CTX_ * 2 * DIM_, 2 * DIM_, DIM_, Kh, Kl, DIM_);

    // 3) V^T split for attention PV fragments
    vt_kernel<<<dim3(CTX_ / 64, B_ * H_), 256>>>(KV, Vth, Vtl);

    // 4) pos' = pos_emb @ Wp + bp  (split-K: 256 blocks + reduce)
    pos_part<<<dim3(8, 32), 256>>>(pos_emb, Wp, Posp);
    pos_reduce<<<128, 256>>>(Posp, bp, Pos);

    // 5) RD = SCALE * Q_head @ pos'^T  (band-culled)
    rd_kernel<<<dim3(16, 16, B_ * H_), 256>>>(Q, Pos, RD);

    // 6) tensor-core flash attention -> O
    attn_kernel<<<dim3(N_ / 64, H_, B_), 128, SMEM_ATTN>>>(
        Q, Kh, Kl, Vth, Vtl, RD, expire, O);

    // 7) out = O @ Wo + bo
    gemm_bf16<<<dim3(DIM_ / 128, (B_ * N_) / 128, 1), 256>>>(
        O, B_ * N_, 0, O, 0, Wo, bo, out, 0, DIM_, DIM_, nullptr, nullptr, 0);
}